// round 8
// baseline (speedup 1.0000x reference)
#include <cuda_runtime.h>
#include <cuda_bf16.h>
#include <cstdint>
#include <math.h>

#define BB 2
#define SS 2048
#define TT (BB*SS)
#define HH 2048
#define NHQ 16
#define NKV 8
#define HD 128
#define INTER 8192
#define EPS 1e-6f

// ======================= scratch =======================
__device__ __align__(256) float g_res1 [(size_t)TT*HH];
__device__ __align__(256) float g_qkv  [(size_t)TT*4096];
__device__ __align__(256) float g_hattn[(size_t)TT*HH];
__device__ float g_invf [64];

__device__ __align__(256) __nv_bfloat16 g_xn_h [(size_t)TT*HH];
__device__ __align__(256) __nv_bfloat16 g_xn_l [(size_t)TT*HH];
__device__ __align__(256) __nv_bfloat16 g_at_h [(size_t)TT*HH];
__device__ __align__(256) __nv_bfloat16 g_at_l [(size_t)TT*HH];
__device__ __align__(256) __nv_bfloat16 g_h2_h [(size_t)TT*HH];
__device__ __align__(256) __nv_bfloat16 g_h2_l [(size_t)TT*HH];
__device__ __align__(256) __nv_bfloat16 g_ac_h [(size_t)TT*INTER];
__device__ __align__(256) __nv_bfloat16 g_ac_l [(size_t)TT*INTER];

// flash operands (bf16 split)
__device__ __align__(256) __nv_bfloat16 g_Qh [(size_t)TT*2048];
__device__ __align__(256) __nv_bfloat16 g_Ql [(size_t)TT*2048];
__device__ __align__(256) __nv_bfloat16 g_Kh [(size_t)TT*1024];
__device__ __align__(256) __nv_bfloat16 g_Kl [(size_t)TT*1024];
__device__ __align__(256) __nv_bfloat16 g_Vh [(size_t)TT*1024];  // [b][hk][d][s]
__device__ __align__(256) __nv_bfloat16 g_Vl [(size_t)TT*1024];

__device__ __align__(256) __nv_bfloat16 g_qkvT_h[(size_t)4096*HH];
__device__ __align__(256) __nv_bfloat16 g_qkvT_l[(size_t)4096*HH];
__device__ __align__(256) __nv_bfloat16 g_woT_h[(size_t)HH*(NHQ*HD)];
__device__ __align__(256) __nv_bfloat16 g_woT_l[(size_t)HH*(NHQ*HD)];
__device__ __align__(256) __nv_bfloat16 g_guT_h[(size_t)(2*INTER)*HH];
__device__ __align__(256) __nv_bfloat16 g_guT_l[(size_t)(2*INTER)*HH];
__device__ __align__(256) __nv_bfloat16 g_wdT_h[(size_t)HH*INTER];
__device__ __align__(256) __nv_bfloat16 g_wdT_l[(size_t)HH*INTER];

// ======================= PTX helpers =======================
__device__ __forceinline__ uint32_t s2u(const void* p) {
    uint32_t a;
    asm("{ .reg .u64 t; cvta.to.shared.u64 t, %1; cvt.u32.u64 %0, t; }" : "=r"(a) : "l"(p));
    return a;
}
__device__ __forceinline__ void cpasync16(uint32_t dst, const void* src) {
    asm volatile("cp.async.cg.shared.global [%0], [%1], 16;" :: "r"(dst), "l"(src) : "memory");
}
__device__ __forceinline__ void cp_commit() { asm volatile("cp.async.commit_group;" ::: "memory"); }
template<int N_>
__device__ __forceinline__ void cp_wait() { asm volatile("cp.async.wait_group %0;" :: "n"(N_) : "memory"); }
__device__ __forceinline__ void ldsm4(uint32_t* r, uint32_t addr) {
    asm volatile("ldmatrix.sync.aligned.m8n8.x4.shared.b16 {%0,%1,%2,%3}, [%4];"
                 : "=r"(r[0]), "=r"(r[1]), "=r"(r[2]), "=r"(r[3]) : "r"(addr));
}
__device__ __forceinline__ void mma_bf16(float* d, const uint32_t* a, const uint32_t* b) {
    asm volatile(
        "mma.sync.aligned.m16n8k16.row.col.f32.bf16.bf16.f32 "
        "{%0,%1,%2,%3}, {%4,%5,%6,%7}, {%8,%9}, {%0,%1,%2,%3};"
        : "+f"(d[0]), "+f"(d[1]), "+f"(d[2]), "+f"(d[3])
        : "r"(a[0]), "r"(a[1]), "r"(a[2]), "r"(a[3]), "r"(b[0]), "r"(b[1]));
}
__device__ __forceinline__ void split_store2(float x, float y, __nv_bfloat162* ph, __nv_bfloat162* pl)
{
    __nv_bfloat16 hx = __float2bfloat16(x), hy = __float2bfloat16(y);
    *ph = __halves2bfloat162(hx, hy);
    *pl = __halves2bfloat162(__float2bfloat16(x - __bfloat162float(hx)),
                             __float2bfloat16(y - __bfloat162float(hy)));
}
__device__ __forceinline__ void split_pack(uint32_t& ph, uint32_t& pl, float x, float y)
{
    __nv_bfloat162 h2, l2;
    split_store2(x, y, &h2, &l2);
    ph = *(uint32_t*)&h2; pl = *(uint32_t*)&l2;
}
// swizzles: 128B rows (u 0..7) and 256B rows (u 0..15)
__device__ __forceinline__ uint32_t soffG(int r, int u)   { return (uint32_t)(r*128 + ((u ^ (r & 7)) << 4)); }
__device__ __forceinline__ uint32_t soff256(int r, int u) { return (uint32_t)(r*256 + ((u ^ (r & 7)) << 4)); }

// ======================= fused add + RMSNorm =======================
__global__ void add_rmsnorm_kernel(const float* __restrict__ a, const float* __restrict__ b,
                                   const float* __restrict__ w, float* __restrict__ res,
                                   __nv_bfloat16* __restrict__ oh, __nv_bfloat16* __restrict__ ol)
{
    int t = blockIdx.x, tid = threadIdx.x;
    const float4* a4 = (const float4*)(a + (size_t)t * HH);
    const float4* b4 = (const float4*)(b + (size_t)t * HH);
    float4* r4 = (float4*)(res + (size_t)t * HH);
    const float4* w4 = (const float4*)w;
    __nv_bfloat162* oh2 = (__nv_bfloat162*)(oh + (size_t)t * HH);
    __nv_bfloat162* ol2 = (__nv_bfloat162*)(ol + (size_t)t * HH);

    float4 vv[2];
    float ss = 0.f;
#pragma unroll
    for (int ii = 0; ii < 2; ii++) {
        int idx = tid + ii * 256;
        float4 x = a4[idx], y = b4[idx];
        x.x += y.x; x.y += y.y; x.z += y.z; x.w += y.w;
        r4[idx] = x; vv[ii] = x;
        ss += x.x*x.x + x.y*x.y + x.z*x.z + x.w*x.w;
    }
#pragma unroll
    for (int off = 16; off; off >>= 1) ss += __shfl_xor_sync(0xffffffffu, ss, off);
    __shared__ float sh[8];
    __shared__ float s_inv;
    if ((tid & 31) == 0) sh[tid >> 5] = ss;
    __syncthreads();
    if (tid == 0) {
        float s = 0.f;
#pragma unroll
        for (int i = 0; i < 8; i++) s += sh[i];
        s_inv = rsqrtf(s / (float)HH + EPS);
    }
    __syncthreads();
    float inv = s_inv;
#pragma unroll
    for (int ii = 0; ii < 2; ii++) {
        int idx = tid + ii * 256;
        float4 x = vv[ii], ww = w4[idx];
        __nv_bfloat162 h0, l0, h1, l1;
        split_store2(x.x*inv*ww.x, x.y*inv*ww.y, &h0, &l0);
        split_store2(x.z*inv*ww.z, x.w*inv*ww.w, &h1, &l1);
        oh2[idx*2] = h0; oh2[idx*2+1] = h1;
        ol2[idx*2] = l0; ol2[idx*2+1] = l1;
    }
}

// ======================= weight split kernels =======================
__global__ void wsplit_kernel(const float* __restrict__ W,
                              __nv_bfloat16* __restrict__ Th, __nv_bfloat16* __restrict__ Tl,
                              int K, int N)
{
    __shared__ float tile[32][33];
    int k0 = blockIdx.y * 32, n0 = blockIdx.x * 32;
    int tx = threadIdx.x, ty = threadIdx.y;
#pragma unroll
    for (int j = 0; j < 4; j++)
        tile[ty + 8*j][tx] = W[(size_t)(k0 + ty + 8*j) * N + n0 + tx];
    __syncthreads();
#pragma unroll
    for (int j = 0; j < 4; j++) {
        int n = ty + 8*j;
        float v = tile[tx][n];
        __nv_bfloat16 h = __float2bfloat16(v);
        Th[(size_t)(n0 + n) * K + k0 + tx] = h;
        Tl[(size_t)(n0 + n) * K + k0 + tx] = __float2bfloat16(v - __bfloat162float(h));
    }
}

__global__ void wsplit_qkv_kernel(const float* __restrict__ wq, const float* __restrict__ wk,
                                  const float* __restrict__ wv,
                                  __nv_bfloat16* __restrict__ Th, __nv_bfloat16* __restrict__ Tl)
{
    __shared__ float tile[32][33];
    int n0 = blockIdx.x * 32, k0 = blockIdx.y * 32;
    int tx = threadIdx.x, ty = threadIdx.y;
    if (blockIdx.x == 0 && blockIdx.y == 0) {
        int id = ty * 32 + tx;
        if (id < 64) g_invf[id] = (float)pow(1.0e6, -(double)id / 64.0);
    }
    int n = n0 + tx;
    const float* src; int nc, stride;
    if (n < 2048)      { src = wq; nc = n;        stride = 2048; }
    else if (n < 3072) { src = wk; nc = n - 2048; stride = 1024; }
    else               { src = wv; nc = n - 3072; stride = 1024; }
#pragma unroll
    for (int j = 0; j < 4; j++)
        tile[ty + 8*j][tx] = src[(size_t)(k0 + ty + 8*j) * stride + nc];
    __syncthreads();
#pragma unroll
    for (int j = 0; j < 4; j++) {
        int nn = n0 + ty + 8*j;
        float v = tile[tx][ty + 8*j];
        __nv_bfloat16 h = __float2bfloat16(v);
        Th[(size_t)nn * HH + k0 + tx] = h;
        Tl[(size_t)nn * HH + k0 + tx] = __float2bfloat16(v - __bfloat162float(h));
    }
}

__global__ void wsplit_gu_kernel(const float* __restrict__ W,
                                 __nv_bfloat16* __restrict__ Th, __nv_bfloat16* __restrict__ Tl)
{
    __shared__ float tile[32][33];
    int n0 = blockIdx.x * 32, k0 = blockIdx.y * 32;
    int tx = threadIdx.x, ty = threadIdx.y;
    int n = n0 + tx;
    int srccol = (n & 1) ? (8192 + (n >> 1)) : (n >> 1);
#pragma unroll
    for (int j = 0; j < 4; j++)
        tile[ty + 8*j][tx] = W[(size_t)(k0 + ty + 8*j) * 16384 + srccol];
    __syncthreads();
#pragma unroll
    for (int j = 0; j < 4; j++) {
        int nn = n0 + ty + 8*j;
        float v = tile[tx][ty + 8*j];
        __nv_bfloat16 h = __float2bfloat16(v);
        Th[(size_t)nn * HH + k0 + tx] = h;
        Tl[(size_t)nn * HH + k0 + tx] = __float2bfloat16(v - __bfloat162float(h));
    }
}

// ======================= mma.sync bf16-split GEMM =======================
#define GS_STAGE 32768
#define GS_B     16384
#define GEMM_SMEM (3*GS_STAGE)

__device__ __forceinline__ void g_load_stage(uint32_t sb, int s,
    const __nv_bfloat16* __restrict__ Ah, const __nv_bfloat16* __restrict__ Al,
    const __nv_bfloat16* __restrict__ Bh, const __nv_bfloat16* __restrict__ Bl,
    int m0, int n0, int k0, int K, int tid)
{
    uint32_t st = sb + s * GS_STAGE;
#pragma unroll
    for (int j = 0; j < 8; j++) {
        int idx = j * 256 + tid;
        int mat = idx >> 10;
        int rem = idx & 1023;
        int r = rem >> 3, u = rem & 7;
        const __nv_bfloat16* src;
        int row = (mat == 0) ? (m0 + r) : (n0 + r);
        if (mat == 0) src = (u < 4) ? Ah : Al;
        else          src = (u < 4) ? Bh : Bl;
        src += (size_t)row * K + k0 + (u & 3) * 8;
        cpasync16(st + mat * GS_B + soffG(r, u), src);
    }
    cp_commit();
}

template<int MODE>
__global__ __launch_bounds__(256, 1) void gemm_mma(
    const __nv_bfloat16* __restrict__ Ah, const __nv_bfloat16* __restrict__ Al,
    const __nv_bfloat16* __restrict__ Bh, const __nv_bfloat16* __restrict__ Bl,
    const float* __restrict__ bq, const float* __restrict__ bk, const float* __restrict__ bv,
    float* __restrict__ C, __nv_bfloat16* __restrict__ actH, __nv_bfloat16* __restrict__ actL,
    int M, int N, int K)
{
    extern __shared__ char smc[];
    uint32_t sb = s2u(smc);
    int tid = threadIdx.x, lane = tid & 31, wid = tid >> 5;
    int wm = wid >> 2, wn = wid & 3;
    int m0 = blockIdx.y * 128, n0 = blockIdx.x * 128;

    float acc[4][4][4];
#pragma unroll
    for (int i = 0; i < 4; i++)
#pragma unroll
        for (int j = 0; j < 4; j++)
#pragma unroll
            for (int c = 0; c < 4; c++) acc[i][j][c] = 0.f;

    int rA = lane & 15, uA = lane >> 4;
    int rB = (lane & 7) | ((lane & 16) >> 1), uB = (lane >> 3) & 1;

    int nIter = K / 32;
    g_load_stage(sb, 0, Ah, Al, Bh, Bl, m0, n0, 0, K, tid);
    g_load_stage(sb, 1, Ah, Al, Bh, Bl, m0, n0, 32, K, tid);

    int cs = 0, ns = 2;
    for (int it = 0; it < nIter; it++) {
        if (it + 1 < nIter) cp_wait<1>(); else cp_wait<0>();
        __syncthreads();
        if (it + 2 < nIter)
            g_load_stage(sb, ns, Ah, Al, Bh, Bl, m0, n0, (it + 2) * 32, K, tid);

        uint32_t st = sb + cs * GS_STAGE;
#pragma unroll
        for (int ks = 0; ks < 2; ks++) {
            uint32_t ah[4][4], al[4][4], bh[4][2], bl[4][2];
#pragma unroll
            for (int mt = 0; mt < 4; mt++) {
                int row = wm * 64 + mt * 16 + rA;
                ldsm4(ah[mt], st + soffG(row, ks * 2 + uA));
                ldsm4(al[mt], st + soffG(row, 4 + ks * 2 + uA));
            }
#pragma unroll
            for (int nt = 0; nt < 2; nt++) {
                int row = wn * 32 + nt * 16 + rB;
                uint32_t t4[4];
                ldsm4(t4, st + GS_B + soffG(row, ks * 2 + uB));
                bh[nt*2][0] = t4[0]; bh[nt*2][1] = t4[1];
                bh[nt*2+1][0] = t4[2]; bh[nt*2+1][1] = t4[3];
                ldsm4(t4, st + GS_B + soffG(row, 4 + ks * 2 + uB));
                bl[nt*2][0] = t4[0]; bl[nt*2][1] = t4[1];
                bl[nt*2+1][0] = t4[2]; bl[nt*2+1][1] = t4[3];
            }
#pragma unroll
            for (int mt = 0; mt < 4; mt++)
#pragma unroll
                for (int nf = 0; nf < 4; nf++) {
                    mma_bf16(acc[mt][nf], ah[mt], bh[nf]);
                    mma_bf16(acc[mt][nf], ah[mt], bl[nf]);
                    mma_bf16(acc[mt][nf], al[mt], bh[nf]);
                }
        }
        cs++; if (cs == 3) cs = 0;
        ns++; if (ns == 3) ns = 0;
    }

    int crow = lane >> 2, ccol = (lane & 3) * 2;
#pragma unroll
    for (int mt = 0; mt < 4; mt++) {
#pragma unroll
        for (int nf = 0; nf < 4; nf++) {
            int r = m0 + wm * 64 + mt * 16 + crow;
            int cidx = n0 + wn * 32 + nf * 8 + ccol;
            if (MODE == 2) {
                int jj = cidx >> 1;
                float ga = acc[mt][nf][0], up = acc[mt][nf][1];
                float v0 = ga / (1.f + __expf(-ga)) * up;
                float gb = acc[mt][nf][2], ub = acc[mt][nf][3];
                float v1 = gb / (1.f + __expf(-gb)) * ub;
                __nv_bfloat16 h0 = __float2bfloat16(v0);
                actH[(size_t)r * INTER + jj] = h0;
                actL[(size_t)r * INTER + jj] = __float2bfloat16(v0 - __bfloat162float(h0));
                __nv_bfloat16 h1 = __float2bfloat16(v1);
                actH[(size_t)(r + 8) * INTER + jj] = h1;
                actL[(size_t)(r + 8) * INTER + jj] = __float2bfloat16(v1 - __bfloat162float(h1));
            } else {
                float b0 = 0.f, b1 = 0.f;
                if (MODE == 1) {
                    b0 = (cidx < 2048) ? bq[cidx] : ((cidx < 3072) ? bk[cidx - 2048] : bv[cidx - 3072]);
                    int c1 = cidx + 1;
                    b1 = (c1 < 2048) ? bq[c1] : ((c1 < 3072) ? bk[c1 - 2048] : bv[c1 - 3072]);
                }
                *(float2*)(C + (size_t)r * N + cidx) =
                    make_float2(acc[mt][nf][0] + b0, acc[mt][nf][1] + b1);
                *(float2*)(C + (size_t)(r + 8) * N + cidx) =
                    make_float2(acc[mt][nf][2] + b0, acc[mt][nf][3] + b1);
            }
        }
    }
}

// ======================= RoPE + split of Q,K =======================
__global__ void qkconv_kernel(const float* __restrict__ qkv, const int* __restrict__ pos,
    __nv_bfloat16* __restrict__ Qh, __nv_bfloat16* __restrict__ Ql,
    __nv_bfloat16* __restrict__ Kh, __nv_bfloat16* __restrict__ Kl)
{
    int idx = blockIdx.x * blockDim.x + threadIdx.x;
    int i = idx & 63;
    int rest = idx >> 6;
    int head = rest % 24;
    int t = rest / 24;
    if (t >= TT) return;
    const float* p = qkv + (size_t)t * 4096 + ((head < 16) ? head * 128 : 2048 + (head - 16) * 128);
    float ang = (float)pos[t] * g_invf[i];
    float sv, cv;
    sincosf(ang, &sv, &cv);
    float x1 = p[i], x2 = p[i + 64];
    float o1 = x1 * cv - x2 * sv;
    float o2 = x2 * cv + x1 * sv;
    __nv_bfloat16 *dh, *dl;
    size_t dst;
    if (head < 16) { dst = (size_t)t * 2048 + head * 128;        dh = Qh; dl = Ql; }
    else           { dst = (size_t)t * 1024 + (head - 16) * 128; dh = Kh; dl = Kl; }
    __nv_bfloat16 h1 = __float2bfloat16(o1);
    dh[dst + i] = h1;
    dl[dst + i] = __float2bfloat16(o1 - __bfloat162float(h1));
    __nv_bfloat16 h2 = __float2bfloat16(o2);
    dh[dst + i + 64] = h2;
    dl[dst + i + 64] = __float2bfloat16(o2 - __bfloat162float(h2));
}

// ======================= V transpose + split: -> [b][hk][d][s] =======================
__global__ void vconv_kernel(const float* __restrict__ qkv,
    __nv_bfloat16* __restrict__ Vh, __nv_bfloat16* __restrict__ Vl)
{
    __shared__ float tile[32][33];
    int bhk = blockIdx.z;
    int b = bhk >> 3, hk = bhk & 7;
    int s0 = blockIdx.x * 32, d0 = blockIdx.y * 32;
    int tx = threadIdx.x, ty = threadIdx.y;
#pragma unroll
    for (int j = 0; j < 4; j++)
        tile[ty + 8*j][tx] = qkv[(size_t)(b * SS + s0 + ty + 8*j) * 4096 + 3072 + hk * 128 + d0 + tx];
    __syncthreads();
#pragma unroll
    for (int j = 0; j < 4; j++) {
        int d = d0 + ty + 8*j;
        float v = tile[tx][ty + 8*j];
        __nv_bfloat16 h = __float2bfloat16(v);
        size_t o = ((size_t)(b * NKV + hk) * HD + d) * SS + s0 + tx;
        Vh[o] = h;
        Vl[o] = __float2bfloat16(v - __bfloat162float(h));
    }
}

// ======================= tensor-core causal flash attention =======================
// 128q x 64k tiles, 256 threads (warp = 16 q rows), bf16-split 3-term.
#define FQ_H 0
#define FQ_L 32768
#define FST(s) (65536 + (s)*65536)
#define FK_H 0
#define FK_L 16384
#define FV_H 32768
#define FV_L 49152
#define FLASH_SMEM (65536 + 2*65536)

__global__ __launch_bounds__(256, 1) void flash_mma(
    const __nv_bfloat16* __restrict__ Qh, const __nv_bfloat16* __restrict__ Ql,
    const __nv_bfloat16* __restrict__ Kh, const __nv_bfloat16* __restrict__ Kl,
    const __nv_bfloat16* __restrict__ Vh, const __nv_bfloat16* __restrict__ Vl,
    __nv_bfloat16* __restrict__ Oh, __nv_bfloat16* __restrict__ Ol)
{
    extern __shared__ char smc[];
    uint32_t sb = s2u(smc);
    int tid = threadIdx.x, lane = tid & 31, wid = tid >> 5;
    int qt = blockIdx.x, h = blockIdx.y, b = blockIdx.z;
    int hk = h >> 1;
    int q0 = qt * 128;
    int rA = lane & 15, uA = lane >> 4;
    int rB = (lane & 7) | ((lane & 16) >> 1), uB = (lane >> 3) & 1;

    // Q stage (once)
#pragma unroll
    for (int j = 0; j < 16; j++) {
        int idx = j * 256 + tid;
        int arr = idx >> 11, rem = idx & 2047;
        int r = rem >> 4, u = rem & 15;
        const __nv_bfloat16* src = (arr ? Ql : Qh) + (size_t)(b * SS + q0 + r) * 2048 + h * 128 + u * 8;
        cpasync16(sb + (arr ? FQ_L : FQ_H) + soff256(r, u), src);
    }

    auto load_kv = [&](int buf, int kbase) {
        uint32_t st = sb + FST(buf);
#pragma unroll
        for (int j = 0; j < 8; j++) {
            int idx = j * 256 + tid;
            int arr = idx >> 10, rem = idx & 1023;
            int r = rem >> 4, u = rem & 15;
            const __nv_bfloat16* src = (arr ? Kl : Kh) + (size_t)(b * SS + kbase + r) * 1024 + hk * 128 + u * 8;
            cpasync16(st + (arr ? FK_L : FK_H) + soff256(r, u), src);
        }
#pragma unroll
        for (int j = 0; j < 8; j++) {
            int idx = j * 256 + tid;
            int arr = idx >> 10, rem = idx & 1023;
            int r = rem >> 3, u = rem & 7;
            const __nv_bfloat16* src = (arr ? Vl : Vh) + ((size_t)(b * NKV + hk) * HD + r) * SS + kbase + u * 8;
            cpasync16(st + (arr ? FV_L : FV_H) + soffG(r, u), src);
        }
        cp_commit();
    };
    load_kv(0, 0);   // group 0 = Q + KV0

    float m0v = -1e30f, m1v = -1e30f, l0v = 0.f, l1v = 0.f;
    float accO[16][4];
#pragma unroll
    for (int i = 0; i < 16; i++)
#pragma unroll
        for (int c = 0; c < 4; c++) accO[i][c] = 0.f;

    const float sc = 0.08838834764831845f;
    int ktmax = 2 * qt + 1;
    int row0 = q0 + wid * 16 + (lane >> 2);

    for (int kt = 0; kt <= ktmax; kt++) {
        cp_wait<0>();
        __syncthreads();
        if (kt < ktmax) load_kv((kt + 1) & 1, (kt + 1) * 64);
        uint32_t st = sb + FST(kt & 1);

        // S = Q K^T
        float accS[8][4];
#pragma unroll
        for (int i = 0; i < 8; i++)
#pragma unroll
            for (int c = 0; c < 4; c++) accS[i][c] = 0.f;

#pragma unroll
        for (int j = 0; j < 8; j++) {
            uint32_t ahf[4], alf[4];
            uint32_t qoff = soff256(wid * 16 + rA, 2 * j + uA);
            ldsm4(ahf, sb + FQ_H + qoff);
            ldsm4(alf, sb + FQ_L + qoff);
            uint32_t bhf[8][2], blf[8][2];
#pragma unroll
            for (int nt = 0; nt < 4; nt++) {
                uint32_t koff = soff256(nt * 16 + rB, 2 * j + uB);
                uint32_t t4[4];
                ldsm4(t4, st + FK_H + koff);
                bhf[2*nt][0] = t4[0]; bhf[2*nt][1] = t4[1];
                bhf[2*nt+1][0] = t4[2]; bhf[2*nt+1][1] = t4[3];
                ldsm4(t4, st + FK_L + koff);
                blf[2*nt][0] = t4[0]; blf[2*nt][1] = t4[1];
                blf[2*nt+1][0] = t4[2]; blf[2*nt+1][1] = t4[3];
            }
#pragma unroll
            for (int nf = 0; nf < 8; nf++) {
                mma_bf16(accS[nf], ahf, bhf[nf]);
                mma_bf16(accS[nf], ahf, blf[nf]);
                mma_bf16(accS[nf], alf, bhf[nf]);
            }
        }

        // scale + mask
        int kbase = kt * 64;
        bool needmask = (kbase + 63) > row0;
#pragma unroll
        for (int nf = 0; nf < 8; nf++) {
#pragma unroll
            for (int e = 0; e < 4; e++) {
                float s = accS[nf][e] * sc;
                if (needmask) {
                    int cc = kbase + nf * 8 + (lane & 3) * 2 + (e & 1);
                    int rr = row0 + ((e >> 1) << 3);
                    if (cc > rr) s = -1e30f;
                }
                accS[nf][e] = s;
            }
        }
        // online softmax
        float vm0 = -1e30f, vm1 = -1e30f;
#pragma unroll
        for (int nf = 0; nf < 8; nf++) {
            vm0 = fmaxf(vm0, fmaxf(accS[nf][0], accS[nf][1]));
            vm1 = fmaxf(vm1, fmaxf(accS[nf][2], accS[nf][3]));
        }
        vm0 = fmaxf(vm0, __shfl_xor_sync(0xffffffffu, vm0, 1));
        vm0 = fmaxf(vm0, __shfl_xor_sync(0xffffffffu, vm0, 2));
        vm1 = fmaxf(vm1, __shfl_xor_sync(0xffffffffu, vm1, 1));
        vm1 = fmaxf(vm1, __shfl_xor_sync(0xffffffffu, vm1, 2));
        float mn0 = fmaxf(m0v, vm0), mn1 = fmaxf(m1v, vm1);
        float c0 = __expf(m0v - mn0), c1 = __expf(m1v - mn1);
        float s0 = 0.f, s1 = 0.f;
#pragma unroll
        for (int nf = 0; nf < 8; nf++) {
            accS[nf][0] = __expf(accS[nf][0] - mn0); s0 += accS[nf][0];
            accS[nf][1] = __expf(accS[nf][1] - mn0); s0 += accS[nf][1];
            accS[nf][2] = __expf(accS[nf][2] - mn1); s1 += accS[nf][2];
            accS[nf][3] = __expf(accS[nf][3] - mn1); s1 += accS[nf][3];
        }
        s0 += __shfl_xor_sync(0xffffffffu, s0, 1);
        s0 += __shfl_xor_sync(0xffffffffu, s0, 2);
        s1 += __shfl_xor_sync(0xffffffffu, s1, 1);
        s1 += __shfl_xor_sync(0xffffffffu, s1, 2);
        l0v = l0v * c0 + s0; l1v = l1v * c1 + s1;
        m0v = mn0; m1v = mn1;
#pragma unroll
        for (int i = 0; i < 16; i++) {
            accO[i][0] *= c0; accO[i][1] *= c0;
            accO[i][2] *= c1; accO[i][3] *= c1;
        }

        // O += P V  (P frags from accS via C->A layout identity)
#pragma unroll
        for (int j2 = 0; j2 < 4; j2++) {
            uint32_t pah[4], pal[4];
            split_pack(pah[0], pal[0], accS[2*j2][0],   accS[2*j2][1]);
            split_pack(pah[1], pal[1], accS[2*j2][2],   accS[2*j2][3]);
            split_pack(pah[2], pal[2], accS[2*j2+1][0], accS[2*j2+1][1]);
            split_pack(pah[3], pal[3], accS[2*j2+1][2], accS[2*j2+1][3]);
#pragma unroll
            for (int nt = 0; nt < 8; nt++) {
                uint32_t voff = soffG(nt * 16 + rB, 2 * j2 + uB);
                uint32_t t4[4], vh0[2], vh1[2], vl0[2], vl1[2];
                ldsm4(t4, st + FV_H + voff);
                vh0[0] = t4[0]; vh0[1] = t4[1]; vh1[0] = t4[2]; vh1[1] = t4[3];
                ldsm4(t4, st + FV_L + voff);
                vl0[0] = t4[0]; vl0[1] = t4[1]; vl1[0] = t4[2]; vl1[1] = t4[3];
                mma_bf16(accO[2*nt],   pah, vh0);
                mma_bf16(accO[2*nt],   pah, vl0);
                mma_bf16(accO[2*nt],   pal, vh0);
                mma_bf16(accO[2*nt+1], pah, vh1);
                mma_bf16(accO[2*nt+1], pah, vl1);
                mma_bf16(accO[2*nt+1], pal, vh1);
            }
        }
    }

    // epilogue: rows row0, row0+8; cols d = nf*8 + (lane&3)*2
    float inv0 = 1.0f / l0v, inv1 = 1.0f / l1v;
#pragma unroll
    for (int nf = 0; nf < 16; nf++) {
        int d = nf * 8 + (lane & 3) * 2;
        size_t o0 = (size_t)(b * SS + row0) * 2048 + h * 128 + d;
        size_t o1 = o0 + (size_t)8 * 2048;
        __nv_bfloat162 hh, ll;
        split_store2(accO[nf][0] * inv0, accO[nf][1] * inv0, &hh, &ll);
        *(__nv_bfloat162*)(Oh + o0) = hh;
        *(__nv_bfloat162*)(Ol + o0) = ll;
        split_store2(accO[nf][2] * inv1, accO[nf][3] * inv1, &hh, &ll);
        *(__nv_bfloat162*)(Oh + o1) = hh;
        *(__nv_bfloat162*)(Ol + o1) = ll;
    }
}

// ======================= launch =======================
extern "C" void kernel_launch(void* const* d_in, const int* in_sizes, int n_in,
                              void* d_out, int out_size)
{
    const int*   positions = (const int*)  d_in[0];
    const float* hidden    = (const float*)d_in[1];
    const float* residual  = (const float*)d_in[2];
    const float* ln1       = (const float*)d_in[3];
    const float* ln2       = (const float*)d_in[4];
    const float* wq        = (const float*)d_in[5];
    const float* bq        = (const float*)d_in[6];
    const float* wk        = (const float*)d_in[7];
    const float* bk        = (const float*)d_in[8];
    const float* wv        = (const float*)d_in[9];
    const float* bv        = (const float*)d_in[10];
    const float* wo        = (const float*)d_in[11];
    const float* wgu       = (const float*)d_in[12];
    const float* wd        = (const float*)d_in[13];

    float* out_h   = (float*)d_out;
    float* out_res = out_h + (size_t)out_size / 2;

    float *res1, *qkv, *hattn;
    __nv_bfloat16 *xn_h, *xn_l, *at_h, *at_l, *h2_h, *h2_l, *ac_h, *ac_l;
    __nv_bfloat16 *Qh, *Ql, *Kh, *Kl, *Vh, *Vl;
    __nv_bfloat16 *qkvT_h, *qkvT_l, *woT_h, *woT_l, *guT_h, *guT_l, *wdT_h, *wdT_l;
    cudaGetSymbolAddress((void**)&res1,  g_res1);
    cudaGetSymbolAddress((void**)&qkv,   g_qkv);
    cudaGetSymbolAddress((void**)&hattn, g_hattn);
    cudaGetSymbolAddress((void**)&xn_h,  g_xn_h);
    cudaGetSymbolAddress((void**)&xn_l,  g_xn_l);
    cudaGetSymbolAddress((void**)&at_h,  g_at_h);
    cudaGetSymbolAddress((void**)&at_l,  g_at_l);
    cudaGetSymbolAddress((void**)&h2_h,  g_h2_h);
    cudaGetSymbolAddress((void**)&h2_l,  g_h2_l);
    cudaGetSymbolAddress((void**)&ac_h,  g_ac_h);
    cudaGetSymbolAddress((void**)&ac_l,  g_ac_l);
    cudaGetSymbolAddress((void**)&Qh,    g_Qh);
    cudaGetSymbolAddress((void**)&Ql,    g_Ql);
    cudaGetSymbolAddress((void**)&Kh,    g_Kh);
    cudaGetSymbolAddress((void**)&Kl,    g_Kl);
    cudaGetSymbolAddress((void**)&Vh,    g_Vh);
    cudaGetSymbolAddress((void**)&Vl,    g_Vl);
    cudaGetSymbolAddress((void**)&qkvT_h, g_qkvT_h);
    cudaGetSymbolAddress((void**)&qkvT_l, g_qkvT_l);
    cudaGetSymbolAddress((void**)&woT_h, g_woT_h);
    cudaGetSymbolAddress((void**)&woT_l, g_woT_l);
    cudaGetSymbolAddress((void**)&guT_h, g_guT_h);
    cudaGetSymbolAddress((void**)&guT_l, g_guT_l);
    cudaGetSymbolAddress((void**)&wdT_h, g_wdT_h);
    cudaGetSymbolAddress((void**)&wdT_l, g_wdT_l);

    cudaFuncSetAttribute(gemm_mma<0>, cudaFuncAttributeMaxDynamicSharedMemorySize, GEMM_SMEM);
    cudaFuncSetAttribute(gemm_mma<1>, cudaFuncAttributeMaxDynamicSharedMemorySize, GEMM_SMEM);
    cudaFuncSetAttribute(gemm_mma<2>, cudaFuncAttributeMaxDynamicSharedMemorySize, GEMM_SMEM);
    cudaFuncSetAttribute(flash_mma, cudaFuncAttributeMaxDynamicSharedMemorySize, FLASH_SMEM);

    // 0. weight preprocessing
    wsplit_qkv_kernel<<<dim3(128, 64), dim3(32,8)>>>(wq, wk, wv, qkvT_h, qkvT_l);
    wsplit_kernel<<<dim3(64, 64), dim3(32,8)>>>(wo, woT_h, woT_l, NHQ*HD, HH);
    wsplit_gu_kernel<<<dim3(512, 64), dim3(32,8)>>>(wgu, guT_h, guT_l);
    wsplit_kernel<<<dim3(64, 256), dim3(32,8)>>>(wd, wdT_h, wdT_l, INTER, HH);

    // 1. res1 + rmsnorm
    add_rmsnorm_kernel<<<TT, 256>>>(hidden, residual, ln1, res1, xn_h, xn_l);

    // 2. fused QKV projection
    gemm_mma<1><<<dim3(32, 32), 256, GEMM_SMEM>>>(xn_h, xn_l, qkvT_h, qkvT_l,
        bq, bk, bv, qkv, nullptr, nullptr, TT, 4096, HH);

    // 3. RoPE + split of Q,K ; V transpose + split
    qkconv_kernel<<<(TT * 24 * 64) / 256, 256>>>(qkv, positions, Qh, Ql, Kh, Kl);
    vconv_kernel<<<dim3(SS/32, HD/32, BB*NKV), dim3(32,8)>>>(qkv, Vh, Vl);

    // 4. tensor-core flash attention -> split at_h/at_l
    flash_mma<<<dim3(SS/128, NHQ, BB), 256, FLASH_SMEM>>>(Qh, Ql, Kh, Kl, Vh, Vl, at_h, at_l);

    // 5. output projection
    gemm_mma<0><<<dim3(16, 32), 256, GEMM_SMEM>>>(at_h, at_l, woT_h, woT_l,
        nullptr, nullptr, nullptr, hattn, nullptr, nullptr, TT, HH, NHQ*HD);

    // 6. res2 + rmsnorm
    add_rmsnorm_kernel<<<TT, 256>>>(hattn, res1, ln2, out_res, h2_h, h2_l);

    // 7. gate_up GEMM + fused SwiGLU
    gemm_mma<2><<<dim3(128, 32), 256, GEMM_SMEM>>>(h2_h, h2_l, guT_h, guT_l,
        nullptr, nullptr, nullptr, nullptr, ac_h, ac_l, TT, 16384, HH);

    // 8. down GEMM -> out first half
    gemm_mma<0><<<dim3(16, 32), 256, GEMM_SMEM>>>(ac_h, ac_l, wdT_h, wdT_l,
        nullptr, nullptr, nullptr, out_h, nullptr, nullptr, TT, HH, INTER);
}

// round 9
// speedup vs baseline: 1.7066x; 1.7066x over previous
#include <cuda_runtime.h>
#include <cuda_bf16.h>
#include <cstdint>
#include <math.h>

#define BB 2
#define SS 2048
#define TT (BB*SS)
#define HH 2048
#define NHQ 16
#define NKV 8
#define HD 128
#define INTER 8192
#define EPS 1e-6f

// ======================= scratch =======================
__device__ __align__(256) float g_res1 [(size_t)TT*HH];
__device__ __align__(256) float g_qkv  [(size_t)TT*4096];
__device__ __align__(256) float g_hattn[(size_t)TT*HH];
__device__ float g_invf [64];

__device__ __align__(256) __nv_bfloat16 g_xn_h [(size_t)TT*HH];
__device__ __align__(256) __nv_bfloat16 g_xn_l [(size_t)TT*HH];
__device__ __align__(256) __nv_bfloat16 g_at_h [(size_t)TT*HH];
__device__ __align__(256) __nv_bfloat16 g_at_l [(size_t)TT*HH];
__device__ __align__(256) __nv_bfloat16 g_h2_h [(size_t)TT*HH];
__device__ __align__(256) __nv_bfloat16 g_h2_l [(size_t)TT*HH];
__device__ __align__(256) __nv_bfloat16 g_ac_h [(size_t)TT*INTER];
__device__ __align__(256) __nv_bfloat16 g_ac_l [(size_t)TT*INTER];

// flash operands (bf16 split)
__device__ __align__(256) __nv_bfloat16 g_Qh [(size_t)TT*2048];
__device__ __align__(256) __nv_bfloat16 g_Ql [(size_t)TT*2048];
__device__ __align__(256) __nv_bfloat16 g_Kh [(size_t)TT*1024];
__device__ __align__(256) __nv_bfloat16 g_Kl [(size_t)TT*1024];
__device__ __align__(256) __nv_bfloat16 g_Vh [(size_t)TT*1024];  // [b][hk][d][s]
__device__ __align__(256) __nv_bfloat16 g_Vl [(size_t)TT*1024];

__device__ __align__(256) __nv_bfloat16 g_qkvT_h[(size_t)4096*HH];
__device__ __align__(256) __nv_bfloat16 g_qkvT_l[(size_t)4096*HH];
__device__ __align__(256) __nv_bfloat16 g_woT_h[(size_t)HH*(NHQ*HD)];
__device__ __align__(256) __nv_bfloat16 g_woT_l[(size_t)HH*(NHQ*HD)];
__device__ __align__(256) __nv_bfloat16 g_guT_h[(size_t)(2*INTER)*HH];
__device__ __align__(256) __nv_bfloat16 g_guT_l[(size_t)(2*INTER)*HH];
__device__ __align__(256) __nv_bfloat16 g_wdT_h[(size_t)HH*INTER];
__device__ __align__(256) __nv_bfloat16 g_wdT_l[(size_t)HH*INTER];

// ======================= PTX helpers =======================
__device__ __forceinline__ uint32_t s2u(const void* p) {
    uint32_t a;
    asm("{ .reg .u64 t; cvta.to.shared.u64 t, %1; cvt.u32.u64 %0, t; }" : "=r"(a) : "l"(p));
    return a;
}
__device__ __forceinline__ void cpasync16(uint32_t dst, const void* src) {
    asm volatile("cp.async.cg.shared.global [%0], [%1], 16;" :: "r"(dst), "l"(src) : "memory");
}
__device__ __forceinline__ void cp_commit() { asm volatile("cp.async.commit_group;" ::: "memory"); }
template<int N_>
__device__ __forceinline__ void cp_wait() { asm volatile("cp.async.wait_group %0;" :: "n"(N_) : "memory"); }
__device__ __forceinline__ void ldsm4(uint32_t* r, uint32_t addr) {
    asm volatile("ldmatrix.sync.aligned.m8n8.x4.shared.b16 {%0,%1,%2,%3}, [%4];"
                 : "=r"(r[0]), "=r"(r[1]), "=r"(r[2]), "=r"(r[3]) : "r"(addr));
}
__device__ __forceinline__ void mma_bf16(float* d, const uint32_t* a, const uint32_t* b) {
    asm volatile(
        "mma.sync.aligned.m16n8k16.row.col.f32.bf16.bf16.f32 "
        "{%0,%1,%2,%3}, {%4,%5,%6,%7}, {%8,%9}, {%0,%1,%2,%3};"
        : "+f"(d[0]), "+f"(d[1]), "+f"(d[2]), "+f"(d[3])
        : "r"(a[0]), "r"(a[1]), "r"(a[2]), "r"(a[3]), "r"(b[0]), "r"(b[1]));
}
__device__ __forceinline__ void split_store2(float x, float y, __nv_bfloat162* ph, __nv_bfloat162* pl)
{
    __nv_bfloat16 hx = __float2bfloat16(x), hy = __float2bfloat16(y);
    *ph = __halves2bfloat162(hx, hy);
    *pl = __halves2bfloat162(__float2bfloat16(x - __bfloat162float(hx)),
                             __float2bfloat16(y - __bfloat162float(hy)));
}
__device__ __forceinline__ void split_pack(uint32_t& ph, uint32_t& pl, float x, float y)
{
    __nv_bfloat162 h2, l2;
    split_store2(x, y, &h2, &l2);
    ph = *(uint32_t*)&h2; pl = *(uint32_t*)&l2;
}
__device__ __forceinline__ uint32_t soffG(int r, int u)   { return (uint32_t)(r*128 + ((u ^ (r & 7)) << 4)); }
__device__ __forceinline__ uint32_t soff256(int r, int u) { return (uint32_t)(r*256 + ((u ^ (r & 7)) << 4)); }

// ======================= fused add + RMSNorm =======================
__global__ void add_rmsnorm_kernel(const float* __restrict__ a, const float* __restrict__ b,
                                   const float* __restrict__ w, float* __restrict__ res,
                                   __nv_bfloat16* __restrict__ oh, __nv_bfloat16* __restrict__ ol)
{
    int t = blockIdx.x, tid = threadIdx.x;
    const float4* a4 = (const float4*)(a + (size_t)t * HH);
    const float4* b4 = (const float4*)(b + (size_t)t * HH);
    float4* r4 = (float4*)(res + (size_t)t * HH);
    const float4* w4 = (const float4*)w;
    __nv_bfloat162* oh2 = (__nv_bfloat162*)(oh + (size_t)t * HH);
    __nv_bfloat162* ol2 = (__nv_bfloat162*)(ol + (size_t)t * HH);

    float4 vv[2];
    float ss = 0.f;
#pragma unroll
    for (int ii = 0; ii < 2; ii++) {
        int idx = tid + ii * 256;
        float4 x = a4[idx], y = b4[idx];
        x.x += y.x; x.y += y.y; x.z += y.z; x.w += y.w;
        r4[idx] = x; vv[ii] = x;
        ss += x.x*x.x + x.y*x.y + x.z*x.z + x.w*x.w;
    }
#pragma unroll
    for (int off = 16; off; off >>= 1) ss += __shfl_xor_sync(0xffffffffu, ss, off);
    __shared__ float sh[8];
    __shared__ float s_inv;
    if ((tid & 31) == 0) sh[tid >> 5] = ss;
    __syncthreads();
    if (tid == 0) {
        float s = 0.f;
#pragma unroll
        for (int i = 0; i < 8; i++) s += sh[i];
        s_inv = rsqrtf(s / (float)HH + EPS);
    }
    __syncthreads();
    float inv = s_inv;
#pragma unroll
    for (int ii = 0; ii < 2; ii++) {
        int idx = tid + ii * 256;
        float4 x = vv[ii], ww = w4[idx];
        __nv_bfloat162 h0, l0, h1, l1;
        split_store2(x.x*inv*ww.x, x.y*inv*ww.y, &h0, &l0);
        split_store2(x.z*inv*ww.z, x.w*inv*ww.w, &h1, &l1);
        oh2[idx*2] = h0; oh2[idx*2+1] = h1;
        ol2[idx*2] = l0; ol2[idx*2+1] = l1;
    }
}

// ======================= weight split kernels =======================
__global__ void wsplit_kernel(const float* __restrict__ W,
                              __nv_bfloat16* __restrict__ Th, __nv_bfloat16* __restrict__ Tl,
                              int K, int N)
{
    __shared__ float tile[32][33];
    int k0 = blockIdx.y * 32, n0 = blockIdx.x * 32;
    int tx = threadIdx.x, ty = threadIdx.y;
#pragma unroll
    for (int j = 0; j < 4; j++)
        tile[ty + 8*j][tx] = W[(size_t)(k0 + ty + 8*j) * N + n0 + tx];
    __syncthreads();
#pragma unroll
    for (int j = 0; j < 4; j++) {
        int n = ty + 8*j;
        float v = tile[tx][n];
        __nv_bfloat16 h = __float2bfloat16(v);
        Th[(size_t)(n0 + n) * K + k0 + tx] = h;
        Tl[(size_t)(n0 + n) * K + k0 + tx] = __float2bfloat16(v - __bfloat162float(h));
    }
}

__global__ void wsplit_qkv_kernel(const float* __restrict__ wq, const float* __restrict__ wk,
                                  const float* __restrict__ wv,
                                  __nv_bfloat16* __restrict__ Th, __nv_bfloat16* __restrict__ Tl)
{
    __shared__ float tile[32][33];
    int n0 = blockIdx.x * 32, k0 = blockIdx.y * 32;
    int tx = threadIdx.x, ty = threadIdx.y;
    if (blockIdx.x == 0 && blockIdx.y == 0) {
        int id = ty * 32 + tx;
        if (id < 64) g_invf[id] = (float)pow(1.0e6, -(double)id / 64.0);
    }
    int n = n0 + tx;
    const float* src; int nc, stride;
    if (n < 2048)      { src = wq; nc = n;        stride = 2048; }
    else if (n < 3072) { src = wk; nc = n - 2048; stride = 1024; }
    else               { src = wv; nc = n - 3072; stride = 1024; }
#pragma unroll
    for (int j = 0; j < 4; j++)
        tile[ty + 8*j][tx] = src[(size_t)(k0 + ty + 8*j) * stride + nc];
    __syncthreads();
#pragma unroll
    for (int j = 0; j < 4; j++) {
        int nn = n0 + ty + 8*j;
        float v = tile[tx][ty + 8*j];
        __nv_bfloat16 h = __float2bfloat16(v);
        Th[(size_t)nn * HH + k0 + tx] = h;
        Tl[(size_t)nn * HH + k0 + tx] = __float2bfloat16(v - __bfloat162float(h));
    }
}

__global__ void wsplit_gu_kernel(const float* __restrict__ W,
                                 __nv_bfloat16* __restrict__ Th, __nv_bfloat16* __restrict__ Tl)
{
    __shared__ float tile[32][33];
    int n0 = blockIdx.x * 32, k0 = blockIdx.y * 32;
    int tx = threadIdx.x, ty = threadIdx.y;
    int n = n0 + tx;
    int srccol = (n & 1) ? (8192 + (n >> 1)) : (n >> 1);
#pragma unroll
    for (int j = 0; j < 4; j++)
        tile[ty + 8*j][tx] = W[(size_t)(k0 + ty + 8*j) * 16384 + srccol];
    __syncthreads();
#pragma unroll
    for (int j = 0; j < 4; j++) {
        int nn = n0 + ty + 8*j;
        float v = tile[tx][ty + 8*j];
        __nv_bfloat16 h = __float2bfloat16(v);
        Th[(size_t)nn * HH + k0 + tx] = h;
        Tl[(size_t)nn * HH + k0 + tx] = __float2bfloat16(v - __bfloat162float(h));
    }
}

// ======================= mma.sync bf16-split GEMM (2-stage, occ 2) =======================
#define GS_STAGE 32768
#define GS_B     16384
#define GEMM_SMEM (2*GS_STAGE)

__device__ __forceinline__ void g_load_stage(uint32_t sb, int s,
    const __nv_bfloat16* __restrict__ Ah, const __nv_bfloat16* __restrict__ Al,
    const __nv_bfloat16* __restrict__ Bh, const __nv_bfloat16* __restrict__ Bl,
    int m0, int n0, int k0, int K, int tid)
{
    uint32_t st = sb + s * GS_STAGE;
#pragma unroll
    for (int j = 0; j < 8; j++) {
        int idx = j * 256 + tid;
        int mat = idx >> 10;
        int rem = idx & 1023;
        int r = rem >> 3, u = rem & 7;
        const __nv_bfloat16* src;
        int row = (mat == 0) ? (m0 + r) : (n0 + r);
        if (mat == 0) src = (u < 4) ? Ah : Al;
        else          src = (u < 4) ? Bh : Bl;
        src += (size_t)row * K + k0 + (u & 3) * 8;
        cpasync16(st + mat * GS_B + soffG(r, u), src);
    }
    cp_commit();
}

// MODE 0: f32 out. MODE 1: qkv bias. MODE 2: fused SwiGLU -> bf16 split.
template<int MODE>
__global__ __launch_bounds__(256, 2) void gemm_mma(
    const __nv_bfloat16* __restrict__ Ah, const __nv_bfloat16* __restrict__ Al,
    const __nv_bfloat16* __restrict__ Bh, const __nv_bfloat16* __restrict__ Bl,
    const float* __restrict__ bq, const float* __restrict__ bk, const float* __restrict__ bv,
    float* __restrict__ C, __nv_bfloat16* __restrict__ actH, __nv_bfloat16* __restrict__ actL,
    int M, int N, int K)
{
    extern __shared__ char smc[];
    uint32_t sb = s2u(smc);
    int tid = threadIdx.x, lane = tid & 31, wid = tid >> 5;
    int wm = wid >> 2, wn = wid & 3;
    int m0 = blockIdx.y * 128, n0 = blockIdx.x * 128;

    float acc[4][4][4];
#pragma unroll
    for (int i = 0; i < 4; i++)
#pragma unroll
        for (int j = 0; j < 4; j++)
#pragma unroll
            for (int c = 0; c < 4; c++) acc[i][j][c] = 0.f;

    int rA = lane & 15, uA = lane >> 4;
    int rB = (lane & 7) | ((lane & 16) >> 1), uB = (lane >> 3) & 1;

    int nIter = K / 32;
    g_load_stage(sb, 0, Ah, Al, Bh, Bl, m0, n0, 0, K, tid);
    g_load_stage(sb, 1, Ah, Al, Bh, Bl, m0, n0, 32, K, tid);

    for (int it = 0; it < nIter; it++) {
        if (it + 1 < nIter) cp_wait<1>(); else cp_wait<0>();
        __syncthreads();

        uint32_t st = sb + (it & 1) * GS_STAGE;
#pragma unroll
        for (int ks = 0; ks < 2; ks++) {
            uint32_t ah[4][4], al[4][4];
#pragma unroll
            for (int mt = 0; mt < 4; mt++) {
                int row = wm * 64 + mt * 16 + rA;
                ldsm4(ah[mt], st + soffG(row, ks * 2 + uA));
                ldsm4(al[mt], st + soffG(row, 4 + ks * 2 + uA));
            }
#pragma unroll
            for (int nt = 0; nt < 2; nt++) {
                int row = wn * 32 + nt * 16 + rB;
                uint32_t th4[4], tl4[4];
                ldsm4(th4, st + GS_B + soffG(row, ks * 2 + uB));
                ldsm4(tl4, st + GS_B + soffG(row, 4 + ks * 2 + uB));
#pragma unroll
                for (int half = 0; half < 2; half++) {
                    int nf = nt * 2 + half;
                    uint32_t bh2[2] = {th4[half*2], th4[half*2+1]};
                    uint32_t bl2[2] = {tl4[half*2], tl4[half*2+1]};
#pragma unroll
                    for (int mt = 0; mt < 4; mt++) {
                        mma_bf16(acc[mt][nf], ah[mt], bh2);
                        mma_bf16(acc[mt][nf], ah[mt], bl2);
                        mma_bf16(acc[mt][nf], al[mt], bh2);
                    }
                }
            }
        }
        __syncthreads();   // all warps done reading stage (it&1)
        if (it + 2 < nIter)
            g_load_stage(sb, it & 1, Ah, Al, Bh, Bl, m0, n0, (it + 2) * 32, K, tid);
    }

    int crow = lane >> 2, ccol = (lane & 3) * 2;
#pragma unroll
    for (int mt = 0; mt < 4; mt++) {
#pragma unroll
        for (int nf = 0; nf < 4; nf++) {
            int r = m0 + wm * 64 + mt * 16 + crow;
            int cidx = n0 + wn * 32 + nf * 8 + ccol;
            if (MODE == 2) {
                int jj = cidx >> 1;
                float ga = acc[mt][nf][0], up = acc[mt][nf][1];
                float v0 = ga / (1.f + __expf(-ga)) * up;
                float gb = acc[mt][nf][2], ub = acc[mt][nf][3];
                float v1 = gb / (1.f + __expf(-gb)) * ub;
                __nv_bfloat16 h0 = __float2bfloat16(v0);
                actH[(size_t)r * INTER + jj] = h0;
                actL[(size_t)r * INTER + jj] = __float2bfloat16(v0 - __bfloat162float(h0));
                __nv_bfloat16 h1 = __float2bfloat16(v1);
                actH[(size_t)(r + 8) * INTER + jj] = h1;
                actL[(size_t)(r + 8) * INTER + jj] = __float2bfloat16(v1 - __bfloat162float(h1));
            } else {
                float b0 = 0.f, b1 = 0.f;
                if (MODE == 1) {
                    b0 = (cidx < 2048) ? bq[cidx] : ((cidx < 3072) ? bk[cidx - 2048] : bv[cidx - 3072]);
                    int c1 = cidx + 1;
                    b1 = (c1 < 2048) ? bq[c1] : ((c1 < 3072) ? bk[c1 - 2048] : bv[c1 - 3072]);
                }
                *(float2*)(C + (size_t)r * N + cidx) =
                    make_float2(acc[mt][nf][0] + b0, acc[mt][nf][1] + b1);
                *(float2*)(C + (size_t)(r + 8) * N + cidx) =
                    make_float2(acc[mt][nf][2] + b0, acc[mt][nf][3] + b1);
            }
        }
    }
}

// ======================= RoPE + split of Q,K =======================
__global__ void qkconv_kernel(const float* __restrict__ qkv, const int* __restrict__ pos,
    __nv_bfloat16* __restrict__ Qh, __nv_bfloat16* __restrict__ Ql,
    __nv_bfloat16* __restrict__ Kh, __nv_bfloat16* __restrict__ Kl)
{
    int idx = blockIdx.x * blockDim.x + threadIdx.x;
    int i = idx & 63;
    int rest = idx >> 6;
    int head = rest % 24;
    int t = rest / 24;
    if (t >= TT) return;
    const float* p = qkv + (size_t)t * 4096 + ((head < 16) ? head * 128 : 2048 + (head - 16) * 128);
    float ang = (float)pos[t] * g_invf[i];
    float sv, cv;
    sincosf(ang, &sv, &cv);
    float x1 = p[i], x2 = p[i + 64];
    float o1 = x1 * cv - x2 * sv;
    float o2 = x2 * cv + x1 * sv;
    __nv_bfloat16 *dh, *dl;
    size_t dst;
    if (head < 16) { dst = (size_t)t * 2048 + head * 128;        dh = Qh; dl = Ql; }
    else           { dst = (size_t)t * 1024 + (head - 16) * 128; dh = Kh; dl = Kl; }
    __nv_bfloat16 h1 = __float2bfloat16(o1);
    dh[dst + i] = h1;
    dl[dst + i] = __float2bfloat16(o1 - __bfloat162float(h1));
    __nv_bfloat16 h2 = __float2bfloat16(o2);
    dh[dst + i + 64] = h2;
    dl[dst + i + 64] = __float2bfloat16(o2 - __bfloat162float(h2));
}

// ======================= V transpose + split =======================
__global__ void vconv_kernel(const float* __restrict__ qkv,
    __nv_bfloat16* __restrict__ Vh, __nv_bfloat16* __restrict__ Vl)
{
    __shared__ float tile[32][33];
    int bhk = blockIdx.z;
    int b = bhk >> 3, hk = bhk & 7;
    int s0 = blockIdx.x * 32, d0 = blockIdx.y * 32;
    int tx = threadIdx.x, ty = threadIdx.y;
#pragma unroll
    for (int j = 0; j < 4; j++)
        tile[ty + 8*j][tx] = qkv[(size_t)(b * SS + s0 + ty + 8*j) * 4096 + 3072 + hk * 128 + d0 + tx];
    __syncthreads();
#pragma unroll
    for (int j = 0; j < 4; j++) {
        int d = d0 + ty + 8*j;
        float v = tile[tx][ty + 8*j];
        __nv_bfloat16 h = __float2bfloat16(v);
        size_t o = ((size_t)(b * NKV + hk) * HD + d) * SS + s0 + tx;
        Vh[o] = h;
        Vl[o] = __float2bfloat16(v - __bfloat162float(h));
    }
}

// ======================= tensor-core causal flash attention =======================
#define FQ_H 0
#define FQ_L 32768
#define FST(s) (65536 + (s)*65536)
#define FK_H 0
#define FK_L 16384
#define FV_H 32768
#define FV_L 49152
#define FLASH_SMEM (65536 + 2*65536)

__global__ __launch_bounds__(256, 1) void flash_mma(
    const __nv_bfloat16* __restrict__ Qh, const __nv_bfloat16* __restrict__ Ql,
    const __nv_bfloat16* __restrict__ Kh, const __nv_bfloat16* __restrict__ Kl,
    const __nv_bfloat16* __restrict__ Vh, const __nv_bfloat16* __restrict__ Vl,
    __nv_bfloat16* __restrict__ Oh, __nv_bfloat16* __restrict__ Ol)
{
    extern __shared__ char smc[];
    uint32_t sb = s2u(smc);
    int tid = threadIdx.x, lane = tid & 31, wid = tid >> 5;
    int qt = (gridDim.x - 1) - blockIdx.x;   // heaviest CTAs first
    int h = blockIdx.y, b = blockIdx.z;
    int hk = h >> 1;
    int q0 = qt * 128;
    int rA = lane & 15, uA = lane >> 4;
    int rB = (lane & 7) | ((lane & 16) >> 1), uB = (lane >> 3) & 1;

#pragma unroll
    for (int j = 0; j < 16; j++) {
        int idx = j * 256 + tid;
        int arr = idx >> 11, rem = idx & 2047;
        int r = rem >> 4, u = rem & 15;
        const __nv_bfloat16* src = (arr ? Ql : Qh) + (size_t)(b * SS + q0 + r) * 2048 + h * 128 + u * 8;
        cpasync16(sb + (arr ? FQ_L : FQ_H) + soff256(r, u), src);
    }

    auto load_kv = [&](int buf, int kbase) {
        uint32_t st = sb + FST(buf);
#pragma unroll
        for (int j = 0; j < 8; j++) {
            int idx = j * 256 + tid;
            int arr = idx >> 10, rem = idx & 1023;
            int r = rem >> 4, u = rem & 15;
            const __nv_bfloat16* src = (arr ? Kl : Kh) + (size_t)(b * SS + kbase + r) * 1024 + hk * 128 + u * 8;
            cpasync16(st + (arr ? FK_L : FK_H) + soff256(r, u), src);
        }
#pragma unroll
        for (int j = 0; j < 8; j++) {
            int idx = j * 256 + tid;
            int arr = idx >> 10, rem = idx & 1023;
            int r = rem >> 3, u = rem & 7;
            const __nv_bfloat16* src = (arr ? Vl : Vh) + ((size_t)(b * NKV + hk) * HD + r) * SS + kbase + u * 8;
            cpasync16(st + (arr ? FV_L : FV_H) + soffG(r, u), src);
        }
        cp_commit();
    };
    load_kv(0, 0);

    float m0v = -1e30f, m1v = -1e30f, l0v = 0.f, l1v = 0.f;
    float accO[16][4];
#pragma unroll
    for (int i = 0; i < 16; i++)
#pragma unroll
        for (int c = 0; c < 4; c++) accO[i][c] = 0.f;

    const float sc = 0.08838834764831845f;
    int ktmax = 2 * qt + 1;
    int row0 = q0 + wid * 16 + (lane >> 2);

    for (int kt = 0; kt <= ktmax; kt++) {
        cp_wait<0>();
        __syncthreads();
        if (kt < ktmax) load_kv((kt + 1) & 1, (kt + 1) * 64);
        uint32_t st = sb + FST(kt & 1);

        float accS[8][4];
#pragma unroll
        for (int i = 0; i < 8; i++)
#pragma unroll
            for (int c = 0; c < 4; c++) accS[i][c] = 0.f;

#pragma unroll
        for (int j = 0; j < 8; j++) {
            uint32_t ahf[4], alf[4];
            uint32_t qoff = soff256(wid * 16 + rA, 2 * j + uA);
            ldsm4(ahf, sb + FQ_H + qoff);
            ldsm4(alf, sb + FQ_L + qoff);
            uint32_t bhf[8][2], blf[8][2];
#pragma unroll
            for (int nt = 0; nt < 4; nt++) {
                uint32_t koff = soff256(nt * 16 + rB, 2 * j + uB);
                uint32_t t4[4];
                ldsm4(t4, st + FK_H + koff);
                bhf[2*nt][0] = t4[0]; bhf[2*nt][1] = t4[1];
                bhf[2*nt+1][0] = t4[2]; bhf[2*nt+1][1] = t4[3];
                ldsm4(t4, st + FK_L + koff);
                blf[2*nt][0] = t4[0]; blf[2*nt][1] = t4[1];
                blf[2*nt+1][0] = t4[2]; blf[2*nt+1][1] = t4[3];
            }
#pragma unroll
            for (int nf = 0; nf < 8; nf++) {
                mma_bf16(accS[nf], ahf, bhf[nf]);
                mma_bf16(accS[nf], ahf, blf[nf]);
                mma_bf16(accS[nf], alf, bhf[nf]);
            }
        }

        int kbase = kt * 64;
        bool needmask = (kbase + 63) > row0;
#pragma unroll
        for (int nf = 0; nf < 8; nf++) {
#pragma unroll
            for (int e = 0; e < 4; e++) {
                float s = accS[nf][e] * sc;
                if (needmask) {
                    int cc = kbase + nf * 8 + (lane & 3) * 2 + (e & 1);
                    int rr = row0 + ((e >> 1) << 3);
                    if (cc > rr) s = -1e30f;
                }
                accS[nf][e] = s;
            }
        }
        float vm0 = -1e30f, vm1 = -1e30f;
#pragma unroll
        for (int nf = 0; nf < 8; nf++) {
            vm0 = fmaxf(vm0, fmaxf(accS[nf][0], accS[nf][1]));
            vm1 = fmaxf(vm1, fmaxf(accS[nf][2], accS[nf][3]));
        }
        vm0 = fmaxf(vm0, __shfl_xor_sync(0xffffffffu, vm0, 1));
        vm0 = fmaxf(vm0, __shfl_xor_sync(0xffffffffu, vm0, 2));
        vm1 = fmaxf(vm1, __shfl_xor_sync(0xffffffffu, vm1, 1));
        vm1 = fmaxf(vm1, __shfl_xor_sync(0xffffffffu, vm1, 2));
        float mn0 = fmaxf(m0v, vm0), mn1 = fmaxf(m1v, vm1);
        float c0 = __expf(m0v - mn0), c1 = __expf(m1v - mn1);
        float s0 = 0.f, s1 = 0.f;
#pragma unroll
        for (int nf = 0; nf < 8; nf++) {
            accS[nf][0] = __expf(accS[nf][0] - mn0); s0 += accS[nf][0];
            accS[nf][1] = __expf(accS[nf][1] - mn0); s0 += accS[nf][1];
            accS[nf][2] = __expf(accS[nf][2] - mn1); s1 += accS[nf][2];
            accS[nf][3] = __expf(accS[nf][3] - mn1); s1 += accS[nf][3];
        }
        s0 += __shfl_xor_sync(0xffffffffu, s0, 1);
        s0 += __shfl_xor_sync(0xffffffffu, s0, 2);
        s1 += __shfl_xor_sync(0xffffffffu, s1, 1);
        s1 += __shfl_xor_sync(0xffffffffu, s1, 2);
        l0v = l0v * c0 + s0; l1v = l1v * c1 + s1;
        m0v = mn0; m1v = mn1;
#pragma unroll
        for (int i = 0; i < 16; i++) {
            accO[i][0] *= c0; accO[i][1] *= c0;
            accO[i][2] *= c1; accO[i][3] *= c1;
        }

#pragma unroll
        for (int j2 = 0; j2 < 4; j2++) {
            uint32_t pah[4], pal[4];
            split_pack(pah[0], pal[0], accS[2*j2][0],   accS[2*j2][1]);
            split_pack(pah[1], pal[1], accS[2*j2][2],   accS[2*j2][3]);
            split_pack(pah[2], pal[2], accS[2*j2+1][0], accS[2*j2+1][1]);
            split_pack(pah[3], pal[3], accS[2*j2+1][2], accS[2*j2+1][3]);
#pragma unroll
            for (int nt = 0; nt < 8; nt++) {
                uint32_t voff = soffG(nt * 16 + rB, 2 * j2 + uB);
                uint32_t t4[4], vh0[2], vh1[2], vl0[2], vl1[2];
                ldsm4(t4, st + FV_H + voff);
                vh0[0] = t4[0]; vh0[1] = t4[1]; vh1[0] = t4[2]; vh1[1] = t4[3];
                ldsm4(t4, st + FV_L + voff);
                vl0[0] = t4[0]; vl0[1] = t4[1]; vl1[0] = t4[2]; vl1[1] = t4[3];
                mma_bf16(accO[2*nt],   pah, vh0);
                mma_bf16(accO[2*nt],   pah, vl0);
                mma_bf16(accO[2*nt],   pal, vh0);
                mma_bf16(accO[2*nt+1], pah, vh1);
                mma_bf16(accO[2*nt+1], pah, vl1);
                mma_bf16(accO[2*nt+1], pal, vh1);
            }
        }
    }

    float inv0 = 1.0f / l0v, inv1 = 1.0f / l1v;
#pragma unroll
    for (int nf = 0; nf < 16; nf++) {
        int d = nf * 8 + (lane & 3) * 2;
        size_t o0 = (size_t)(b * SS + row0) * 2048 + h * 128 + d;
        size_t o1 = o0 + (size_t)8 * 2048;
        __nv_bfloat162 hh, ll;
        split_store2(accO[nf][0] * inv0, accO[nf][1] * inv0, &hh, &ll);
        *(__nv_bfloat162*)(Oh + o0) = hh;
        *(__nv_bfloat162*)(Ol + o0) = ll;
        split_store2(accO[nf][2] * inv1, accO[nf][3] * inv1, &hh, &ll);
        *(__nv_bfloat162*)(Oh + o1) = hh;
        *(__nv_bfloat162*)(Ol + o1) = ll;
    }
}

// ======================= launch =======================
extern "C" void kernel_launch(void* const* d_in, const int* in_sizes, int n_in,
                              void* d_out, int out_size)
{
    const int*   positions = (const int*)  d_in[0];
    const float* hidden    = (const float*)d_in[1];
    const float* residual  = (const float*)d_in[2];
    const float* ln1       = (const float*)d_in[3];
    const float* ln2       = (const float*)d_in[4];
    const float* wq        = (const float*)d_in[5];
    const float* bq        = (const float*)d_in[6];
    const float* wk        = (const float*)d_in[7];
    const float* bk        = (const float*)d_in[8];
    const float* wv        = (const float*)d_in[9];
    const float* bv        = (const float*)d_in[10];
    const float* wo        = (const float*)d_in[11];
    const float* wgu       = (const float*)d_in[12];
    const float* wd        = (const float*)d_in[13];

    float* out_h   = (float*)d_out;
    float* out_res = out_h + (size_t)out_size / 2;

    float *res1, *qkv, *hattn;
    __nv_bfloat16 *xn_h, *xn_l, *at_h, *at_l, *h2_h, *h2_l, *ac_h, *ac_l;
    __nv_bfloat16 *Qh, *Ql, *Kh, *Kl, *Vh, *Vl;
    __nv_bfloat16 *qkvT_h, *qkvT_l, *woT_h, *woT_l, *guT_h, *guT_l, *wdT_h, *wdT_l;
    cudaGetSymbolAddress((void**)&res1,  g_res1);
    cudaGetSymbolAddress((void**)&qkv,   g_qkv);
    cudaGetSymbolAddress((void**)&hattn, g_hattn);
    cudaGetSymbolAddress((void**)&xn_h,  g_xn_h);
    cudaGetSymbolAddress((void**)&xn_l,  g_xn_l);
    cudaGetSymbolAddress((void**)&at_h,  g_at_h);
    cudaGetSymbolAddress((void**)&at_l,  g_at_l);
    cudaGetSymbolAddress((void**)&h2_h,  g_h2_h);
    cudaGetSymbolAddress((void**)&h2_l,  g_h2_l);
    cudaGetSymbolAddress((void**)&ac_h,  g_ac_h);
    cudaGetSymbolAddress((void**)&ac_l,  g_ac_l);
    cudaGetSymbolAddress((void**)&Qh,    g_Qh);
    cudaGetSymbolAddress((void**)&Ql,    g_Ql);
    cudaGetSymbolAddress((void**)&Kh,    g_Kh);
    cudaGetSymbolAddress((void**)&Kl,    g_Kl);
    cudaGetSymbolAddress((void**)&Vh,    g_Vh);
    cudaGetSymbolAddress((void**)&Vl,    g_Vl);
    cudaGetSymbolAddress((void**)&qkvT_h, g_qkvT_h);
    cudaGetSymbolAddress((void**)&qkvT_l, g_qkvT_l);
    cudaGetSymbolAddress((void**)&woT_h, g_woT_h);
    cudaGetSymbolAddress((void**)&woT_l, g_woT_l);
    cudaGetSymbolAddress((void**)&guT_h, g_guT_h);
    cudaGetSymbolAddress((void**)&guT_l, g_guT_l);
    cudaGetSymbolAddress((void**)&wdT_h, g_wdT_h);
    cudaGetSymbolAddress((void**)&wdT_l, g_wdT_l);

    cudaFuncSetAttribute(gemm_mma<0>, cudaFuncAttributeMaxDynamicSharedMemorySize, GEMM_SMEM);
    cudaFuncSetAttribute(gemm_mma<1>, cudaFuncAttributeMaxDynamicSharedMemorySize, GEMM_SMEM);
    cudaFuncSetAttribute(gemm_mma<2>, cudaFuncAttributeMaxDynamicSharedMemorySize, GEMM_SMEM);
    cudaFuncSetAttribute(flash_mma, cudaFuncAttributeMaxDynamicSharedMemorySize, FLASH_SMEM);

    // 0. weight preprocessing
    wsplit_qkv_kernel<<<dim3(128, 64), dim3(32,8)>>>(wq, wk, wv, qkvT_h, qkvT_l);
    wsplit_kernel<<<dim3(64, 64), dim3(32,8)>>>(wo, woT_h, woT_l, NHQ*HD, HH);
    wsplit_gu_kernel<<<dim3(512, 64), dim3(32,8)>>>(wgu, guT_h, guT_l);
    wsplit_kernel<<<dim3(64, 256), dim3(32,8)>>>(wd, wdT_h, wdT_l, INTER, HH);

    // 1. res1 + rmsnorm
    add_rmsnorm_kernel<<<TT, 256>>>(hidden, residual, ln1, res1, xn_h, xn_l);

    // 2. fused QKV projection
    gemm_mma<1><<<dim3(32, 32), 256, GEMM_SMEM>>>(xn_h, xn_l, qkvT_h, qkvT_l,
        bq, bk, bv, qkv, nullptr, nullptr, TT, 4096, HH);

    // 3. RoPE + split of Q,K ; V transpose + split
    qkconv_kernel<<<(TT * 24 * 64) / 256, 256>>>(qkv, positions, Qh, Ql, Kh, Kl);
    vconv_kernel<<<dim3(SS/32, HD/32, BB*NKV), dim3(32,8)>>>(qkv, Vh, Vl);

    // 4. tensor-core flash attention -> split at_h/at_l
    flash_mma<<<dim3(SS/128, NHQ, BB), 256, FLASH_SMEM>>>(Qh, Ql, Kh, Kl, Vh, Vl, at_h, at_l);

    // 5. output projection
    gemm_mma<0><<<dim3(16, 32), 256, GEMM_SMEM>>>(at_h, at_l, woT_h, woT_l,
        nullptr, nullptr, nullptr, hattn, nullptr, nullptr, TT, HH, NHQ*HD);

    // 6. res2 + rmsnorm
    add_rmsnorm_kernel<<<TT, 256>>>(hattn, res1, ln2, out_res, h2_h, h2_l);

    // 7. gate_up GEMM + fused SwiGLU
    gemm_mma<2><<<dim3(128, 32), 256, GEMM_SMEM>>>(h2_h, h2_l, guT_h, guT_l,
        nullptr, nullptr, nullptr, nullptr, ac_h, ac_l, TT, 16384, HH);

    // 8. down GEMM -> out first half
    gemm_mma<0><<<dim3(16, 32), 256, GEMM_SMEM>>>(ac_h, ac_l, wdT_h, wdT_l,
        nullptr, nullptr, nullptr, out_h, nullptr, nullptr, TT, HH, INTER);
}

// round 10
// speedup vs baseline: 2.5912x; 1.5183x over previous
#include <cuda_runtime.h>
#include <cuda_bf16.h>
#include <cuda_fp16.h>
#include <cstdint>
#include <math.h>

#define BB 2
#define SS 2048
#define TT (BB*SS)
#define HH 2048
#define NHQ 16
#define NKV 8
#define HD 128
#define INTER 8192
#define EPS 1e-6f

// ======================= scratch =======================
__device__ __align__(256) float g_res1 [(size_t)TT*HH];
__device__ __align__(256) float g_qkv  [(size_t)TT*4096];
__device__ __align__(256) float g_hattn[(size_t)TT*HH];
__device__ float g_invf [64];

// fp16 split activations (A operands)
__device__ __align__(256) __half g_xn_h [(size_t)TT*HH];
__device__ __align__(256) __half g_xn_l [(size_t)TT*HH];
__device__ __align__(256) __half g_at_h [(size_t)TT*HH];
__device__ __align__(256) __half g_at_l [(size_t)TT*HH];
__device__ __align__(256) __half g_h2_h [(size_t)TT*HH];
__device__ __align__(256) __half g_h2_l [(size_t)TT*HH];
__device__ __align__(256) __half g_ac_h [(size_t)TT*INTER];
__device__ __align__(256) __half g_ac_l [(size_t)TT*INTER];

// flash operands (bf16 split, 3-term)
__device__ __align__(256) __nv_bfloat16 g_Qh [(size_t)TT*2048];
__device__ __align__(256) __nv_bfloat16 g_Ql [(size_t)TT*2048];
__device__ __align__(256) __nv_bfloat16 g_Kh [(size_t)TT*1024];
__device__ __align__(256) __nv_bfloat16 g_Kl [(size_t)TT*1024];
__device__ __align__(256) __nv_bfloat16 g_Vh [(size_t)TT*1024];  // [b][hk][d][s]
__device__ __align__(256) __nv_bfloat16 g_Vl [(size_t)TT*1024];

// single-fp16 transposed weights [N, K]
__device__ __align__(256) __half g_qkvT[(size_t)4096*HH];
__device__ __align__(256) __half g_woT [(size_t)HH*(NHQ*HD)];
__device__ __align__(256) __half g_guT [(size_t)(2*INTER)*HH];   // interleaved gate/up
__device__ __align__(256) __half g_wdT [(size_t)HH*INTER];

// ======================= PTX helpers =======================
__device__ __forceinline__ uint32_t s2u(const void* p) {
    uint32_t a;
    asm("{ .reg .u64 t; cvta.to.shared.u64 t, %1; cvt.u32.u64 %0, t; }" : "=r"(a) : "l"(p));
    return a;
}
__device__ __forceinline__ void cpasync16(uint32_t dst, const void* src) {
    asm volatile("cp.async.cg.shared.global [%0], [%1], 16;" :: "r"(dst), "l"(src) : "memory");
}
__device__ __forceinline__ void cp_commit() { asm volatile("cp.async.commit_group;" ::: "memory"); }
template<int N_>
__device__ __forceinline__ void cp_wait() { asm volatile("cp.async.wait_group %0;" :: "n"(N_) : "memory"); }
__device__ __forceinline__ void ldsm4(uint32_t* r, uint32_t addr) {
    asm volatile("ldmatrix.sync.aligned.m8n8.x4.shared.b16 {%0,%1,%2,%3}, [%4];"
                 : "=r"(r[0]), "=r"(r[1]), "=r"(r[2]), "=r"(r[3]) : "r"(addr));
}
__device__ __forceinline__ void mma_bf16(float* d, const uint32_t* a, const uint32_t* b) {
    asm volatile(
        "mma.sync.aligned.m16n8k16.row.col.f32.bf16.bf16.f32 "
        "{%0,%1,%2,%3}, {%4,%5,%6,%7}, {%8,%9}, {%0,%1,%2,%3};"
        : "+f"(d[0]), "+f"(d[1]), "+f"(d[2]), "+f"(d[3])
        : "r"(a[0]), "r"(a[1]), "r"(a[2]), "r"(a[3]), "r"(b[0]), "r"(b[1]));
}
__device__ __forceinline__ void mma_f16(float* d, const uint32_t* a, const uint32_t* b) {
    asm volatile(
        "mma.sync.aligned.m16n8k16.row.col.f32.f16.f16.f32 "
        "{%0,%1,%2,%3}, {%4,%5,%6,%7}, {%8,%9}, {%0,%1,%2,%3};"
        : "+f"(d[0]), "+f"(d[1]), "+f"(d[2]), "+f"(d[3])
        : "r"(a[0]), "r"(a[1]), "r"(a[2]), "r"(a[3]), "r"(b[0]), "r"(b[1]));
}
// bf16 split (flash)
__device__ __forceinline__ void split_store2(float x, float y, __nv_bfloat162* ph, __nv_bfloat162* pl)
{
    __nv_bfloat16 hx = __float2bfloat16(x), hy = __float2bfloat16(y);
    *ph = __halves2bfloat162(hx, hy);
    *pl = __halves2bfloat162(__float2bfloat16(x - __bfloat162float(hx)),
                             __float2bfloat16(y - __bfloat162float(hy)));
}
__device__ __forceinline__ void split_pack(uint32_t& ph, uint32_t& pl, float x, float y)
{
    __nv_bfloat162 h2, l2;
    split_store2(x, y, &h2, &l2);
    ph = *(uint32_t*)&h2; pl = *(uint32_t*)&l2;
}
// fp16 split (GEMM A operands)
__device__ __forceinline__ void split_store2h(float x, float y, __half2* ph, __half2* pl)
{
    __half hx = __float2half(x), hy = __float2half(y);
    *ph = __halves2half2(hx, hy);
    *pl = __halves2half2(__float2half(x - __half2float(hx)),
                         __float2half(y - __half2float(hy)));
}
__device__ __forceinline__ uint32_t soffG(int r, int u)   { return (uint32_t)(r*128 + ((u ^ (r & 7)) << 4)); }
__device__ __forceinline__ uint32_t soff256(int r, int u) { return (uint32_t)(r*256 + ((u ^ (r & 7)) << 4)); }

// ======================= fused add + RMSNorm (fp16-split out) =======================
__global__ void add_rmsnorm_kernel(const float* __restrict__ a, const float* __restrict__ b,
                                   const float* __restrict__ w, float* __restrict__ res,
                                   __half* __restrict__ oh, __half* __restrict__ ol)
{
    int t = blockIdx.x, tid = threadIdx.x;
    const float4* a4 = (const float4*)(a + (size_t)t * HH);
    const float4* b4 = (const float4*)(b + (size_t)t * HH);
    float4* r4 = (float4*)(res + (size_t)t * HH);
    const float4* w4 = (const float4*)w;
    __half2* oh2 = (__half2*)(oh + (size_t)t * HH);
    __half2* ol2 = (__half2*)(ol + (size_t)t * HH);

    float4 vv[2];
    float ss = 0.f;
#pragma unroll
    for (int ii = 0; ii < 2; ii++) {
        int idx = tid + ii * 256;
        float4 x = a4[idx], y = b4[idx];
        x.x += y.x; x.y += y.y; x.z += y.z; x.w += y.w;
        r4[idx] = x; vv[ii] = x;
        ss += x.x*x.x + x.y*x.y + x.z*x.z + x.w*x.w;
    }
#pragma unroll
    for (int off = 16; off; off >>= 1) ss += __shfl_xor_sync(0xffffffffu, ss, off);
    __shared__ float sh[8];
    __shared__ float s_inv;
    if ((tid & 31) == 0) sh[tid >> 5] = ss;
    __syncthreads();
    if (tid == 0) {
        float s = 0.f;
#pragma unroll
        for (int i = 0; i < 8; i++) s += sh[i];
        s_inv = rsqrtf(s / (float)HH + EPS);
    }
    __syncthreads();
    float inv = s_inv;
#pragma unroll
    for (int ii = 0; ii < 2; ii++) {
        int idx = tid + ii * 256;
        float4 x = vv[ii], ww = w4[idx];
        __half2 h0, l0, h1, l1;
        split_store2h(x.x*inv*ww.x, x.y*inv*ww.y, &h0, &l0);
        split_store2h(x.z*inv*ww.z, x.w*inv*ww.w, &h1, &l1);
        oh2[idx*2] = h0; oh2[idx*2+1] = h1;
        ol2[idx*2] = l0; ol2[idx*2+1] = l1;
    }
}

// ======================= weight split kernels (single fp16) =======================
__global__ void wsplit_kernel(const float* __restrict__ W, __half* __restrict__ Tw, int K, int N)
{
    __shared__ float tile[32][33];
    int k0 = blockIdx.y * 32, n0 = blockIdx.x * 32;
    int tx = threadIdx.x, ty = threadIdx.y;
#pragma unroll
    for (int j = 0; j < 4; j++)
        tile[ty + 8*j][tx] = W[(size_t)(k0 + ty + 8*j) * N + n0 + tx];
    __syncthreads();
#pragma unroll
    for (int j = 0; j < 4; j++) {
        int n = ty + 8*j;
        Tw[(size_t)(n0 + n) * K + k0 + tx] = __float2half(tile[tx][n]);
    }
}

__global__ void wsplit_qkv_kernel(const float* __restrict__ wq, const float* __restrict__ wk,
                                  const float* __restrict__ wv, __half* __restrict__ Tw)
{
    __shared__ float tile[32][33];
    int n0 = blockIdx.x * 32, k0 = blockIdx.y * 32;
    int tx = threadIdx.x, ty = threadIdx.y;
    if (blockIdx.x == 0 && blockIdx.y == 0) {
        int id = ty * 32 + tx;
        if (id < 64) g_invf[id] = (float)pow(1.0e6, -(double)id / 64.0);
    }
    int n = n0 + tx;
    const float* src; int nc, stride;
    if (n < 2048)      { src = wq; nc = n;        stride = 2048; }
    else if (n < 3072) { src = wk; nc = n - 2048; stride = 1024; }
    else               { src = wv; nc = n - 3072; stride = 1024; }
#pragma unroll
    for (int j = 0; j < 4; j++)
        tile[ty + 8*j][tx] = src[(size_t)(k0 + ty + 8*j) * stride + nc];
    __syncthreads();
#pragma unroll
    for (int j = 0; j < 4; j++) {
        int nn = n0 + ty + 8*j;
        Tw[(size_t)nn * HH + k0 + tx] = __float2half(tile[tx][ty + 8*j]);
    }
}

__global__ void wsplit_gu_kernel(const float* __restrict__ W, __half* __restrict__ Tw)
{
    __shared__ float tile[32][33];
    int n0 = blockIdx.x * 32, k0 = blockIdx.y * 32;
    int tx = threadIdx.x, ty = threadIdx.y;
    int n = n0 + tx;
    int srccol = (n & 1) ? (8192 + (n >> 1)) : (n >> 1);
#pragma unroll
    for (int j = 0; j < 4; j++)
        tile[ty + 8*j][tx] = W[(size_t)(k0 + ty + 8*j) * 16384 + srccol];
    __syncthreads();
#pragma unroll
    for (int j = 0; j < 4; j++) {
        int nn = n0 + ty + 8*j;
        Tw[(size_t)nn * HH + k0 + tx] = __float2half(tile[tx][ty + 8*j]);
    }
}

// ======================= fp16 2-term GEMM (BK=64, 2-stage, occ 2) =======================
// stage: A-hi [128r x 128B] | A-lo [128r x 128B] | B [128r x 128B]  = 48KB
#define G3_AL 16384
#define G3_B  32768
#define G3_STAGE 49152
#define GEMM_SMEM (2*G3_STAGE)

__device__ __forceinline__ void g_load_stage(uint32_t sb, int s,
    const __half* __restrict__ Ah, const __half* __restrict__ Al, const __half* __restrict__ Bw,
    int m0, int n0, int k0, int K, int tid)
{
    uint32_t st = sb + s * G3_STAGE;
#pragma unroll
    for (int j = 0; j < 12; j++) {
        int idx = j * 256 + tid;
        int seg = idx >> 10;
        int rem = idx & 1023;
        int r = rem >> 3, u = rem & 7;
        const __half* src;
        if (seg == 0)      src = Ah + (size_t)(m0 + r) * K;
        else if (seg == 1) src = Al + (size_t)(m0 + r) * K;
        else               src = Bw + (size_t)(n0 + r) * K;
        src += k0 + u * 8;
        cpasync16(st + seg * 16384 + soffG(r, u), src);
    }
    cp_commit();
}

// MODE 0: f32 out. MODE 1: qkv bias. MODE 2: fused SwiGLU -> fp16 split.
template<int MODE>
__global__ __launch_bounds__(256, 2) void gemm_mma(
    const __half* __restrict__ Ah, const __half* __restrict__ Al, const __half* __restrict__ Bw,
    const float* __restrict__ bq, const float* __restrict__ bk, const float* __restrict__ bv,
    float* __restrict__ C, __half* __restrict__ actH, __half* __restrict__ actL,
    int M, int N, int K)
{
    extern __shared__ char smc[];
    uint32_t sb = s2u(smc);
    int tid = threadIdx.x, lane = tid & 31, wid = tid >> 5;
    int wm = wid >> 2, wn = wid & 3;
    int m0 = blockIdx.y * 128, n0 = blockIdx.x * 128;

    float acc[4][4][4];
#pragma unroll
    for (int i = 0; i < 4; i++)
#pragma unroll
        for (int j = 0; j < 4; j++)
#pragma unroll
            for (int c = 0; c < 4; c++) acc[i][j][c] = 0.f;

    int rA = lane & 15, uA = lane >> 4;
    int rB = (lane & 7) | ((lane & 16) >> 1), uB = (lane >> 3) & 1;

    int nIter = K / 64;
    g_load_stage(sb, 0, Ah, Al, Bw, m0, n0, 0, K, tid);
    g_load_stage(sb, 1, Ah, Al, Bw, m0, n0, 64, K, tid);

    for (int it = 0; it < nIter; it++) {
        if (it + 1 < nIter) cp_wait<1>(); else cp_wait<0>();
        __syncthreads();

        uint32_t st = sb + (it & 1) * G3_STAGE;
#pragma unroll
        for (int ks = 0; ks < 4; ks++) {
            uint32_t ah[4][4], al[4][4];
#pragma unroll
            for (int mt = 0; mt < 4; mt++) {
                int row = wm * 64 + mt * 16 + rA;
                ldsm4(ah[mt], st + soffG(row, ks * 2 + uA));
                ldsm4(al[mt], st + G3_AL + soffG(row, ks * 2 + uA));
            }
#pragma unroll
            for (int nt = 0; nt < 2; nt++) {
                int row = wn * 32 + nt * 16 + rB;
                uint32_t t4[4];
                ldsm4(t4, st + G3_B + soffG(row, ks * 2 + uB));
#pragma unroll
                for (int half = 0; half < 2; half++) {
                    int nf = nt * 2 + half;
                    uint32_t b2[2] = {t4[half*2], t4[half*2+1]};
#pragma unroll
                    for (int mt = 0; mt < 4; mt++) {
                        mma_f16(acc[mt][nf], ah[mt], b2);
                        mma_f16(acc[mt][nf], al[mt], b2);
                    }
                }
            }
        }
        __syncthreads();
        if (it + 2 < nIter)
            g_load_stage(sb, it & 1, Ah, Al, Bw, m0, n0, (it + 2) * 64, K, tid);
    }

    int crow = lane >> 2, ccol = (lane & 3) * 2;
#pragma unroll
    for (int mt = 0; mt < 4; mt++) {
#pragma unroll
        for (int nf = 0; nf < 4; nf++) {
            int r = m0 + wm * 64 + mt * 16 + crow;
            int cidx = n0 + wn * 32 + nf * 8 + ccol;
            if (MODE == 2) {
                int jj = cidx >> 1;
                float ga = acc[mt][nf][0], up = acc[mt][nf][1];
                float v0 = ga / (1.f + __expf(-ga)) * up;
                float gb = acc[mt][nf][2], ub = acc[mt][nf][3];
                float v1 = gb / (1.f + __expf(-gb)) * ub;
                __half h0 = __float2half(v0);
                actH[(size_t)r * INTER + jj] = h0;
                actL[(size_t)r * INTER + jj] = __float2half(v0 - __half2float(h0));
                __half h1 = __float2half(v1);
                actH[(size_t)(r + 8) * INTER + jj] = h1;
                actL[(size_t)(r + 8) * INTER + jj] = __float2half(v1 - __half2float(h1));
            } else {
                float b0 = 0.f, b1 = 0.f;
                if (MODE == 1) {
                    b0 = (cidx < 2048) ? bq[cidx] : ((cidx < 3072) ? bk[cidx - 2048] : bv[cidx - 3072]);
                    int c1 = cidx + 1;
                    b1 = (c1 < 2048) ? bq[c1] : ((c1 < 3072) ? bk[c1 - 2048] : bv[c1 - 3072]);
                }
                *(float2*)(C + (size_t)r * N + cidx) =
                    make_float2(acc[mt][nf][0] + b0, acc[mt][nf][1] + b1);
                *(float2*)(C + (size_t)(r + 8) * N + cidx) =
                    make_float2(acc[mt][nf][2] + b0, acc[mt][nf][3] + b1);
            }
        }
    }
}

// ======================= RoPE + split of Q,K (bf16, for flash) =======================
__global__ void qkconv_kernel(const float* __restrict__ qkv, const int* __restrict__ pos,
    __nv_bfloat16* __restrict__ Qh, __nv_bfloat16* __restrict__ Ql,
    __nv_bfloat16* __restrict__ Kh, __nv_bfloat16* __restrict__ Kl)
{
    int idx = blockIdx.x * blockDim.x + threadIdx.x;
    int i = idx & 63;
    int rest = idx >> 6;
    int head = rest % 24;
    int t = rest / 24;
    if (t >= TT) return;
    const float* p = qkv + (size_t)t * 4096 + ((head < 16) ? head * 128 : 2048 + (head - 16) * 128);
    float ang = (float)pos[t] * g_invf[i];
    float sv, cv;
    sincosf(ang, &sv, &cv);
    float x1 = p[i], x2 = p[i + 64];
    float o1 = x1 * cv - x2 * sv;
    float o2 = x2 * cv + x1 * sv;
    __nv_bfloat16 *dh, *dl;
    size_t dst;
    if (head < 16) { dst = (size_t)t * 2048 + head * 128;        dh = Qh; dl = Ql; }
    else           { dst = (size_t)t * 1024 + (head - 16) * 128; dh = Kh; dl = Kl; }
    __nv_bfloat16 h1 = __float2bfloat16(o1);
    dh[dst + i] = h1;
    dl[dst + i] = __float2bfloat16(o1 - __bfloat162float(h1));
    __nv_bfloat16 h2 = __float2bfloat16(o2);
    dh[dst + i + 64] = h2;
    dl[dst + i + 64] = __float2bfloat16(o2 - __bfloat162float(h2));
}

// ======================= V transpose + split =======================
__global__ void vconv_kernel(const float* __restrict__ qkv,
    __nv_bfloat16* __restrict__ Vh, __nv_bfloat16* __restrict__ Vl)
{
    __shared__ float tile[32][33];
    int bhk = blockIdx.z;
    int b = bhk >> 3, hk = bhk & 7;
    int s0 = blockIdx.x * 32, d0 = blockIdx.y * 32;
    int tx = threadIdx.x, ty = threadIdx.y;
#pragma unroll
    for (int j = 0; j < 4; j++)
        tile[ty + 8*j][tx] = qkv[(size_t)(b * SS + s0 + ty + 8*j) * 4096 + 3072 + hk * 128 + d0 + tx];
    __syncthreads();
#pragma unroll
    for (int j = 0; j < 4; j++) {
        int d = d0 + ty + 8*j;
        float v = tile[tx][ty + 8*j];
        __nv_bfloat16 h = __float2bfloat16(v);
        size_t o = ((size_t)(b * NKV + hk) * HD + d) * SS + s0 + tx;
        Vh[o] = h;
        Vl[o] = __float2bfloat16(v - __bfloat162float(h));
    }
}

// ======================= tensor-core causal flash attention (bf16 3-term) =======================
#define FQ_H 0
#define FQ_L 32768
#define FST(s) (65536 + (s)*65536)
#define FK_H 0
#define FK_L 16384
#define FV_H 32768
#define FV_L 49152
#define FLASH_SMEM (65536 + 2*65536)

__global__ __launch_bounds__(256, 1) void flash_mma(
    const __nv_bfloat16* __restrict__ Qh, const __nv_bfloat16* __restrict__ Ql,
    const __nv_bfloat16* __restrict__ Kh, const __nv_bfloat16* __restrict__ Kl,
    const __nv_bfloat16* __restrict__ Vh, const __nv_bfloat16* __restrict__ Vl,
    __half* __restrict__ Oh, __half* __restrict__ Ol)
{
    extern __shared__ char smc[];
    uint32_t sb = s2u(smc);
    int tid = threadIdx.x, lane = tid & 31, wid = tid >> 5;
    int qt = (gridDim.x - 1) - blockIdx.x;
    int h = blockIdx.y, b = blockIdx.z;
    int hk = h >> 1;
    int q0 = qt * 128;
    int rA = lane & 15, uA = lane >> 4;
    int rB = (lane & 7) | ((lane & 16) >> 1), uB = (lane >> 3) & 1;

#pragma unroll
    for (int j = 0; j < 16; j++) {
        int idx = j * 256 + tid;
        int arr = idx >> 11, rem = idx & 2047;
        int r = rem >> 4, u = rem & 15;
        const __nv_bfloat16* src = (arr ? Ql : Qh) + (size_t)(b * SS + q0 + r) * 2048 + h * 128 + u * 8;
        cpasync16(sb + (arr ? FQ_L : FQ_H) + soff256(r, u), src);
    }

    auto load_kv = [&](int buf, int kbase) {
        uint32_t st = sb + FST(buf);
#pragma unroll
        for (int j = 0; j < 8; j++) {
            int idx = j * 256 + tid;
            int arr = idx >> 10, rem = idx & 1023;
            int r = rem >> 4, u = rem & 15;
            const __nv_bfloat16* src = (arr ? Kl : Kh) + (size_t)(b * SS + kbase + r) * 1024 + hk * 128 + u * 8;
            cpasync16(st + (arr ? FK_L : FK_H) + soff256(r, u), src);
        }
#pragma unroll
        for (int j = 0; j < 8; j++) {
            int idx = j * 256 + tid;
            int arr = idx >> 10, rem = idx & 1023;
            int r = rem >> 3, u = rem & 7;
            const __nv_bfloat16* src = (arr ? Vl : Vh) + ((size_t)(b * NKV + hk) * HD + r) * SS + kbase + u * 8;
            cpasync16(st + (arr ? FV_L : FV_H) + soffG(r, u), src);
        }
        cp_commit();
    };
    load_kv(0, 0);

    float m0v = -1e30f, m1v = -1e30f, l0v = 0.f, l1v = 0.f;
    float accO[16][4];
#pragma unroll
    for (int i = 0; i < 16; i++)
#pragma unroll
        for (int c = 0; c < 4; c++) accO[i][c] = 0.f;

    const float sc = 0.08838834764831845f;
    int ktmax = 2 * qt + 1;
    int row0 = q0 + wid * 16 + (lane >> 2);

    for (int kt = 0; kt <= ktmax; kt++) {
        cp_wait<0>();
        __syncthreads();
        if (kt < ktmax) load_kv((kt + 1) & 1, (kt + 1) * 64);
        uint32_t st = sb + FST(kt & 1);

        float accS[8][4];
#pragma unroll
        for (int i = 0; i < 8; i++)
#pragma unroll
            for (int c = 0; c < 4; c++) accS[i][c] = 0.f;

#pragma unroll
        for (int j = 0; j < 8; j++) {
            uint32_t ahf[4], alf[4];
            uint32_t qoff = soff256(wid * 16 + rA, 2 * j + uA);
            ldsm4(ahf, sb + FQ_H + qoff);
            ldsm4(alf, sb + FQ_L + qoff);
            uint32_t bhf[8][2], blf[8][2];
#pragma unroll
            for (int nt = 0; nt < 4; nt++) {
                uint32_t koff = soff256(nt * 16 + rB, 2 * j + uB);
                uint32_t t4[4];
                ldsm4(t4, st + FK_H + koff);
                bhf[2*nt][0] = t4[0]; bhf[2*nt][1] = t4[1];
                bhf[2*nt+1][0] = t4[2]; bhf[2*nt+1][1] = t4[3];
                ldsm4(t4, st + FK_L + koff);
                blf[2*nt][0] = t4[0]; blf[2*nt][1] = t4[1];
                blf[2*nt+1][0] = t4[2]; blf[2*nt+1][1] = t4[3];
            }
#pragma unroll
            for (int nf = 0; nf < 8; nf++) {
                mma_bf16(accS[nf], ahf, bhf[nf]);
                mma_bf16(accS[nf], ahf, blf[nf]);
                mma_bf16(accS[nf], alf, bhf[nf]);
            }
        }

        int kbase = kt * 64;
        bool needmask = (kbase + 63) > row0;
#pragma unroll
        for (int nf = 0; nf < 8; nf++) {
#pragma unroll
            for (int e = 0; e < 4; e++) {
                float s = accS[nf][e] * sc;
                if (needmask) {
                    int cc = kbase + nf * 8 + (lane & 3) * 2 + (e & 1);
                    int rr = row0 + ((e >> 1) << 3);
                    if (cc > rr) s = -1e30f;
                }
                accS[nf][e] = s;
            }
        }
        float vm0 = -1e30f, vm1 = -1e30f;
#pragma unroll
        for (int nf = 0; nf < 8; nf++) {
            vm0 = fmaxf(vm0, fmaxf(accS[nf][0], accS[nf][1]));
            vm1 = fmaxf(vm1, fmaxf(accS[nf][2], accS[nf][3]));
        }
        vm0 = fmaxf(vm0, __shfl_xor_sync(0xffffffffu, vm0, 1));
        vm0 = fmaxf(vm0, __shfl_xor_sync(0xffffffffu, vm0, 2));
        vm1 = fmaxf(vm1, __shfl_xor_sync(0xffffffffu, vm1, 1));
        vm1 = fmaxf(vm1, __shfl_xor_sync(0xffffffffu, vm1, 2));
        float mn0 = fmaxf(m0v, vm0), mn1 = fmaxf(m1v, vm1);
        float c0 = __expf(m0v - mn0), c1 = __expf(m1v - mn1);
        float s0 = 0.f, s1 = 0.f;
#pragma unroll
        for (int nf = 0; nf < 8; nf++) {
            accS[nf][0] = __expf(accS[nf][0] - mn0); s0 += accS[nf][0];
            accS[nf][1] = __expf(accS[nf][1] - mn0); s0 += accS[nf][1];
            accS[nf][2] = __expf(accS[nf][2] - mn1); s1 += accS[nf][2];
            accS[nf][3] = __expf(accS[nf][3] - mn1); s1 += accS[nf][3];
        }
        s0 += __shfl_xor_sync(0xffffffffu, s0, 1);
        s0 += __shfl_xor_sync(0xffffffffu, s0, 2);
        s1 += __shfl_xor_sync(0xffffffffu, s1, 1);
        s1 += __shfl_xor_sync(0xffffffffu, s1, 2);
        l0v = l0v * c0 + s0; l1v = l1v * c1 + s1;
        m0v = mn0; m1v = mn1;
#pragma unroll
        for (int i = 0; i < 16; i++) {
            accO[i][0] *= c0; accO[i][1] *= c0;
            accO[i][2] *= c1; accO[i][3] *= c1;
        }

#pragma unroll
        for (int j2 = 0; j2 < 4; j2++) {
            uint32_t pah[4], pal[4];
            split_pack(pah[0], pal[0], accS[2*j2][0],   accS[2*j2][1]);
            split_pack(pah[1], pal[1], accS[2*j2][2],   accS[2*j2][3]);
            split_pack(pah[2], pal[2], accS[2*j2+1][0], accS[2*j2+1][1]);
            split_pack(pah[3], pal[3], accS[2*j2+1][2], accS[2*j2+1][3]);
#pragma unroll
            for (int nt = 0; nt < 8; nt++) {
                uint32_t voff = soffG(nt * 16 + rB, 2 * j2 + uB);
                uint32_t t4[4], vh0[2], vh1[2], vl0[2], vl1[2];
                ldsm4(t4, st + FV_H + voff);
                vh0[0] = t4[0]; vh0[1] = t4[1]; vh1[0] = t4[2]; vh1[1] = t4[3];
                ldsm4(t4, st + FV_L + voff);
                vl0[0] = t4[0]; vl0[1] = t4[1]; vl1[0] = t4[2]; vl1[1] = t4[3];
                mma_bf16(accO[2*nt],   pah, vh0);
                mma_bf16(accO[2*nt],   pah, vl0);
                mma_bf16(accO[2*nt],   pal, vh0);
                mma_bf16(accO[2*nt+1], pah, vh1);
                mma_bf16(accO[2*nt+1], pah, vl1);
                mma_bf16(accO[2*nt+1], pal, vh1);
            }
        }
    }

    float inv0 = 1.0f / l0v, inv1 = 1.0f / l1v;
#pragma unroll
    for (int nf = 0; nf < 16; nf++) {
        int d = nf * 8 + (lane & 3) * 2;
        size_t o0 = (size_t)(b * SS + row0) * 2048 + h * 128 + d;
        size_t o1 = o0 + (size_t)8 * 2048;
        __half2 hh, ll;
        split_store2h(accO[nf][0] * inv0, accO[nf][1] * inv0, &hh, &ll);
        *(__half2*)(Oh + o0) = hh;
        *(__half2*)(Ol + o0) = ll;
        split_store2h(accO[nf][2] * inv1, accO[nf][3] * inv1, &hh, &ll);
        *(__half2*)(Oh + o1) = hh;
        *(__half2*)(Ol + o1) = ll;
    }
}

// ======================= launch =======================
extern "C" void kernel_launch(void* const* d_in, const int* in_sizes, int n_in,
                              void* d_out, int out_size)
{
    const int*   positions = (const int*)  d_in[0];
    const float* hidden    = (const float*)d_in[1];
    const float* residual  = (const float*)d_in[2];
    const float* ln1       = (const float*)d_in[3];
    const float* ln2       = (const float*)d_in[4];
    const float* wq        = (const float*)d_in[5];
    const float* bq        = (const float*)d_in[6];
    const float* wk        = (const float*)d_in[7];
    const float* bk        = (const float*)d_in[8];
    const float* wv        = (const float*)d_in[9];
    const float* bv        = (const float*)d_in[10];
    const float* wo        = (const float*)d_in[11];
    const float* wgu       = (const float*)d_in[12];
    const float* wd        = (const float*)d_in[13];

    float* out_h   = (float*)d_out;
    float* out_res = out_h + (size_t)out_size / 2;

    float *res1, *qkv, *hattn;
    __half *xn_h, *xn_l, *at_h, *at_l, *h2_h, *h2_l, *ac_h, *ac_l;
    __nv_bfloat16 *Qh, *Ql, *Kh, *Kl, *Vh, *Vl;
    __half *qkvT, *woT, *guT, *wdT;
    cudaGetSymbolAddress((void**)&res1,  g_res1);
    cudaGetSymbolAddress((void**)&qkv,   g_qkv);
    cudaGetSymbolAddress((void**)&hattn, g_hattn);
    cudaGetSymbolAddress((void**)&xn_h,  g_xn_h);
    cudaGetSymbolAddress((void**)&xn_l,  g_xn_l);
    cudaGetSymbolAddress((void**)&at_h,  g_at_h);
    cudaGetSymbolAddress((void**)&at_l,  g_at_l);
    cudaGetSymbolAddress((void**)&h2_h,  g_h2_h);
    cudaGetSymbolAddress((void**)&h2_l,  g_h2_l);
    cudaGetSymbolAddress((void**)&ac_h,  g_ac_h);
    cudaGetSymbolAddress((void**)&ac_l,  g_ac_l);
    cudaGetSymbolAddress((void**)&Qh,    g_Qh);
    cudaGetSymbolAddress((void**)&Ql,    g_Ql);
    cudaGetSymbolAddress((void**)&Kh,    g_Kh);
    cudaGetSymbolAddress((void**)&Kl,    g_Kl);
    cudaGetSymbolAddress((void**)&Vh,    g_Vh);
    cudaGetSymbolAddress((void**)&Vl,    g_Vl);
    cudaGetSymbolAddress((void**)&qkvT,  g_qkvT);
    cudaGetSymbolAddress((void**)&woT,   g_woT);
    cudaGetSymbolAddress((void**)&guT,   g_guT);
    cudaGetSymbolAddress((void**)&wdT,   g_wdT);

    cudaFuncSetAttribute(gemm_mma<0>, cudaFuncAttributeMaxDynamicSharedMemorySize, GEMM_SMEM);
    cudaFuncSetAttribute(gemm_mma<1>, cudaFuncAttributeMaxDynamicSharedMemorySize, GEMM_SMEM);
    cudaFuncSetAttribute(gemm_mma<2>, cudaFuncAttributeMaxDynamicSharedMemorySize, GEMM_SMEM);
    cudaFuncSetAttribute(flash_mma, cudaFuncAttributeMaxDynamicSharedMemorySize, FLASH_SMEM);

    // 0. weight preprocessing (single fp16)
    wsplit_qkv_kernel<<<dim3(128, 64), dim3(32,8)>>>(wq, wk, wv, qkvT);
    wsplit_kernel<<<dim3(64, 64), dim3(32,8)>>>(wo, woT, NHQ*HD, HH);
    wsplit_gu_kernel<<<dim3(512, 64), dim3(32,8)>>>(wgu, guT);
    wsplit_kernel<<<dim3(64, 256), dim3(32,8)>>>(wd, wdT, INTER, HH);

    // 1. res1 + rmsnorm -> fp16 split
    add_rmsnorm_kernel<<<TT, 256>>>(hidden, residual, ln1, res1, xn_h, xn_l);

    // 2. fused QKV projection
    gemm_mma<1><<<dim3(32, 32), 256, GEMM_SMEM>>>(xn_h, xn_l, qkvT,
        bq, bk, bv, qkv, nullptr, nullptr, TT, 4096, HH);

    // 3. RoPE + split of Q,K ; V transpose + split (bf16 for flash)
    qkconv_kernel<<<(TT * 24 * 64) / 256, 256>>>(qkv, positions, Qh, Ql, Kh, Kl);
    vconv_kernel<<<dim3(SS/32, HD/32, BB*NKV), dim3(32,8)>>>(qkv, Vh, Vl);

    // 4. flash attention -> fp16 split at_h/at_l
    flash_mma<<<dim3(SS/128, NHQ, BB), 256, FLASH_SMEM>>>(Qh, Ql, Kh, Kl, Vh, Vl, at_h, at_l);

    // 5. output projection
    gemm_mma<0><<<dim3(16, 32), 256, GEMM_SMEM>>>(at_h, at_l, woT,
        nullptr, nullptr, nullptr, hattn, nullptr, nullptr, TT, HH, NHQ*HD);

    // 6. res2 + rmsnorm -> fp16 split
    add_rmsnorm_kernel<<<TT, 256>>>(hattn, res1, ln2, out_res, h2_h, h2_l);

    // 7. gate_up GEMM + fused SwiGLU -> fp16 split act
    gemm_mma<2><<<dim3(128, 32), 256, GEMM_SMEM>>>(h2_h, h2_l, guT,
        nullptr, nullptr, nullptr, nullptr, ac_h, ac_l, TT, 16384, HH);

    // 8. down GEMM -> out first half
    gemm_mma<0><<<dim3(16, 32), 256, GEMM_SMEM>>>(ac_h, ac_l, wdT,
        nullptr, nullptr, nullptr, out_h, nullptr, nullptr, TT, HH, INTER);
}

// round 13
// speedup vs baseline: 2.6620x; 1.0273x over previous
#include <cuda_runtime.h>
#include <cuda_bf16.h>
#include <cuda_fp16.h>
#include <cstdint>
#include <math.h>

#define BB 2
#define SS 2048
#define TT (BB*SS)
#define HH 2048
#define NHQ 16
#define NKV 8
#define HD 128
#define INTER 8192
#define EPS 1e-6f

// ======================= scratch =======================
__device__ __align__(256) float g_res1 [(size_t)TT*HH];
__device__ __align__(256) float g_qkv  [(size_t)TT*4096];
__device__ __align__(256) float g_hattn[(size_t)TT*HH];
__device__ float g_invf [64];

// fp16 split activations (A operands)
__device__ __align__(256) __half g_xn_h [(size_t)TT*HH];
__device__ __align__(256) __half g_xn_l [(size_t)TT*HH];
__device__ __align__(256) __half g_at_h [(size_t)TT*HH];
__device__ __align__(256) __half g_at_l [(size_t)TT*HH];
__device__ __align__(256) __half g_h2_h [(size_t)TT*HH];
__device__ __align__(256) __half g_h2_l [(size_t)TT*HH];
__device__ __align__(256) __half g_ac_h [(size_t)TT*INTER];
__device__ __align__(256) __half g_ac_l [(size_t)TT*INTER];

// flash operands: Q/K bf16 split (3-term QK), V single fp16 (2-term PV)
__device__ __align__(256) __nv_bfloat16 g_Qh [(size_t)TT*2048];
__device__ __align__(256) __nv_bfloat16 g_Ql [(size_t)TT*2048];
__device__ __align__(256) __nv_bfloat16 g_Kh [(size_t)TT*1024];
__device__ __align__(256) __nv_bfloat16 g_Kl [(size_t)TT*1024];
__device__ __align__(256) __half        g_Vh [(size_t)TT*1024];  // [b][hk][d][s]

// single-fp16 transposed weights [N, K]
__device__ __align__(256) __half g_qkvT[(size_t)4096*HH];
__device__ __align__(256) __half g_woT [(size_t)HH*(NHQ*HD)];
__device__ __align__(256) __half g_guT [(size_t)(2*INTER)*HH];   // interleaved gate/up
__device__ __align__(256) __half g_wdT [(size_t)HH*INTER];

// ======================= PTX helpers =======================
__device__ __forceinline__ uint32_t s2u(const void* p) {
    uint32_t a;
    asm("{ .reg .u64 t; cvta.to.shared.u64 t, %1; cvt.u32.u64 %0, t; }" : "=r"(a) : "l"(p));
    return a;
}
__device__ __forceinline__ void cpasync16(uint32_t dst, const void* src) {
    asm volatile("cp.async.cg.shared.global [%0], [%1], 16;" :: "r"(dst), "l"(src) : "memory");
}
__device__ __forceinline__ void cp_commit() { asm volatile("cp.async.commit_group;" ::: "memory"); }
template<int N_>
__device__ __forceinline__ void cp_wait() { asm volatile("cp.async.wait_group %0;" :: "n"(N_) : "memory"); }
__device__ __forceinline__ void ldsm4(uint32_t* r, uint32_t addr) {
    asm volatile("ldmatrix.sync.aligned.m8n8.x4.shared.b16 {%0,%1,%2,%3}, [%4];"
                 : "=r"(r[0]), "=r"(r[1]), "=r"(r[2]), "=r"(r[3]) : "r"(addr));
}
__device__ __forceinline__ void mma_bf16(float* d, const uint32_t* a, const uint32_t* b) {
    asm volatile(
        "mma.sync.aligned.m16n8k16.row.col.f32.bf16.bf16.f32 "
        "{%0,%1,%2,%3}, {%4,%5,%6,%7}, {%8,%9}, {%0,%1,%2,%3};"
        : "+f"(d[0]), "+f"(d[1]), "+f"(d[2]), "+f"(d[3])
        : "r"(a[0]), "r"(a[1]), "r"(a[2]), "r"(a[3]), "r"(b[0]), "r"(b[1]));
}
__device__ __forceinline__ void mma_f16(float* d, const uint32_t* a, const uint32_t* b) {
    asm volatile(
        "mma.sync.aligned.m16n8k16.row.col.f32.f16.f16.f32 "
        "{%0,%1,%2,%3}, {%4,%5,%6,%7}, {%8,%9}, {%0,%1,%2,%3};"
        : "+f"(d[0]), "+f"(d[1]), "+f"(d[2]), "+f"(d[3])
        : "r"(a[0]), "r"(a[1]), "r"(a[2]), "r"(a[3]), "r"(b[0]), "r"(b[1]));
}
// bf16 split (flash Q/K)
__device__ __forceinline__ void split_store2(float x, float y, __nv_bfloat162* ph, __nv_bfloat162* pl)
{
    __nv_bfloat16 hx = __float2bfloat16(x), hy = __float2bfloat16(y);
    *ph = __halves2bfloat162(hx, hy);
    *pl = __halves2bfloat162(__float2bfloat16(x - __bfloat162float(hx)),
                             __float2bfloat16(y - __bfloat162float(hy)));
}
// fp16 split
__device__ __forceinline__ void split_store2h(float x, float y, __half2* ph, __half2* pl)
{
    __half hx = __float2half(x), hy = __float2half(y);
    *ph = __halves2half2(hx, hy);
    *pl = __halves2half2(__float2half(x - __half2float(hx)),
                         __float2half(y - __half2float(hy)));
}
__device__ __forceinline__ void split_pack_h(uint32_t& ph, uint32_t& pl, float x, float y)
{
    __half2 h2, l2;
    split_store2h(x, y, &h2, &l2);
    ph = *(uint32_t*)&h2; pl = *(uint32_t*)&l2;
}
__device__ __forceinline__ uint32_t soffG(int r, int u)   { return (uint32_t)(r*128 + ((u ^ (r & 7)) << 4)); }
__device__ __forceinline__ uint32_t soff256(int r, int u) { return (uint32_t)(r*256 + ((u ^ (r & 7)) << 4)); }

// ======================= fused add + RMSNorm (fp16-split out) =======================
__global__ void add_rmsnorm_kernel(const float* __restrict__ a, const float* __restrict__ b,
                                   const float* __restrict__ w, float* __restrict__ res,
                                   __half* __restrict__ oh, __half* __restrict__ ol)
{
    int t = blockIdx.x, tid = threadIdx.x;
    const float4* a4 = (const float4*)(a + (size_t)t * HH);
    const float4* b4 = (const float4*)(b + (size_t)t * HH);
    float4* r4 = (float4*)(res + (size_t)t * HH);
    const float4* w4 = (const float4*)w;
    __half2* oh2 = (__half2*)(oh + (size_t)t * HH);
    __half2* ol2 = (__half2*)(ol + (size_t)t * HH);

    float4 vv[2];
    float ss = 0.f;
#pragma unroll
    for (int ii = 0; ii < 2; ii++) {
        int idx = tid + ii * 256;
        float4 x = a4[idx], y = b4[idx];
        x.x += y.x; x.y += y.y; x.z += y.z; x.w += y.w;
        r4[idx] = x; vv[ii] = x;
        ss += x.x*x.x + x.y*x.y + x.z*x.z + x.w*x.w;
    }
#pragma unroll
    for (int off = 16; off; off >>= 1) ss += __shfl_xor_sync(0xffffffffu, ss, off);
    __shared__ float sh[8];
    __shared__ float s_inv;
    if ((tid & 31) == 0) sh[tid >> 5] = ss;
    __syncthreads();
    if (tid == 0) {
        float s = 0.f;
#pragma unroll
        for (int i = 0; i < 8; i++) s += sh[i];
        s_inv = rsqrtf(s / (float)HH + EPS);
    }
    __syncthreads();
    float inv = s_inv;
#pragma unroll
    for (int ii = 0; ii < 2; ii++) {
        int idx = tid + ii * 256;
        float4 x = vv[ii], ww = w4[idx];
        __half2 h0, l0, h1, l1;
        split_store2h(x.x*inv*ww.x, x.y*inv*ww.y, &h0, &l0);
        split_store2h(x.z*inv*ww.z, x.w*inv*ww.w, &h1, &l1);
        oh2[idx*2] = h0; oh2[idx*2+1] = h1;
        ol2[idx*2] = l0; ol2[idx*2+1] = l1;
    }
}

// ======================= weight split kernels (single fp16) =======================
__global__ void wsplit_kernel(const float* __restrict__ W, __half* __restrict__ Tw, int K, int N)
{
    __shared__ float tile[32][33];
    int k0 = blockIdx.y * 32, n0 = blockIdx.x * 32;
    int tx = threadIdx.x, ty = threadIdx.y;
#pragma unroll
    for (int j = 0; j < 4; j++)
        tile[ty + 8*j][tx] = W[(size_t)(k0 + ty + 8*j) * N + n0 + tx];
    __syncthreads();
#pragma unroll
    for (int j = 0; j < 4; j++) {
        int n = ty + 8*j;
        Tw[(size_t)(n0 + n) * K + k0 + tx] = __float2half(tile[tx][n]);
    }
}

__global__ void wsplit_qkv_kernel(const float* __restrict__ wq, const float* __restrict__ wk,
                                  const float* __restrict__ wv, __half* __restrict__ Tw)
{
    __shared__ float tile[32][33];
    int n0 = blockIdx.x * 32, k0 = blockIdx.y * 32;
    int tx = threadIdx.x, ty = threadIdx.y;
    if (blockIdx.x == 0 && blockIdx.y == 0) {
        int id = ty * 32 + tx;
        if (id < 64) g_invf[id] = (float)pow(1.0e6, -(double)id / 64.0);
    }
    int n = n0 + tx;
    const float* src; int nc, stride;
    if (n < 2048)      { src = wq; nc = n;        stride = 2048; }
    else if (n < 3072) { src = wk; nc = n - 2048; stride = 1024; }
    else               { src = wv; nc = n - 3072; stride = 1024; }
#pragma unroll
    for (int j = 0; j < 4; j++)
        tile[ty + 8*j][tx] = src[(size_t)(k0 + ty + 8*j) * stride + nc];
    __syncthreads();
#pragma unroll
    for (int j = 0; j < 4; j++) {
        int nn = n0 + ty + 8*j;
        Tw[(size_t)nn * HH + k0 + tx] = __float2half(tile[tx][ty + 8*j]);
    }
}

__global__ void wsplit_gu_kernel(const float* __restrict__ W, __half* __restrict__ Tw)
{
    __shared__ float tile[32][33];
    int n0 = blockIdx.x * 32, k0 = blockIdx.y * 32;
    int tx = threadIdx.x, ty = threadIdx.y;
    int n = n0 + tx;
    int srccol = (n & 1) ? (8192 + (n >> 1)) : (n >> 1);
#pragma unroll
    for (int j = 0; j < 4; j++)
        tile[ty + 8*j][tx] = W[(size_t)(k0 + ty + 8*j) * 16384 + srccol];
    __syncthreads();
#pragma unroll
    for (int j = 0; j < 4; j++) {
        int nn = n0 + ty + 8*j;
        Tw[(size_t)nn * HH + k0 + tx] = __float2half(tile[tx][ty + 8*j]);
    }
}

// ======================= fp16 2-term GEMM (BK=64, 2-stage, occ 2, 4Mx2N warps) =======================
// stage: A-hi [128r x 128B] | A-lo | B  = 48KB
#define G3_AL 16384
#define G3_B  32768
#define G3_STAGE 49152
#define GEMM_SMEM (2*G3_STAGE)

__device__ __forceinline__ void g_load_stage(uint32_t sb, int s,
    const __half* __restrict__ Ah, const __half* __restrict__ Al, const __half* __restrict__ Bw,
    int m0, int n0, int k0, int K, int tid)
{
    uint32_t st = sb + s * G3_STAGE;
#pragma unroll
    for (int j = 0; j < 12; j++) {
        int idx = j * 256 + tid;
        int seg = idx >> 10;
        int rem = idx & 1023;
        int r = rem >> 3, u = rem & 7;
        const __half* src;
        if (seg == 0)      src = Ah + (size_t)(m0 + r) * K;
        else if (seg == 1) src = Al + (size_t)(m0 + r) * K;
        else               src = Bw + (size_t)(n0 + r) * K;
        src += k0 + u * 8;
        cpasync16(st + seg * 16384 + soffG(r, u), src);
    }
    cp_commit();
}

// MODE 0: f32 out. MODE 1: qkv bias. MODE 2: fused SwiGLU -> fp16 split.
template<int MODE>
__global__ __launch_bounds__(256, 2) void gemm_mma(
    const __half* __restrict__ Ah, const __half* __restrict__ Al, const __half* __restrict__ Bw,
    const float* __restrict__ bq, const float* __restrict__ bk, const float* __restrict__ bv,
    float* __restrict__ C, __half* __restrict__ actH, __half* __restrict__ actL,
    int M, int N, int K)
{
    extern __shared__ char smc[];
    uint32_t sb = s2u(smc);
    int tid = threadIdx.x, lane = tid & 31, wid = tid >> 5;
    int wm = wid & 3, wn = wid >> 2;          // 4 M-strips x 2 N-halves
    int m0 = blockIdx.y * 128, n0 = blockIdx.x * 128;

    float acc[2][8][4];
#pragma unroll
    for (int i = 0; i < 2; i++)
#pragma unroll
        for (int j = 0; j < 8; j++)
#pragma unroll
            for (int c = 0; c < 4; c++) acc[i][j][c] = 0.f;

    int rA = lane & 15, uA = lane >> 4;
    int rB = (lane & 7) | ((lane & 16) >> 1), uB = (lane >> 3) & 1;

    int nIter = K / 64;
    g_load_stage(sb, 0, Ah, Al, Bw, m0, n0, 0, K, tid);
    g_load_stage(sb, 1, Ah, Al, Bw, m0, n0, 64, K, tid);

    for (int it = 0; it < nIter; it++) {
        if (it + 1 < nIter) cp_wait<1>(); else cp_wait<0>();
        __syncthreads();

        uint32_t st = sb + (it & 1) * G3_STAGE;
#pragma unroll
        for (int ks = 0; ks < 4; ks++) {
            uint32_t ah[2][4], al[2][4];
#pragma unroll
            for (int mt = 0; mt < 2; mt++) {
                int row = wm * 32 + mt * 16 + rA;
                ldsm4(ah[mt], st + soffG(row, ks * 2 + uA));
                ldsm4(al[mt], st + G3_AL + soffG(row, ks * 2 + uA));
            }
#pragma unroll
            for (int nt = 0; nt < 4; nt++) {
                int row = wn * 64 + nt * 16 + rB;
                uint32_t t4[4];
                ldsm4(t4, st + G3_B + soffG(row, ks * 2 + uB));
#pragma unroll
                for (int half = 0; half < 2; half++) {
                    int nf = nt * 2 + half;
                    uint32_t b2[2] = {t4[half*2], t4[half*2+1]};
#pragma unroll
                    for (int mt = 0; mt < 2; mt++) {
                        mma_f16(acc[mt][nf], ah[mt], b2);
                        mma_f16(acc[mt][nf], al[mt], b2);
                    }
                }
            }
        }
        __syncthreads();
        if (it + 2 < nIter)
            g_load_stage(sb, it & 1, Ah, Al, Bw, m0, n0, (it + 2) * 64, K, tid);
    }

    int crow = lane >> 2, ccol = (lane & 3) * 2;
#pragma unroll
    for (int mt = 0; mt < 2; mt++) {
#pragma unroll
        for (int nf = 0; nf < 8; nf++) {
            int r = m0 + wm * 32 + mt * 16 + crow;
            int cidx = n0 + wn * 64 + nf * 8 + ccol;
            if (MODE == 2) {
                int jj = cidx >> 1;
                float ga = acc[mt][nf][0], up = acc[mt][nf][1];
                float v0 = ga / (1.f + __expf(-ga)) * up;
                float gb = acc[mt][nf][2], ub = acc[mt][nf][3];
                float v1 = gb / (1.f + __expf(-gb)) * ub;
                __half h0 = __float2half(v0);
                actH[(size_t)r * INTER + jj] = h0;
                actL[(size_t)r * INTER + jj] = __float2half(v0 - __half2float(h0));
                __half h1 = __float2half(v1);
                actH[(size_t)(r + 8) * INTER + jj] = h1;
                actL[(size_t)(r + 8) * INTER + jj] = __float2half(v1 - __half2float(h1));
            } else {
                float b0 = 0.f, b1 = 0.f;
                if (MODE == 1) {
                    b0 = (cidx < 2048) ? bq[cidx] : ((cidx < 3072) ? bk[cidx - 2048] : bv[cidx - 3072]);
                    int c1 = cidx + 1;
                    b1 = (c1 < 2048) ? bq[c1] : ((c1 < 3072) ? bk[c1 - 2048] : bv[c1 - 3072]);
                }
                *(float2*)(C + (size_t)r * N + cidx) =
                    make_float2(acc[mt][nf][0] + b0, acc[mt][nf][1] + b1);
                *(float2*)(C + (size_t)(r + 8) * N + cidx) =
                    make_float2(acc[mt][nf][2] + b0, acc[mt][nf][3] + b1);
            }
        }
    }
}

// ======================= RoPE + split of Q,K (bf16, for flash) =======================
__global__ void qkconv_kernel(const float* __restrict__ qkv, const int* __restrict__ pos,
    __nv_bfloat16* __restrict__ Qh, __nv_bfloat16* __restrict__ Ql,
    __nv_bfloat16* __restrict__ Kh, __nv_bfloat16* __restrict__ Kl)
{
    int idx = blockIdx.x * blockDim.x + threadIdx.x;
    int i = idx & 63;
    int rest = idx >> 6;
    int head = rest % 24;
    int t = rest / 24;
    if (t >= TT) return;
    const float* p = qkv + (size_t)t * 4096 + ((head < 16) ? head * 128 : 2048 + (head - 16) * 128);
    float ang = (float)pos[t] * g_invf[i];
    float sv, cv;
    sincosf(ang, &sv, &cv);
    float x1 = p[i], x2 = p[i + 64];
    float o1 = x1 * cv - x2 * sv;
    float o2 = x2 * cv + x1 * sv;
    __nv_bfloat16 *dh, *dl;
    size_t dst;
    if (head < 16) { dst = (size_t)t * 2048 + head * 128;        dh = Qh; dl = Ql; }
    else           { dst = (size_t)t * 1024 + (head - 16) * 128; dh = Kh; dl = Kl; }
    __nv_bfloat16 h1 = __float2bfloat16(o1);
    dh[dst + i] = h1;
    dl[dst + i] = __float2bfloat16(o1 - __bfloat162float(h1));
    __nv_bfloat16 h2 = __float2bfloat16(o2);
    dh[dst + i + 64] = h2;
    dl[dst + i + 64] = __float2bfloat16(o2 - __bfloat162float(h2));
}

// ======================= V transpose (single fp16) =======================
__global__ void vconv_kernel(const float* __restrict__ qkv, __half* __restrict__ Vh)
{
    __shared__ float tile[32][33];
    int bhk = blockIdx.z;
    int b = bhk >> 3, hk = bhk & 7;
    int s0 = blockIdx.x * 32, d0 = blockIdx.y * 32;
    int tx = threadIdx.x, ty = threadIdx.y;
#pragma unroll
    for (int j = 0; j < 4; j++)
        tile[ty + 8*j][tx] = qkv[(size_t)(b * SS + s0 + ty + 8*j) * 4096 + 3072 + hk * 128 + d0 + tx];
    __syncthreads();
#pragma unroll
    for (int j = 0; j < 4; j++) {
        int d = d0 + ty + 8*j;
        size_t o = ((size_t)(b * NKV + hk) * HD + d) * SS + s0 + tx;
        Vh[o] = __float2half(tile[tx][ty + 8*j]);
    }
}

// ======================= tensor-core causal flash attention =======================
// QK: bf16 3-term; PV: fp16 2-term (P split, V single fp16)
#define FQ_H 0
#define FQ_L 32768
#define FST(s) (65536 + (s)*49152)
#define FK_H 0
#define FK_L 16384
#define FV   32768
#define FLASH_SMEM (65536 + 2*49152)

__global__ __launch_bounds__(256, 1) void flash_mma(
    const __nv_bfloat16* __restrict__ Qh, const __nv_bfloat16* __restrict__ Ql,
    const __nv_bfloat16* __restrict__ Kh, const __nv_bfloat16* __restrict__ Kl,
    const __half* __restrict__ Vh,
    __half* __restrict__ Oh, __half* __restrict__ Ol)
{
    extern __shared__ char smc[];
    uint32_t sb = s2u(smc);
    int tid = threadIdx.x, lane = tid & 31, wid = tid >> 5;
    int qt = (gridDim.x - 1) - blockIdx.x;
    int h = blockIdx.y, b = blockIdx.z;
    int hk = h >> 1;
    int q0 = qt * 128;
    int rA = lane & 15, uA = lane >> 4;
    int rB = (lane & 7) | ((lane & 16) >> 1), uB = (lane >> 3) & 1;

#pragma unroll
    for (int j = 0; j < 16; j++) {
        int idx = j * 256 + tid;
        int arr = idx >> 11, rem = idx & 2047;
        int r = rem >> 4, u = rem & 15;
        const __nv_bfloat16* src = (arr ? Ql : Qh) + (size_t)(b * SS + q0 + r) * 2048 + h * 128 + u * 8;
        cpasync16(sb + (arr ? FQ_L : FQ_H) + soff256(r, u), src);
    }

    auto load_kv = [&](int buf, int kbase) {
        uint32_t st = sb + FST(buf);
#pragma unroll
        for (int j = 0; j < 8; j++) {
            int idx = j * 256 + tid;
            int arr = idx >> 10, rem = idx & 1023;
            int r = rem >> 4, u = rem & 15;
            const __nv_bfloat16* src = (arr ? Kl : Kh) + (size_t)(b * SS + kbase + r) * 1024 + hk * 128 + u * 8;
            cpasync16(st + (arr ? FK_L : FK_H) + soff256(r, u), src);
        }
#pragma unroll
        for (int j = 0; j < 4; j++) {
            int idx = j * 256 + tid;
            int r = idx >> 3, u = idx & 7;
            const __half* src = Vh + ((size_t)(b * NKV + hk) * HD + r) * SS + kbase + u * 8;
            cpasync16(st + FV + soffG(r, u), src);
        }
        cp_commit();
    };
    load_kv(0, 0);

    float m0v = -1e30f, m1v = -1e30f, l0v = 0.f, l1v = 0.f;
    float accO[16][4];
#pragma unroll
    for (int i = 0; i < 16; i++)
#pragma unroll
        for (int c = 0; c < 4; c++) accO[i][c] = 0.f;

    const float sc = 0.08838834764831845f;
    int ktmax = 2 * qt + 1;
    int row0 = q0 + wid * 16 + (lane >> 2);

    for (int kt = 0; kt <= ktmax; kt++) {
        cp_wait<0>();
        __syncthreads();
        if (kt < ktmax) load_kv((kt + 1) & 1, (kt + 1) * 64);
        uint32_t st = sb + FST(kt & 1);

        float accS[8][4];
#pragma unroll
        for (int i = 0; i < 8; i++)
#pragma unroll
            for (int c = 0; c < 4; c++) accS[i][c] = 0.f;

#pragma unroll
        for (int j = 0; j < 8; j++) {
            uint32_t ahf[4], alf[4];
            uint32_t qoff = soff256(wid * 16 + rA, 2 * j + uA);
            ldsm4(ahf, sb + FQ_H + qoff);
            ldsm4(alf, sb + FQ_L + qoff);
            uint32_t bhf[8][2], blf[8][2];
#pragma unroll
            for (int nt = 0; nt < 4; nt++) {
                uint32_t koff = soff256(nt * 16 + rB, 2 * j + uB);
                uint32_t t4[4];
                ldsm4(t4, st + FK_H + koff);
                bhf[2*nt][0] = t4[0]; bhf[2*nt][1] = t4[1];
                bhf[2*nt+1][0] = t4[2]; bhf[2*nt+1][1] = t4[3];
                ldsm4(t4, st + FK_L + koff);
                blf[2*nt][0] = t4[0]; blf[2*nt][1] = t4[1];
                blf[2*nt+1][0] = t4[2]; blf[2*nt+1][1] = t4[3];
            }
#pragma unroll
            for (int nf = 0; nf < 8; nf++) {
                mma_bf16(accS[nf], ahf, bhf[nf]);
                mma_bf16(accS[nf], ahf, blf[nf]);
                mma_bf16(accS[nf], alf, bhf[nf]);
            }
        }

        int kbase = kt * 64;
        bool needmask = (kbase + 63) > row0;
#pragma unroll
        for (int nf = 0; nf < 8; nf++) {
#pragma unroll
            for (int e = 0; e < 4; e++) {
                float s = accS[nf][e] * sc;
                if (needmask) {
                    int cc = kbase + nf * 8 + (lane & 3) * 2 + (e & 1);
                    int rr = row0 + ((e >> 1) << 3);
                    if (cc > rr) s = -1e30f;
                }
                accS[nf][e] = s;
            }
        }
        float vm0 = -1e30f, vm1 = -1e30f;
#pragma unroll
        for (int nf = 0; nf < 8; nf++) {
            vm0 = fmaxf(vm0, fmaxf(accS[nf][0], accS[nf][1]));
            vm1 = fmaxf(vm1, fmaxf(accS[nf][2], accS[nf][3]));
        }
        vm0 = fmaxf(vm0, __shfl_xor_sync(0xffffffffu, vm0, 1));
        vm0 = fmaxf(vm0, __shfl_xor_sync(0xffffffffu, vm0, 2));
        vm1 = fmaxf(vm1, __shfl_xor_sync(0xffffffffu, vm1, 1));
        vm1 = fmaxf(vm1, __shfl_xor_sync(0xffffffffu, vm1, 2));
        float mn0 = fmaxf(m0v, vm0), mn1 = fmaxf(m1v, vm1);
        float c0 = __expf(m0v - mn0), c1 = __expf(m1v - mn1);
        float s0 = 0.f, s1 = 0.f;
#pragma unroll
        for (int nf = 0; nf < 8; nf++) {
            accS[nf][0] = __expf(accS[nf][0] - mn0); s0 += accS[nf][0];
            accS[nf][1] = __expf(accS[nf][1] - mn0); s0 += accS[nf][1];
            accS[nf][2] = __expf(accS[nf][2] - mn1); s1 += accS[nf][2];
            accS[nf][3] = __expf(accS[nf][3] - mn1); s1 += accS[nf][3];
        }
        s0 += __shfl_xor_sync(0xffffffffu, s0, 1);
        s0 += __shfl_xor_sync(0xffffffffu, s0, 2);
        s1 += __shfl_xor_sync(0xffffffffu, s1, 1);
        s1 += __shfl_xor_sync(0xffffffffu, s1, 2);
        l0v = l0v * c0 + s0; l1v = l1v * c1 + s1;
        m0v = mn0; m1v = mn1;
#pragma unroll
        for (int i = 0; i < 16; i++) {
            accO[i][0] *= c0; accO[i][1] *= c0;
            accO[i][2] *= c1; accO[i][3] *= c1;
        }

        // O += P V  (P split fp16, V single fp16)
#pragma unroll
        for (int j2 = 0; j2 < 4; j2++) {
            uint32_t pah[4], pal[4];
            split_pack_h(pah[0], pal[0], accS[2*j2][0],   accS[2*j2][1]);
            split_pack_h(pah[1], pal[1], accS[2*j2][2],   accS[2*j2][3]);
            split_pack_h(pah[2], pal[2], accS[2*j2+1][0], accS[2*j2+1][1]);
            split_pack_h(pah[3], pal[3], accS[2*j2+1][2], accS[2*j2+1][3]);
#pragma unroll
            for (int nt = 0; nt < 8; nt++) {
                uint32_t voff = soffG(nt * 16 + rB, 2 * j2 + uB);
                uint32_t t4[4], v0[2], v1[2];
                ldsm4(t4, st + FV + voff);
                v0[0] = t4[0]; v0[1] = t4[1]; v1[0] = t4[2]; v1[1] = t4[3];
                mma_f16(accO[2*nt],   pah, v0);
                mma_f16(accO[2*nt],   pal, v0);
                mma_f16(accO[2*nt+1], pah, v1);
                mma_f16(accO[2*nt+1], pal, v1);
            }
        }
    }

    float inv0 = 1.0f / l0v, inv1 = 1.0f / l1v;
#pragma unroll
    for (int nf = 0; nf < 16; nf++) {
        int d = nf * 8 + (lane & 3) * 2;
        size_t o0 = (size_t)(b * SS + row0) * 2048 + h * 128 + d;
        size_t o1 = o0 + (size_t)8 * 2048;
        __half2 hh, ll;
        split_store2h(accO[nf][0] * inv0, accO[nf][1] * inv0, &hh, &ll);
        *(__half2*)(Oh + o0) = hh;
        *(__half2*)(Ol + o0) = ll;
        split_store2h(accO[nf][2] * inv1, accO[nf][3] * inv1, &hh, &ll);
        *(__half2*)(Oh + o1) = hh;
        *(__half2*)(Ol + o1) = ll;
    }
}

// ======================= launch =======================
extern "C" void kernel_launch(void* const* d_in, const int* in_sizes, int n_in,
                              void* d_out, int out_size)
{
    const int*   positions = (const int*)  d_in[0];
    const float* hidden    = (const float*)d_in[1];
    const float* residual  = (const float*)d_in[2];
    const float* ln1       = (const float*)d_in[3];
    const float* ln2       = (const float*)d_in[4];
    const float* wq        = (const float*)d_in[5];
    const float* bq        = (const float*)d_in[6];
    const float* wk        = (const float*)d_in[7];
    const float* bk        = (const float*)d_in[8];
    const float* wv        = (const float*)d_in[9];
    const float* bv        = (const float*)d_in[10];
    const float* wo        = (const float*)d_in[11];
    const float* wgu       = (const float*)d_in[12];
    const float* wd        = (const float*)d_in[13];

    float* out_h   = (float*)d_out;
    float* out_res = out_h + (size_t)out_size / 2;

    float *res1, *qkv, *hattn;
    __half *xn_h, *xn_l, *at_h, *at_l, *h2_h, *h2_l, *ac_h, *ac_l;
    __nv_bfloat16 *Qh, *Ql, *Kh, *Kl;
    __half *Vh;
    __half *qkvT, *woT, *guT, *wdT;
    cudaGetSymbolAddress((void**)&res1,  g_res1);
    cudaGetSymbolAddress((void**)&qkv,   g_qkv);
    cudaGetSymbolAddress((void**)&hattn, g_hattn);
    cudaGetSymbolAddress((void**)&xn_h,  g_xn_h);
    cudaGetSymbolAddress((void**)&xn_l,  g_xn_l);
    cudaGetSymbolAddress((void**)&at_h,  g_at_h);
    cudaGetSymbolAddress((void**)&at_l,  g_at_l);
    cudaGetSymbolAddress((void**)&h2_h,  g_h2_h);
    cudaGetSymbolAddress((void**)&h2_l,  g_h2_l);
    cudaGetSymbolAddress((void**)&ac_h,  g_ac_h);
    cudaGetSymbolAddress((void**)&ac_l,  g_ac_l);
    cudaGetSymbolAddress((void**)&Qh,    g_Qh);
    cudaGetSymbolAddress((void**)&Ql,    g_Ql);
    cudaGetSymbolAddress((void**)&Kh,    g_Kh);
    cudaGetSymbolAddress((void**)&Kl,    g_Kl);
    cudaGetSymbolAddress((void**)&Vh,    g_Vh);
    cudaGetSymbolAddress((void**)&qkvT,  g_qkvT);
    cudaGetSymbolAddress((void**)&woT,   g_woT);
    cudaGetSymbolAddress((void**)&guT,   g_guT);
    cudaGetSymbolAddress((void**)&wdT,   g_wdT);

    cudaFuncSetAttribute(gemm_mma<0>, cudaFuncAttributeMaxDynamicSharedMemorySize, GEMM_SMEM);
    cudaFuncSetAttribute(gemm_mma<1>, cudaFuncAttributeMaxDynamicSharedMemorySize, GEMM_SMEM);
    cudaFuncSetAttribute(gemm_mma<2>, cudaFuncAttributeMaxDynamicSharedMemorySize, GEMM_SMEM);
    cudaFuncSetAttribute(flash_mma, cudaFuncAttributeMaxDynamicSharedMemorySize, FLASH_SMEM);

    // 0. weight preprocessing (single fp16)
    wsplit_qkv_kernel<<<dim3(128, 64), dim3(32,8)>>>(wq, wk, wv, qkvT);
    wsplit_kernel<<<dim3(64, 64), dim3(32,8)>>>(wo, woT, NHQ*HD, HH);
    wsplit_gu_kernel<<<dim3(512, 64), dim3(32,8)>>>(wgu, guT);
    wsplit_kernel<<<dim3(64, 256), dim3(32,8)>>>(wd, wdT, INTER, HH);

    // 1. res1 + rmsnorm -> fp16 split
    add_rmsnorm_kernel<<<TT, 256>>>(hidden, residual, ln1, res1, xn_h, xn_l);

    // 2. fused QKV projection
    gemm_mma<1><<<dim3(32, 32), 256, GEMM_SMEM>>>(xn_h, xn_l, qkvT,
        bq, bk, bv, qkv, nullptr, nullptr, TT, 4096, HH);

    // 3. RoPE + split of Q,K ; V transpose (fp16)
    qkconv_kernel<<<(TT * 24 * 64) / 256, 256>>>(qkv, positions, Qh, Ql, Kh, Kl);
    vconv_kernel<<<dim3(SS/32, HD/32, BB*NKV), dim3(32,8)>>>(qkv, Vh);

    // 4. flash attention -> fp16 split at_h/at_l
    flash_mma<<<dim3(SS/128, NHQ, BB), 256, FLASH_SMEM>>>(Qh, Ql, Kh, Kl, Vh, at_h, at_l);

    // 5. output projection
    gemm_mma<0><<<dim3(16, 32), 256, GEMM_SMEM>>>(at_h, at_l, woT,
        nullptr, nullptr, nullptr, hattn, nullptr, nullptr, TT, HH, NHQ*HD);

    // 6. res2 + rmsnorm -> fp16 split
    add_rmsnorm_kernel<<<TT, 256>>>(hattn, res1, ln2, out_res, h2_h, h2_l);

    // 7. gate_up GEMM + fused SwiGLU -> fp16 split act
    gemm_mma<2><<<dim3(128, 32), 256, GEMM_SMEM>>>(h2_h, h2_l, guT,
        nullptr, nullptr, nullptr, nullptr, ac_h, ac_l, TT, 16384, HH);

    // 8. down GEMM -> out first half
    gemm_mma<0><<<dim3(16, 32), 256, GEMM_SMEM>>>(ac_h, ac_l, wdT,
        nullptr, nullptr, nullptr, out_h, nullptr, nullptr, TT, HH, INTER);
}

// round 14
// speedup vs baseline: 4.3447x; 1.6321x over previous
#include <cuda_runtime.h>
#include <cuda_bf16.h>
#include <cuda_fp16.h>
#include <cstdint>
#include <math.h>

#define BB 2
#define SS 2048
#define TT (BB*SS)
#define HH 2048
#define NHQ 16
#define NKV 8
#define HD 128
#define INTER 8192
#define EPS 1e-6f

// ======================= scratch =======================
__device__ __align__(256) float g_res1 [(size_t)TT*HH];
__device__ __align__(256) float g_qkv  [(size_t)TT*4096];
__device__ __align__(256) float g_hattn[(size_t)TT*HH];
__device__ float g_invf [64];

// single-fp16 activations (GEMM A operands)
__device__ __align__(256) __half g_xn [(size_t)TT*HH];
__device__ __align__(256) __half g_at [(size_t)TT*HH];
__device__ __align__(256) __half g_h2 [(size_t)TT*HH];
__device__ __align__(256) __half g_ac [(size_t)TT*INTER];

// flash operands: Q/K bf16 split (3-term QK), V single fp16
__device__ __align__(256) __nv_bfloat16 g_Qh [(size_t)TT*2048];
__device__ __align__(256) __nv_bfloat16 g_Ql [(size_t)TT*2048];
__device__ __align__(256) __nv_bfloat16 g_Kh [(size_t)TT*1024];
__device__ __align__(256) __nv_bfloat16 g_Kl [(size_t)TT*1024];
__device__ __align__(256) __half        g_Vh [(size_t)TT*1024];  // [b][hk][d][s]

// single-fp16 transposed weights [N, K]
__device__ __align__(256) __half g_qkvT[(size_t)4096*HH];
__device__ __align__(256) __half g_woT [(size_t)HH*(NHQ*HD)];
__device__ __align__(256) __half g_guT [(size_t)(2*INTER)*HH];   // interleaved gate/up
__device__ __align__(256) __half g_wdT [(size_t)HH*INTER];

// ======================= PTX helpers =======================
__device__ __forceinline__ uint32_t s2u(const void* p) {
    uint32_t a;
    asm("{ .reg .u64 t; cvta.to.shared.u64 t, %1; cvt.u32.u64 %0, t; }" : "=r"(a) : "l"(p));
    return a;
}
__device__ __forceinline__ void cpasync16(uint32_t dst, const void* src) {
    asm volatile("cp.async.cg.shared.global [%0], [%1], 16;" :: "r"(dst), "l"(src) : "memory");
}
__device__ __forceinline__ void cp_commit() { asm volatile("cp.async.commit_group;" ::: "memory"); }
template<int N_>
__device__ __forceinline__ void cp_wait() { asm volatile("cp.async.wait_group %0;" :: "n"(N_) : "memory"); }
__device__ __forceinline__ void ldsm4(uint32_t* r, uint32_t addr) {
    asm volatile("ldmatrix.sync.aligned.m8n8.x4.shared.b16 {%0,%1,%2,%3}, [%4];"
                 : "=r"(r[0]), "=r"(r[1]), "=r"(r[2]), "=r"(r[3]) : "r"(addr));
}
__device__ __forceinline__ void mma_bf16(float* d, const uint32_t* a, const uint32_t* b) {
    asm volatile(
        "mma.sync.aligned.m16n8k16.row.col.f32.bf16.bf16.f32 "
        "{%0,%1,%2,%3}, {%4,%5,%6,%7}, {%8,%9}, {%0,%1,%2,%3};"
        : "+f"(d[0]), "+f"(d[1]), "+f"(d[2]), "+f"(d[3])
        : "r"(a[0]), "r"(a[1]), "r"(a[2]), "r"(a[3]), "r"(b[0]), "r"(b[1]));
}
__device__ __forceinline__ void mma_f16(float* d, const uint32_t* a, const uint32_t* b) {
    asm volatile(
        "mma.sync.aligned.m16n8k16.row.col.f32.f16.f16.f32 "
        "{%0,%1,%2,%3}, {%4,%5,%6,%7}, {%8,%9}, {%0,%1,%2,%3};"
        : "+f"(d[0]), "+f"(d[1]), "+f"(d[2]), "+f"(d[3])
        : "r"(a[0]), "r"(a[1]), "r"(a[2]), "r"(a[3]), "r"(b[0]), "r"(b[1]));
}
// bf16 split (flash Q/K)
__device__ __forceinline__ void split_store2(float x, float y, __nv_bfloat162* ph, __nv_bfloat162* pl)
{
    __nv_bfloat16 hx = __float2bfloat16(x), hy = __float2bfloat16(y);
    *ph = __halves2bfloat162(hx, hy);
    *pl = __halves2bfloat162(__float2bfloat16(x - __bfloat162float(hx)),
                             __float2bfloat16(y - __bfloat162float(hy)));
}
// fp16 split (flash P)
__device__ __forceinline__ void split_pack_h(uint32_t& ph, uint32_t& pl, float x, float y)
{
    __half hx = __float2half(x), hy = __float2half(y);
    __half2 h2 = __halves2half2(hx, hy);
    __half2 l2 = __halves2half2(__float2half(x - __half2float(hx)),
                                __float2half(y - __half2float(hy)));
    ph = *(uint32_t*)&h2; pl = *(uint32_t*)&l2;
}
__device__ __forceinline__ uint32_t soffG(int r, int u)   { return (uint32_t)(r*128 + ((u ^ (r & 7)) << 4)); }
__device__ __forceinline__ uint32_t soff256(int r, int u) { return (uint32_t)(r*256 + ((u ^ (r & 7)) << 4)); }

// ======================= fused add + RMSNorm (fp16 out) =======================
__global__ void add_rmsnorm_kernel(const float* __restrict__ a, const float* __restrict__ b,
                                   const float* __restrict__ w, float* __restrict__ res,
                                   __half* __restrict__ oh)
{
    int t = blockIdx.x, tid = threadIdx.x;
    const float4* a4 = (const float4*)(a + (size_t)t * HH);
    const float4* b4 = (const float4*)(b + (size_t)t * HH);
    float4* r4 = (float4*)(res + (size_t)t * HH);
    const float4* w4 = (const float4*)w;
    __half2* oh2 = (__half2*)(oh + (size_t)t * HH);

    float4 vv[2];
    float ss = 0.f;
#pragma unroll
    for (int ii = 0; ii < 2; ii++) {
        int idx = tid + ii * 256;
        float4 x = a4[idx], y = b4[idx];
        x.x += y.x; x.y += y.y; x.z += y.z; x.w += y.w;
        r4[idx] = x; vv[ii] = x;
        ss += x.x*x.x + x.y*x.y + x.z*x.z + x.w*x.w;
    }
#pragma unroll
    for (int off = 16; off; off >>= 1) ss += __shfl_xor_sync(0xffffffffu, ss, off);
    __shared__ float sh[8];
    __shared__ float s_inv;
    if ((tid & 31) == 0) sh[tid >> 5] = ss;
    __syncthreads();
    if (tid == 0) {
        float s = 0.f;
#pragma unroll
        for (int i = 0; i < 8; i++) s += sh[i];
        s_inv = rsqrtf(s / (float)HH + EPS);
    }
    __syncthreads();
    float inv = s_inv;
#pragma unroll
    for (int ii = 0; ii < 2; ii++) {
        int idx = tid + ii * 256;
        float4 x = vv[ii], ww = w4[idx];
        oh2[idx*2]   = __floats2half2_rn(x.x*inv*ww.x, x.y*inv*ww.y);
        oh2[idx*2+1] = __floats2half2_rn(x.z*inv*ww.z, x.w*inv*ww.w);
    }
}

// ======================= weight split kernels (single fp16) =======================
__global__ void wsplit_kernel(const float* __restrict__ W, __half* __restrict__ Tw, int K, int N)
{
    __shared__ float tile[32][33];
    int k0 = blockIdx.y * 32, n0 = blockIdx.x * 32;
    int tx = threadIdx.x, ty = threadIdx.y;
#pragma unroll
    for (int j = 0; j < 4; j++)
        tile[ty + 8*j][tx] = W[(size_t)(k0 + ty + 8*j) * N + n0 + tx];
    __syncthreads();
#pragma unroll
    for (int j = 0; j < 4; j++) {
        int n = ty + 8*j;
        Tw[(size_t)(n0 + n) * K + k0 + tx] = __float2half(tile[tx][n]);
    }
}

__global__ void wsplit_qkv_kernel(const float* __restrict__ wq, const float* __restrict__ wk,
                                  const float* __restrict__ wv, __half* __restrict__ Tw)
{
    __shared__ float tile[32][33];
    int n0 = blockIdx.x * 32, k0 = blockIdx.y * 32;
    int tx = threadIdx.x, ty = threadIdx.y;
    if (blockIdx.x == 0 && blockIdx.y == 0) {
        int id = ty * 32 + tx;
        if (id < 64) g_invf[id] = (float)pow(1.0e6, -(double)id / 64.0);
    }
    int n = n0 + tx;
    const float* src; int nc, stride;
    if (n < 2048)      { src = wq; nc = n;        stride = 2048; }
    else if (n < 3072) { src = wk; nc = n - 2048; stride = 1024; }
    else               { src = wv; nc = n - 3072; stride = 1024; }
#pragma unroll
    for (int j = 0; j < 4; j++)
        tile[ty + 8*j][tx] = src[(size_t)(k0 + ty + 8*j) * stride + nc];
    __syncthreads();
#pragma unroll
    for (int j = 0; j < 4; j++) {
        int nn = n0 + ty + 8*j;
        Tw[(size_t)nn * HH + k0 + tx] = __float2half(tile[tx][ty + 8*j]);
    }
}

__global__ void wsplit_gu_kernel(const float* __restrict__ W, __half* __restrict__ Tw)
{
    __shared__ float tile[32][33];
    int n0 = blockIdx.x * 32, k0 = blockIdx.y * 32;
    int tx = threadIdx.x, ty = threadIdx.y;
    int n = n0 + tx;
    int srccol = (n & 1) ? (8192 + (n >> 1)) : (n >> 1);
#pragma unroll
    for (int j = 0; j < 4; j++)
        tile[ty + 8*j][tx] = W[(size_t)(k0 + ty + 8*j) * 16384 + srccol];
    __syncthreads();
#pragma unroll
    for (int j = 0; j < 4; j++) {
        int nn = n0 + ty + 8*j;
        Tw[(size_t)nn * HH + k0 + tx] = __float2half(tile[tx][ty + 8*j]);
    }
}

// ======================= single-fp16 GEMM (1 MMA/k16, BK=64, 2-stage, occ 2) =======================
// stage: A [128r x 128B] | B [128r x 128B] = 32KB
#define G4_B  16384
#define G4_STAGE 32768
#define GEMM_SMEM (2*G4_STAGE)

__device__ __forceinline__ void g_load_stage(uint32_t sb, int s,
    const __half* __restrict__ A, const __half* __restrict__ Bw,
    int m0, int n0, int k0, int K, int tid)
{
    uint32_t st = sb + s * G4_STAGE;
#pragma unroll
    for (int j = 0; j < 8; j++) {
        int idx = j * 256 + tid;
        int seg = idx >> 10;
        int rem = idx & 1023;
        int r = rem >> 3, u = rem & 7;
        const __half* src = (seg == 0) ? (A + (size_t)(m0 + r) * K)
                                       : (Bw + (size_t)(n0 + r) * K);
        src += k0 + u * 8;
        cpasync16(st + seg * G4_B + soffG(r, u), src);
    }
    cp_commit();
}

// MODE 0: f32 out. MODE 1: qkv bias. MODE 2: fused SwiGLU -> fp16.
template<int MODE>
__global__ __launch_bounds__(256, 2) void gemm_mma(
    const __half* __restrict__ A, const __half* __restrict__ Bw,
    const float* __restrict__ bq, const float* __restrict__ bk, const float* __restrict__ bv,
    float* __restrict__ C, __half* __restrict__ actH,
    int M, int N, int K)
{
    extern __shared__ char smc[];
    uint32_t sb = s2u(smc);
    int tid = threadIdx.x, lane = tid & 31, wid = tid >> 5;
    int wm = wid & 3, wn = wid >> 2;          // 4 M-strips x 2 N-halves
    int m0 = blockIdx.y * 128, n0 = blockIdx.x * 128;

    float acc[2][8][4];
#pragma unroll
    for (int i = 0; i < 2; i++)
#pragma unroll
        for (int j = 0; j < 8; j++)
#pragma unroll
            for (int c = 0; c < 4; c++) acc[i][j][c] = 0.f;

    int rA = lane & 15, uA = lane >> 4;
    int rB = (lane & 7) | ((lane & 16) >> 1), uB = (lane >> 3) & 1;

    int nIter = K / 64;
    g_load_stage(sb, 0, A, Bw, m0, n0, 0, K, tid);
    g_load_stage(sb, 1, A, Bw, m0, n0, 64, K, tid);

    for (int it = 0; it < nIter; it++) {
        if (it + 1 < nIter) cp_wait<1>(); else cp_wait<0>();
        __syncthreads();

        uint32_t st = sb + (it & 1) * G4_STAGE;
#pragma unroll
        for (int ks = 0; ks < 4; ks++) {
            uint32_t ah[2][4];
#pragma unroll
            for (int mt = 0; mt < 2; mt++) {
                int row = wm * 32 + mt * 16 + rA;
                ldsm4(ah[mt], st + soffG(row, ks * 2 + uA));
            }
#pragma unroll
            for (int nt = 0; nt < 4; nt++) {
                int row = wn * 64 + nt * 16 + rB;
                uint32_t t4[4];
                ldsm4(t4, st + G4_B + soffG(row, ks * 2 + uB));
#pragma unroll
                for (int half = 0; half < 2; half++) {
                    int nf = nt * 2 + half;
                    uint32_t b2[2] = {t4[half*2], t4[half*2+1]};
#pragma unroll
                    for (int mt = 0; mt < 2; mt++)
                        mma_f16(acc[mt][nf], ah[mt], b2);
                }
            }
        }
        __syncthreads();
        if (it + 2 < nIter)
            g_load_stage(sb, it & 1, A, Bw, m0, n0, (it + 2) * 64, K, tid);
    }

    int crow = lane >> 2, ccol = (lane & 3) * 2;
#pragma unroll
    for (int mt = 0; mt < 2; mt++) {
#pragma unroll
        for (int nf = 0; nf < 8; nf++) {
            int r = m0 + wm * 32 + mt * 16 + crow;
            int cidx = n0 + wn * 64 + nf * 8 + ccol;
            if (MODE == 2) {
                int jj = cidx >> 1;
                float ga = acc[mt][nf][0], up = acc[mt][nf][1];
                float v0 = ga / (1.f + __expf(-ga)) * up;
                float gb = acc[mt][nf][2], ub = acc[mt][nf][3];
                float v1 = gb / (1.f + __expf(-gb)) * ub;
                actH[(size_t)r * INTER + jj] = __float2half(v0);
                actH[(size_t)(r + 8) * INTER + jj] = __float2half(v1);
            } else {
                float b0 = 0.f, b1 = 0.f;
                if (MODE == 1) {
                    b0 = (cidx < 2048) ? bq[cidx] : ((cidx < 3072) ? bk[cidx - 2048] : bv[cidx - 3072]);
                    int c1 = cidx + 1;
                    b1 = (c1 < 2048) ? bq[c1] : ((c1 < 3072) ? bk[c1 - 2048] : bv[c1 - 3072]);
                }
                *(float2*)(C + (size_t)r * N + cidx) =
                    make_float2(acc[mt][nf][0] + b0, acc[mt][nf][1] + b1);
                *(float2*)(C + (size_t)(r + 8) * N + cidx) =
                    make_float2(acc[mt][nf][2] + b0, acc[mt][nf][3] + b1);
            }
        }
    }
}

// ======================= RoPE + split of Q,K (bf16, for flash) =======================
__global__ void qkconv_kernel(const float* __restrict__ qkv, const int* __restrict__ pos,
    __nv_bfloat16* __restrict__ Qh, __nv_bfloat16* __restrict__ Ql,
    __nv_bfloat16* __restrict__ Kh, __nv_bfloat16* __restrict__ Kl)
{
    int idx = blockIdx.x * blockDim.x + threadIdx.x;
    int i = idx & 63;
    int rest = idx >> 6;
    int head = rest % 24;
    int t = rest / 24;
    if (t >= TT) return;
    const float* p = qkv + (size_t)t * 4096 + ((head < 16) ? head * 128 : 2048 + (head - 16) * 128);
    float ang = (float)pos[t] * g_invf[i];
    float sv, cv;
    sincosf(ang, &sv, &cv);
    float x1 = p[i], x2 = p[i + 64];
    float o1 = x1 * cv - x2 * sv;
    float o2 = x2 * cv + x1 * sv;
    __nv_bfloat16 *dh, *dl;
    size_t dst;
    if (head < 16) { dst = (size_t)t * 2048 + head * 128;        dh = Qh; dl = Ql; }
    else           { dst = (size_t)t * 1024 + (head - 16) * 128; dh = Kh; dl = Kl; }
    __nv_bfloat16 h1 = __float2bfloat16(o1);
    dh[dst + i] = h1;
    dl[dst + i] = __float2bfloat16(o1 - __bfloat162float(h1));
    __nv_bfloat16 h2 = __float2bfloat16(o2);
    dh[dst + i + 64] = h2;
    dl[dst + i + 64] = __float2bfloat16(o2 - __bfloat162float(h2));
}

// ======================= V transpose (single fp16) =======================
__global__ void vconv_kernel(const float* __restrict__ qkv, __half* __restrict__ Vh)
{
    __shared__ float tile[32][33];
    int bhk = blockIdx.z;
    int b = bhk >> 3, hk = bhk & 7;
    int s0 = blockIdx.x * 32, d0 = blockIdx.y * 32;
    int tx = threadIdx.x, ty = threadIdx.y;
#pragma unroll
    for (int j = 0; j < 4; j++)
        tile[ty + 8*j][tx] = qkv[(size_t)(b * SS + s0 + ty + 8*j) * 4096 + 3072 + hk * 128 + d0 + tx];
    __syncthreads();
#pragma unroll
    for (int j = 0; j < 4; j++) {
        int d = d0 + ty + 8*j;
        size_t o = ((size_t)(b * NKV + hk) * HD + d) * SS + s0 + tx;
        Vh[o] = __float2half(tile[tx][ty + 8*j]);
    }
}

// ======================= tensor-core causal flash attention =======================
// QK: bf16 3-term; PV: fp16 (P split, V single); out: single fp16
#define FQ_H 0
#define FQ_L 32768
#define FST(s) (65536 + (s)*49152)
#define FK_H 0
#define FK_L 16384
#define FV   32768
#define FLASH_SMEM (65536 + 2*49152)

__global__ __launch_bounds__(256, 1) void flash_mma(
    const __nv_bfloat16* __restrict__ Qh, const __nv_bfloat16* __restrict__ Ql,
    const __nv_bfloat16* __restrict__ Kh, const __nv_bfloat16* __restrict__ Kl,
    const __half* __restrict__ Vh, __half* __restrict__ Oh)
{
    extern __shared__ char smc[];
    uint32_t sb = s2u(smc);
    int tid = threadIdx.x, lane = tid & 31, wid = tid >> 5;
    int qt = (gridDim.x - 1) - blockIdx.x;
    int h = blockIdx.y, b = blockIdx.z;
    int hk = h >> 1;
    int q0 = qt * 128;
    int rA = lane & 15, uA = lane >> 4;
    int rB = (lane & 7) | ((lane & 16) >> 1), uB = (lane >> 3) & 1;

#pragma unroll
    for (int j = 0; j < 16; j++) {
        int idx = j * 256 + tid;
        int arr = idx >> 11, rem = idx & 2047;
        int r = rem >> 4, u = rem & 15;
        const __nv_bfloat16* src = (arr ? Ql : Qh) + (size_t)(b * SS + q0 + r) * 2048 + h * 128 + u * 8;
        cpasync16(sb + (arr ? FQ_L : FQ_H) + soff256(r, u), src);
    }

    auto load_kv = [&](int buf, int kbase) {
        uint32_t st = sb + FST(buf);
#pragma unroll
        for (int j = 0; j < 8; j++) {
            int idx = j * 256 + tid;
            int arr = idx >> 10, rem = idx & 1023;
            int r = rem >> 4, u = rem & 15;
            const __nv_bfloat16* src = (arr ? Kl : Kh) + (size_t)(b * SS + kbase + r) * 1024 + hk * 128 + u * 8;
            cpasync16(st + (arr ? FK_L : FK_H) + soff256(r, u), src);
        }
#pragma unroll
        for (int j = 0; j < 4; j++) {
            int idx = j * 256 + tid;
            int r = idx >> 3, u = idx & 7;
            const __half* src = Vh + ((size_t)(b * NKV + hk) * HD + r) * SS + kbase + u * 8;
            cpasync16(st + FV + soffG(r, u), src);
        }
        cp_commit();
    };
    load_kv(0, 0);

    float m0v = -1e30f, m1v = -1e30f, l0v = 0.f, l1v = 0.f;
    float accO[16][4];
#pragma unroll
    for (int i = 0; i < 16; i++)
#pragma unroll
        for (int c = 0; c < 4; c++) accO[i][c] = 0.f;

    const float sc = 0.08838834764831845f;
    int ktmax = 2 * qt + 1;
    int row0 = q0 + wid * 16 + (lane >> 2);

    for (int kt = 0; kt <= ktmax; kt++) {
        cp_wait<0>();
        __syncthreads();
        if (kt < ktmax) load_kv((kt + 1) & 1, (kt + 1) * 64);
        uint32_t st = sb + FST(kt & 1);

        float accS[8][4];
#pragma unroll
        for (int i = 0; i < 8; i++)
#pragma unroll
            for (int c = 0; c < 4; c++) accS[i][c] = 0.f;

#pragma unroll
        for (int j = 0; j < 8; j++) {
            uint32_t ahf[4], alf[4];
            uint32_t qoff = soff256(wid * 16 + rA, 2 * j + uA);
            ldsm4(ahf, sb + FQ_H + qoff);
            ldsm4(alf, sb + FQ_L + qoff);
            uint32_t bhf[8][2], blf[8][2];
#pragma unroll
            for (int nt = 0; nt < 4; nt++) {
                uint32_t koff = soff256(nt * 16 + rB, 2 * j + uB);
                uint32_t t4[4];
                ldsm4(t4, st + FK_H + koff);
                bhf[2*nt][0] = t4[0]; bhf[2*nt][1] = t4[1];
                bhf[2*nt+1][0] = t4[2]; bhf[2*nt+1][1] = t4[3];
                ldsm4(t4, st + FK_L + koff);
                blf[2*nt][0] = t4[0]; blf[2*nt][1] = t4[1];
                blf[2*nt+1][0] = t4[2]; blf[2*nt+1][1] = t4[3];
            }
#pragma unroll
            for (int nf = 0; nf < 8; nf++) {
                mma_bf16(accS[nf], ahf, bhf[nf]);
                mma_bf16(accS[nf], ahf, blf[nf]);
                mma_bf16(accS[nf], alf, bhf[nf]);
            }
        }

        int kbase = kt * 64;
        bool needmask = (kbase + 63) > row0;
#pragma unroll
        for (int nf = 0; nf < 8; nf++) {
#pragma unroll
            for (int e = 0; e < 4; e++) {
                float s = accS[nf][e] * sc;
                if (needmask) {
                    int cc = kbase + nf * 8 + (lane & 3) * 2 + (e & 1);
                    int rr = row0 + ((e >> 1) << 3);
                    if (cc > rr) s = -1e30f;
                }
                accS[nf][e] = s;
            }
        }
        float vm0 = -1e30f, vm1 = -1e30f;
#pragma unroll
        for (int nf = 0; nf < 8; nf++) {
            vm0 = fmaxf(vm0, fmaxf(accS[nf][0], accS[nf][1]));
            vm1 = fmaxf(vm1, fmaxf(accS[nf][2], accS[nf][3]));
        }
        vm0 = fmaxf(vm0, __shfl_xor_sync(0xffffffffu, vm0, 1));
        vm0 = fmaxf(vm0, __shfl_xor_sync(0xffffffffu, vm0, 2));
        vm1 = fmaxf(vm1, __shfl_xor_sync(0xffffffffu, vm1, 1));
        vm1 = fmaxf(vm1, __shfl_xor_sync(0xffffffffu, vm1, 2));
        float mn0 = fmaxf(m0v, vm0), mn1 = fmaxf(m1v, vm1);
        float c0 = __expf(m0v - mn0), c1 = __expf(m1v - mn1);
        float s0 = 0.f, s1 = 0.f;
#pragma unroll
        for (int nf = 0; nf < 8; nf++) {
            accS[nf][0] = __expf(accS[nf][0] - mn0); s0 += accS[nf][0];
            accS[nf][1] = __expf(accS[nf][1] - mn0); s0 += accS[nf][1];
            accS[nf][2] = __expf(accS[nf][2] - mn1); s1 += accS[nf][2];
            accS[nf][3] = __expf(accS[nf][3] - mn1); s1 += accS[nf][3];
        }
        s0 += __shfl_xor_sync(0xffffffffu, s0, 1);
        s0 += __shfl_xor_sync(0xffffffffu, s0, 2);
        s1 += __shfl_xor_sync(0xffffffffu, s1, 1);
        s1 += __shfl_xor_sync(0xffffffffu, s1, 2);
        l0v = l0v * c0 + s0; l1v = l1v * c1 + s1;
        m0v = mn0; m1v = mn1;
#pragma unroll
        for (int i = 0; i < 16; i++) {
            accO[i][0] *= c0; accO[i][1] *= c0;
            accO[i][2] *= c1; accO[i][3] *= c1;
        }

#pragma unroll
        for (int j2 = 0; j2 < 4; j2++) {
            uint32_t pah[4], pal[4];
            split_pack_h(pah[0], pal[0], accS[2*j2][0],   accS[2*j2][1]);
            split_pack_h(pah[1], pal[1], accS[2*j2][2],   accS[2*j2][3]);
            split_pack_h(pah[2], pal[2], accS[2*j2+1][0], accS[2*j2+1][1]);
            split_pack_h(pah[3], pal[3], accS[2*j2+1][2], accS[2*j2+1][3]);
#pragma unroll
            for (int nt = 0; nt < 8; nt++) {
                uint32_t voff = soffG(nt * 16 + rB, 2 * j2 + uB);
                uint32_t t4[4], v0[2], v1[2];
                ldsm4(t4, st + FV + voff);
                v0[0] = t4[0]; v0[1] = t4[1]; v1[0] = t4[2]; v1[1] = t4[3];
                mma_f16(accO[2*nt],   pah, v0);
                mma_f16(accO[2*nt],   pal, v0);
                mma_f16(accO[2*nt+1], pah, v1);
                mma_f16(accO[2*nt+1], pal, v1);
            }
        }
    }

    float inv0 = 1.0f / l0v, inv1 = 1.0f / l1v;
#pragma unroll
    for (int nf = 0; nf < 16; nf++) {
        int d = nf * 8 + (lane & 3) * 2;
        size_t o0 = (size_t)(b * SS + row0) * 2048 + h * 128 + d;
        size_t o1 = o0 + (size_t)8 * 2048;
        *(__half2*)(Oh + o0) = __floats2half2_rn(accO[nf][0] * inv0, accO[nf][1] * inv0);
        *(__half2*)(Oh + o1) = __floats2half2_rn(accO[nf][2] * inv1, accO[nf][3] * inv1);
    }
}

// ======================= launch =======================
extern "C" void kernel_launch(void* const* d_in, const int* in_sizes, int n_in,
                              void* d_out, int out_size)
{
    const int*   positions = (const int*)  d_in[0];
    const float* hidden    = (const float*)d_in[1];
    const float* residual  = (const float*)d_in[2];
    const float* ln1       = (const float*)d_in[3];
    const float* ln2       = (const float*)d_in[4];
    const float* wq        = (const float*)d_in[5];
    const float* bq        = (const float*)d_in[6];
    const float* wk        = (const float*)d_in[7];
    const float* bk        = (const float*)d_in[8];
    const float* wv        = (const float*)d_in[9];
    const float* bv        = (const float*)d_in[10];
    const float* wo        = (const float*)d_in[11];
    const float* wgu       = (const float*)d_in[12];
    const float* wd        = (const float*)d_in[13];

    float* out_h   = (float*)d_out;
    float* out_res = out_h + (size_t)out_size / 2;

    float *res1, *qkv, *hattn;
    __half *xn, *at, *h2, *ac, *Vh;
    __nv_bfloat16 *Qh, *Ql, *Kh, *Kl;
    __half *qkvT, *woT, *guT, *wdT;
    cudaGetSymbolAddress((void**)&res1,  g_res1);
    cudaGetSymbolAddress((void**)&qkv,   g_qkv);
    cudaGetSymbolAddress((void**)&hattn, g_hattn);
    cudaGetSymbolAddress((void**)&xn,    g_xn);
    cudaGetSymbolAddress((void**)&at,    g_at);
    cudaGetSymbolAddress((void**)&h2,    g_h2);
    cudaGetSymbolAddress((void**)&ac,    g_ac);
    cudaGetSymbolAddress((void**)&Qh,    g_Qh);
    cudaGetSymbolAddress((void**)&Ql,    g_Ql);
    cudaGetSymbolAddress((void**)&Kh,    g_Kh);
    cudaGetSymbolAddress((void**)&Kl,    g_Kl);
    cudaGetSymbolAddress((void**)&Vh,    g_Vh);
    cudaGetSymbolAddress((void**)&qkvT,  g_qkvT);
    cudaGetSymbolAddress((void**)&woT,   g_woT);
    cudaGetSymbolAddress((void**)&guT,   g_guT);
    cudaGetSymbolAddress((void**)&wdT,   g_wdT);

    cudaFuncSetAttribute(gemm_mma<0>, cudaFuncAttributeMaxDynamicSharedMemorySize, GEMM_SMEM);
    cudaFuncSetAttribute(gemm_mma<1>, cudaFuncAttributeMaxDynamicSharedMemorySize, GEMM_SMEM);
    cudaFuncSetAttribute(gemm_mma<2>, cudaFuncAttributeMaxDynamicSharedMemorySize, GEMM_SMEM);
    cudaFuncSetAttribute(flash_mma, cudaFuncAttributeMaxDynamicSharedMemorySize, FLASH_SMEM);

    // 0. weight preprocessing (single fp16)
    wsplit_qkv_kernel<<<dim3(128, 64), dim3(32,8)>>>(wq, wk, wv, qkvT);
    wsplit_kernel<<<dim3(64, 64), dim3(32,8)>>>(wo, woT, NHQ*HD, HH);
    wsplit_gu_kernel<<<dim3(512, 64), dim3(32,8)>>>(wgu, guT);
    wsplit_kernel<<<dim3(64, 256), dim3(32,8)>>>(wd, wdT, INTER, HH);

    // 1. res1 + rmsnorm -> fp16
    add_rmsnorm_kernel<<<TT, 256>>>(hidden, residual, ln1, res1, xn);

    // 2. fused QKV projection
    gemm_mma<1><<<dim3(32, 32), 256, GEMM_SMEM>>>(xn, qkvT,
        bq, bk, bv, qkv, nullptr, TT, 4096, HH);

    // 3. RoPE + split of Q,K ; V transpose
    qkconv_kernel<<<(TT * 24 * 64) / 256, 256>>>(qkv, positions, Qh, Ql, Kh, Kl);
    vconv_kernel<<<dim3(SS/32, HD/32, BB*NKV), dim3(32,8)>>>(qkv, Vh);

    // 4. flash attention -> fp16 at
    flash_mma<<<dim3(SS/128, NHQ, BB), 256, FLASH_SMEM>>>(Qh, Ql, Kh, Kl, Vh, at);

    // 5. output projection
    gemm_mma<0><<<dim3(16, 32), 256, GEMM_SMEM>>>(at, woT,
        nullptr, nullptr, nullptr, hattn, nullptr, TT, HH, NHQ*HD);

    // 6. res2 + rmsnorm -> fp16
    add_rmsnorm_kernel<<<TT, 256>>>(hattn, res1, ln2, out_res, h2);

    // 7. gate_up GEMM + fused SwiGLU -> fp16 act
    gemm_mma<2><<<dim3(128, 32), 256, GEMM_SMEM>>>(h2, guT,
        nullptr, nullptr, nullptr, nullptr, ac, TT, 16384, HH);

    // 8. down GEMM -> out first half
    gemm_mma<0><<<dim3(16, 32), 256, GEMM_SMEM>>>(ac, wdT,
        nullptr, nullptr, nullptr, out_h, nullptr, TT, HH, INTER);
}

// round 16
// speedup vs baseline: 4.5859x; 1.0555x over previous
#include <cuda_runtime.h>
#include <cuda_bf16.h>
#include <cuda_fp16.h>
#include <cstdint>
#include <math.h>

#define BB 2
#define SS 2048
#define TT (BB*SS)
#define HH 2048
#define NHQ 16
#define NKV 8
#define HD 128
#define INTER 8192
#define EPS 1e-6f

// ======================= scratch =======================
__device__ __align__(256) float g_res1 [(size_t)TT*HH];
__device__ __align__(256) float g_qkv  [(size_t)TT*4096];
__device__ __align__(256) float g_hattn[(size_t)TT*HH];
__device__ float g_invf [64];

// single-fp16 activations (GEMM A operands)
__device__ __align__(256) __half g_xn [(size_t)TT*HH];
__device__ __align__(256) __half g_at [(size_t)TT*HH];
__device__ __align__(256) __half g_h2 [(size_t)TT*HH];
__device__ __align__(256) __half g_ac [(size_t)TT*INTER];

// flash operands: single fp16 Q, K; V single fp16 [b][hk][d][s]
__device__ __align__(256) __half g_Qf [(size_t)TT*2048];
__device__ __align__(256) __half g_Kf [(size_t)TT*1024];
__device__ __align__(256) __half g_Vh [(size_t)TT*1024];

// single-fp16 transposed weights [N, K]
__device__ __align__(256) __half g_qkvT[(size_t)4096*HH];
__device__ __align__(256) __half g_woT [(size_t)HH*(NHQ*HD)];
__device__ __align__(256) __half g_guT [(size_t)(2*INTER)*HH];   // interleaved gate/up
__device__ __align__(256) __half g_wdT [(size_t)HH*INTER];

// ======================= PTX helpers =======================
__device__ __forceinline__ uint32_t s2u(const void* p) {
    uint32_t a;
    asm("{ .reg .u64 t; cvta.to.shared.u64 t, %1; cvt.u32.u64 %0, t; }" : "=r"(a) : "l"(p));
    return a;
}
__device__ __forceinline__ void cpasync16(uint32_t dst, const void* src) {
    asm volatile("cp.async.cg.shared.global [%0], [%1], 16;" :: "r"(dst), "l"(src) : "memory");
}
__device__ __forceinline__ void cp_commit() { asm volatile("cp.async.commit_group;" ::: "memory"); }
template<int N_>
__device__ __forceinline__ void cp_wait() { asm volatile("cp.async.wait_group %0;" :: "n"(N_) : "memory"); }
__device__ __forceinline__ void ldsm4(uint32_t* r, uint32_t addr) {
    asm volatile("ldmatrix.sync.aligned.m8n8.x4.shared.b16 {%0,%1,%2,%3}, [%4];"
                 : "=r"(r[0]), "=r"(r[1]), "=r"(r[2]), "=r"(r[3]) : "r"(addr));
}
__device__ __forceinline__ void mma_f16(float* d, const uint32_t* a, const uint32_t* b) {
    asm volatile(
        "mma.sync.aligned.m16n8k16.row.col.f32.f16.f16.f32 "
        "{%0,%1,%2,%3}, {%4,%5,%6,%7}, {%8,%9}, {%0,%1,%2,%3};"
        : "+f"(d[0]), "+f"(d[1]), "+f"(d[2]), "+f"(d[3])
        : "r"(a[0]), "r"(a[1]), "r"(a[2]), "r"(a[3]), "r"(b[0]), "r"(b[1]));
}
// fp16 split (flash P)
__device__ __forceinline__ void split_pack_h(uint32_t& ph, uint32_t& pl, float x, float y)
{
    __half hx = __float2half(x), hy = __float2half(y);
    __half2 h2 = __halves2half2(hx, hy);
    __half2 l2 = __halves2half2(__float2half(x - __half2float(hx)),
                                __float2half(y - __half2float(hy)));
    ph = *(uint32_t*)&h2; pl = *(uint32_t*)&l2;
}
__device__ __forceinline__ uint32_t soffG(int r, int u)   { return (uint32_t)(r*128 + ((u ^ (r & 7)) << 4)); }
__device__ __forceinline__ uint32_t soff256(int r, int u) { return (uint32_t)(r*256 + ((u ^ (r & 7)) << 4)); }

// ======================= fused add + RMSNorm (fp16 out) =======================
__global__ void add_rmsnorm_kernel(const float* __restrict__ a, const float* __restrict__ b,
                                   const float* __restrict__ w, float* __restrict__ res,
                                   __half* __restrict__ oh)
{
    int t = blockIdx.x, tid = threadIdx.x;
    const float4* a4 = (const float4*)(a + (size_t)t * HH);
    const float4* b4 = (const float4*)(b + (size_t)t * HH);
    float4* r4 = (float4*)(res + (size_t)t * HH);
    const float4* w4 = (const float4*)w;
    __half2* oh2 = (__half2*)(oh + (size_t)t * HH);

    float4 vv[2];
    float ss = 0.f;
#pragma unroll
    for (int ii = 0; ii < 2; ii++) {
        int idx = tid + ii * 256;
        float4 x = a4[idx], y = b4[idx];
        x.x += y.x; x.y += y.y; x.z += y.z; x.w += y.w;
        r4[idx] = x; vv[ii] = x;
        ss += x.x*x.x + x.y*x.y + x.z*x.z + x.w*x.w;
    }
#pragma unroll
    for (int off = 16; off; off >>= 1) ss += __shfl_xor_sync(0xffffffffu, ss, off);
    __shared__ float sh[8];
    __shared__ float s_inv;
    if ((tid & 31) == 0) sh[tid >> 5] = ss;
    __syncthreads();
    if (tid == 0) {
        float s = 0.f;
#pragma unroll
        for (int i = 0; i < 8; i++) s += sh[i];
        s_inv = rsqrtf(s / (float)HH + EPS);
    }
    __syncthreads();
    float inv = s_inv;
#pragma unroll
    for (int ii = 0; ii < 2; ii++) {
        int idx = tid + ii * 256;
        float4 x = vv[ii], ww = w4[idx];
        oh2[idx*2]   = __floats2half2_rn(x.x*inv*ww.x, x.y*inv*ww.y);
        oh2[idx*2+1] = __floats2half2_rn(x.z*inv*ww.z, x.w*inv*ww.w);
    }
}

// ======================= weight split kernels (single fp16) =======================
__global__ void wsplit_kernel(const float* __restrict__ W, __half* __restrict__ Tw, int K, int N)
{
    __shared__ float tile[32][33];
    int k0 = blockIdx.y * 32, n0 = blockIdx.x * 32;
    int tx = threadIdx.x, ty = threadIdx.y;
#pragma unroll
    for (int j = 0; j < 4; j++)
        tile[ty + 8*j][tx] = W[(size_t)(k0 + ty + 8*j) * N + n0 + tx];
    __syncthreads();
#pragma unroll
    for (int j = 0; j < 4; j++) {
        int n = ty + 8*j;
        Tw[(size_t)(n0 + n) * K + k0 + tx] = __float2half(tile[tx][n]);
    }
}

__global__ void wsplit_qkv_kernel(const float* __restrict__ wq, const float* __restrict__ wk,
                                  const float* __restrict__ wv, __half* __restrict__ Tw)
{
    __shared__ float tile[32][33];
    int n0 = blockIdx.x * 32, k0 = blockIdx.y * 32;
    int tx = threadIdx.x, ty = threadIdx.y;
    if (blockIdx.x == 0 && blockIdx.y == 0) {
        int id = ty * 32 + tx;
        if (id < 64) g_invf[id] = (float)pow(1.0e6, -(double)id / 64.0);
    }
    int n = n0 + tx;
    const float* src; int nc, stride;
    if (n < 2048)      { src = wq; nc = n;        stride = 2048; }
    else if (n < 3072) { src = wk; nc = n - 2048; stride = 1024; }
    else               { src = wv; nc = n - 3072; stride = 1024; }
#pragma unroll
    for (int j = 0; j < 4; j++)
        tile[ty + 8*j][tx] = src[(size_t)(k0 + ty + 8*j) * stride + nc];
    __syncthreads();
#pragma unroll
    for (int j = 0; j < 4; j++) {
        int nn = n0 + ty + 8*j;
        Tw[(size_t)nn * HH + k0 + tx] = __float2half(tile[tx][ty + 8*j]);
    }
}

__global__ void wsplit_gu_kernel(const float* __restrict__ W, __half* __restrict__ Tw)
{
    __shared__ float tile[32][33];
    int n0 = blockIdx.x * 32, k0 = blockIdx.y * 32;
    int tx = threadIdx.x, ty = threadIdx.y;
    int n = n0 + tx;
    int srccol = (n & 1) ? (8192 + (n >> 1)) : (n >> 1);
#pragma unroll
    for (int j = 0; j < 4; j++)
        tile[ty + 8*j][tx] = W[(size_t)(k0 + ty + 8*j) * 16384 + srccol];
    __syncthreads();
#pragma unroll
    for (int j = 0; j < 4; j++) {
        int nn = n0 + ty + 8*j;
        Tw[(size_t)nn * HH + k0 + tx] = __float2half(tile[tx][ty + 8*j]);
    }
}

// ======================= single-fp16 GEMM (1 MMA/k16, BK=64, 2-stage, occ 2) =======================
#define G4_B  16384
#define G4_STAGE 32768
#define GEMM_SMEM (2*G4_STAGE)

__device__ __forceinline__ void g_load_stage(uint32_t sb, int s,
    const __half* __restrict__ A, const __half* __restrict__ Bw,
    int m0, int n0, int k0, int K, int tid)
{
    uint32_t st = sb + s * G4_STAGE;
#pragma unroll
    for (int j = 0; j < 8; j++) {
        int idx = j * 256 + tid;
        int seg = idx >> 10;
        int rem = idx & 1023;
        int r = rem >> 3, u = rem & 7;
        const __half* src = (seg == 0) ? (A + (size_t)(m0 + r) * K)
                                       : (Bw + (size_t)(n0 + r) * K);
        src += k0 + u * 8;
        cpasync16(st + seg * G4_B + soffG(r, u), src);
    }
    cp_commit();
}

// MODE 0: f32 out. MODE 1: qkv bias. MODE 2: fused SwiGLU -> fp16.
template<int MODE>
__global__ __launch_bounds__(256, 2) void gemm_mma(
    const __half* __restrict__ A, const __half* __restrict__ Bw,
    const float* __restrict__ bq, const float* __restrict__ bk, const float* __restrict__ bv,
    float* __restrict__ C, __half* __restrict__ actH,
    int M, int N, int K)
{
    extern __shared__ char smc[];
    uint32_t sb = s2u(smc);
    int tid = threadIdx.x, lane = tid & 31, wid = tid >> 5;
    int wm = wid & 3, wn = wid >> 2;          // 4 M-strips x 2 N-halves
    int m0 = blockIdx.y * 128, n0 = blockIdx.x * 128;

    float acc[2][8][4];
#pragma unroll
    for (int i = 0; i < 2; i++)
#pragma unroll
        for (int j = 0; j < 8; j++)
#pragma unroll
            for (int c = 0; c < 4; c++) acc[i][j][c] = 0.f;

    int rA = lane & 15, uA = lane >> 4;
    int rB = (lane & 7) | ((lane & 16) >> 1), uB = (lane >> 3) & 1;

    int nIter = K / 64;
    g_load_stage(sb, 0, A, Bw, m0, n0, 0, K, tid);
    g_load_stage(sb, 1, A, Bw, m0, n0, 64, K, tid);

    for (int it = 0; it < nIter; it++) {
        if (it + 1 < nIter) cp_wait<1>(); else cp_wait<0>();
        __syncthreads();

        uint32_t st = sb + (it & 1) * G4_STAGE;
#pragma unroll
        for (int ks = 0; ks < 4; ks++) {
            uint32_t ah[2][4];
#pragma unroll
            for (int mt = 0; mt < 2; mt++) {
                int row = wm * 32 + mt * 16 + rA;
                ldsm4(ah[mt], st + soffG(row, ks * 2 + uA));
            }
#pragma unroll
            for (int nt = 0; nt < 4; nt++) {
                int row = wn * 64 + nt * 16 + rB;
                uint32_t t4[4];
                ldsm4(t4, st + G4_B + soffG(row, ks * 2 + uB));
#pragma unroll
                for (int half = 0; half < 2; half++) {
                    int nf = nt * 2 + half;
                    uint32_t b2[2] = {t4[half*2], t4[half*2+1]};
#pragma unroll
                    for (int mt = 0; mt < 2; mt++)
                        mma_f16(acc[mt][nf], ah[mt], b2);
                }
            }
        }
        __syncthreads();
        if (it + 2 < nIter)
            g_load_stage(sb, it & 1, A, Bw, m0, n0, (it + 2) * 64, K, tid);
    }

    int crow = lane >> 2, ccol = (lane & 3) * 2;
#pragma unroll
    for (int mt = 0; mt < 2; mt++) {
#pragma unroll
        for (int nf = 0; nf < 8; nf++) {
            int r = m0 + wm * 32 + mt * 16 + crow;
            int cidx = n0 + wn * 64 + nf * 8 + ccol;
            if (MODE == 2) {
                int jj = cidx >> 1;
                float ga = acc[mt][nf][0], up = acc[mt][nf][1];
                float v0 = ga / (1.f + __expf(-ga)) * up;
                float gb = acc[mt][nf][2], ub = acc[mt][nf][3];
                float v1 = gb / (1.f + __expf(-gb)) * ub;
                actH[(size_t)r * INTER + jj] = __float2half(v0);
                actH[(size_t)(r + 8) * INTER + jj] = __float2half(v1);
            } else {
                float b0 = 0.f, b1 = 0.f;
                if (MODE == 1) {
                    b0 = (cidx < 2048) ? bq[cidx] : ((cidx < 3072) ? bk[cidx - 2048] : bv[cidx - 3072]);
                    int c1 = cidx + 1;
                    b1 = (c1 < 2048) ? bq[c1] : ((c1 < 3072) ? bk[c1 - 2048] : bv[c1 - 3072]);
                }
                *(float2*)(C + (size_t)r * N + cidx) =
                    make_float2(acc[mt][nf][0] + b0, acc[mt][nf][1] + b1);
                *(float2*)(C + (size_t)(r + 8) * N + cidx) =
                    make_float2(acc[mt][nf][2] + b0, acc[mt][nf][3] + b1);
            }
        }
    }
}

// ======================= RoPE + convert Q,K to single fp16 =======================
__global__ void qkconv_kernel(const float* __restrict__ qkv, const int* __restrict__ pos,
    __half* __restrict__ Qf, __half* __restrict__ Kf)
{
    int idx = blockIdx.x * blockDim.x + threadIdx.x;
    int i = idx & 63;
    int rest = idx >> 6;
    int head = rest % 24;
    int t = rest / 24;
    if (t >= TT) return;
    const float* p = qkv + (size_t)t * 4096 + ((head < 16) ? head * 128 : 2048 + (head - 16) * 128);
    float ang = (float)pos[t] * g_invf[i];
    float sv, cv;
    sincosf(ang, &sv, &cv);
    float x1 = p[i], x2 = p[i + 64];
    float o1 = x1 * cv - x2 * sv;
    float o2 = x2 * cv + x1 * sv;
    __half* d;
    size_t dst;
    if (head < 16) { dst = (size_t)t * 2048 + head * 128;        d = Qf; }
    else           { dst = (size_t)t * 1024 + (head - 16) * 128; d = Kf; }
    d[dst + i]      = __float2half(o1);
    d[dst + i + 64] = __float2half(o2);
}

// ======================= V transpose (single fp16) =======================
__global__ void vconv_kernel(const float* __restrict__ qkv, __half* __restrict__ Vh)
{
    __shared__ float tile[32][33];
    int bhk = blockIdx.z;
    int b = bhk >> 3, hk = bhk & 7;
    int s0 = blockIdx.x * 32, d0 = blockIdx.y * 32;
    int tx = threadIdx.x, ty = threadIdx.y;
#pragma unroll
    for (int j = 0; j < 4; j++)
        tile[ty + 8*j][tx] = qkv[(size_t)(b * SS + s0 + ty + 8*j) * 4096 + 3072 + hk * 128 + d0 + tx];
    __syncthreads();
#pragma unroll
    for (int j = 0; j < 4; j++) {
        int d = d0 + ty + 8*j;
        size_t o = ((size_t)(b * NKV + hk) * HD + d) * SS + s0 + tx;
        Vh[o] = __float2half(tile[tx][ty + 8*j]);
    }
}

// ======================= tensor-core causal flash attention =======================
// QK: single fp16 (1 MMA/k16); PV: P split fp16 x V fp16; out: single fp16
#define FQ 0
#define FST(s) (32768 + (s)*32768)
#define FK 0
#define FV 16384
#define FLASH_SMEM (32768 + 2*32768)

__global__ __launch_bounds__(256, 1) void flash_mma(
    const __half* __restrict__ Qf, const __half* __restrict__ Kf,
    const __half* __restrict__ Vh, __half* __restrict__ Oh)
{
    extern __shared__ char smc[];
    uint32_t sb = s2u(smc);
    int tid = threadIdx.x, lane = tid & 31, wid = tid >> 5;
    int qt = (gridDim.x - 1) - blockIdx.x;
    int h = blockIdx.y, b = blockIdx.z;
    int hk = h >> 1;
    int q0 = qt * 128;
    int rA = lane & 15, uA = lane >> 4;
    int rB = (lane & 7) | ((lane & 16) >> 1), uB = (lane >> 3) & 1;

    // Q stage (once): 128 rows x 16 units
#pragma unroll
    for (int j = 0; j < 8; j++) {
        int idx = j * 256 + tid;
        int r = idx >> 4, u = idx & 15;
        const __half* src = Qf + (size_t)(b * SS + q0 + r) * 2048 + h * 128 + u * 8;
        cpasync16(sb + FQ + soff256(r, u), src);
    }

    auto load_kv = [&](int buf, int kbase) {
        uint32_t st = sb + FST(buf);
#pragma unroll
        for (int j = 0; j < 4; j++) {   // K: 64 rows x 16 units
            int idx = j * 256 + tid;
            int r = idx >> 4, u = idx & 15;
            const __half* src = Kf + (size_t)(b * SS + kbase + r) * 1024 + hk * 128 + u * 8;
            cpasync16(st + FK + soff256(r, u), src);
        }
#pragma unroll
        for (int j = 0; j < 4; j++) {   // V: 128 d-rows x 8 units
            int idx = j * 256 + tid;
            int r = idx >> 3, u = idx & 7;
            const __half* src = Vh + ((size_t)(b * NKV + hk) * HD + r) * SS + kbase + u * 8;
            cpasync16(st + FV + soffG(r, u), src);
        }
        cp_commit();
    };
    load_kv(0, 0);

    float m0v = -1e30f, m1v = -1e30f, l0v = 0.f, l1v = 0.f;
    float accO[16][4];
#pragma unroll
    for (int i = 0; i < 16; i++)
#pragma unroll
        for (int c = 0; c < 4; c++) accO[i][c] = 0.f;

    const float sc = 0.08838834764831845f;
    int ktmax = 2 * qt + 1;
    int row0 = q0 + wid * 16 + (lane >> 2);

    for (int kt = 0; kt <= ktmax; kt++) {
        cp_wait<0>();
        __syncthreads();
        if (kt < ktmax) load_kv((kt + 1) & 1, (kt + 1) * 64);
        uint32_t st = sb + FST(kt & 1);

        // S = Q K^T (single fp16)
        float accS[8][4];
#pragma unroll
        for (int i = 0; i < 8; i++)
#pragma unroll
            for (int c = 0; c < 4; c++) accS[i][c] = 0.f;

#pragma unroll
        for (int j = 0; j < 8; j++) {
            uint32_t af[4];
            ldsm4(af, sb + FQ + soff256(wid * 16 + rA, 2 * j + uA));
            uint32_t bf[8][2];
#pragma unroll
            for (int nt = 0; nt < 4; nt++) {
                uint32_t t4[4];
                ldsm4(t4, st + FK + soff256(nt * 16 + rB, 2 * j + uB));
                bf[2*nt][0] = t4[0]; bf[2*nt][1] = t4[1];
                bf[2*nt+1][0] = t4[2]; bf[2*nt+1][1] = t4[3];
            }
#pragma unroll
            for (int nf = 0; nf < 8; nf++)
                mma_f16(accS[nf], af, bf[nf]);
        }

        int kbase = kt * 64;
        bool needmask = (kbase + 63) > row0;
#pragma unroll
        for (int nf = 0; nf < 8; nf++) {
#pragma unroll
            for (int e = 0; e < 4; e++) {
                float s = accS[nf][e] * sc;
                if (needmask) {
                    int cc = kbase + nf * 8 + (lane & 3) * 2 + (e & 1);
                    int rr = row0 + ((e >> 1) << 3);
                    if (cc > rr) s = -1e30f;
                }
                accS[nf][e] = s;
            }
        }
        float vm0 = -1e30f, vm1 = -1e30f;
#pragma unroll
        for (int nf = 0; nf < 8; nf++) {
            vm0 = fmaxf(vm0, fmaxf(accS[nf][0], accS[nf][1]));
            vm1 = fmaxf(vm1, fmaxf(accS[nf][2], accS[nf][3]));
        }
        vm0 = fmaxf(vm0, __shfl_xor_sync(0xffffffffu, vm0, 1));
        vm0 = fmaxf(vm0, __shfl_xor_sync(0xffffffffu, vm0, 2));
        vm1 = fmaxf(vm1, __shfl_xor_sync(0xffffffffu, vm1, 1));
        vm1 = fmaxf(vm1, __shfl_xor_sync(0xffffffffu, vm1, 2));
        float mn0 = fmaxf(m0v, vm0), mn1 = fmaxf(m1v, vm1);
        float c0 = __expf(m0v - mn0), c1 = __expf(m1v - mn1);
        float s0 = 0.f, s1 = 0.f;
#pragma unroll
        for (int nf = 0; nf < 8; nf++) {
            accS[nf][0] = __expf(accS[nf][0] - mn0); s0 += accS[nf][0];
            accS[nf][1] = __expf(accS[nf][1] - mn0); s0 += accS[nf][1];
            accS[nf][2] = __expf(accS[nf][2] - mn1); s1 += accS[nf][2];
            accS[nf][3] = __expf(accS[nf][3] - mn1); s1 += accS[nf][3];
        }
        s0 += __shfl_xor_sync(0xffffffffu, s0, 1);
        s0 += __shfl_xor_sync(0xffffffffu, s0, 2);
        s1 += __shfl_xor_sync(0xffffffffu, s1, 1);
        s1 += __shfl_xor_sync(0xffffffffu, s1, 2);
        l0v = l0v * c0 + s0; l1v = l1v * c1 + s1;
        m0v = mn0; m1v = mn1;
#pragma unroll
        for (int i = 0; i < 16; i++) {
            accO[i][0] *= c0; accO[i][1] *= c0;
            accO[i][2] *= c1; accO[i][3] *= c1;
        }

        // O += P V  (P split fp16, V single fp16)
#pragma unroll
        for (int j2 = 0; j2 < 4; j2++) {
            uint32_t pah[4], pal[4];
            split_pack_h(pah[0], pal[0], accS[2*j2][0],   accS[2*j2][1]);
            split_pack_h(pah[1], pal[1], accS[2*j2][2],   accS[2*j2][3]);
            split_pack_h(pah[2], pal[2], accS[2*j2+1][0], accS[2*j2+1][1]);
            split_pack_h(pah[3], pal[3], accS[2*j2+1][2], accS[2*j2+1][3]);
#pragma unroll
            for (int nt = 0; nt < 8; nt++) {
                uint32_t voff = soffG(nt * 16 + rB, 2 * j2 + uB);
                uint32_t t4[4], v0[2], v1[2];
                ldsm4(t4, st + FV + voff);
                v0[0] = t4[0]; v0[1] = t4[1]; v1[0] = t4[2]; v1[1] = t4[3];
                mma_f16(accO[2*nt],   pah, v0);
                mma_f16(accO[2*nt],   pal, v0);
                mma_f16(accO[2*nt+1], pah, v1);
                mma_f16(accO[2*nt+1], pal, v1);
            }
        }
    }

    float inv0 = 1.0f / l0v, inv1 = 1.0f / l1v;
#pragma unroll
    for (int nf = 0; nf < 16; nf++) {
        int d = nf * 8 + (lane & 3) * 2;
        size_t o0 = (size_t)(b * SS + row0) * 2048 + h * 128 + d;
        size_t o1 = o0 + (size_t)8 * 2048;
        *(__half2*)(Oh + o0) = __floats2half2_rn(accO[nf][0] * inv0, accO[nf][1] * inv0);
        *(__half2*)(Oh + o1) = __floats2half2_rn(accO[nf][2] * inv1, accO[nf][3] * inv1);
    }
}

// ======================= launch =======================
extern "C" void kernel_launch(void* const* d_in, const int* in_sizes, int n_in,
                              void* d_out, int out_size)
{
    const int*   positions = (const int*)  d_in[0];
    const float* hidden    = (const float*)d_in[1];
    const float* residual  = (const float*)d_in[2];
    const float* ln1       = (const float*)d_in[3];
    const float* ln2       = (const float*)d_in[4];
    const float* wq        = (const float*)d_in[5];
    const float* bq        = (const float*)d_in[6];
    const float* wk        = (const float*)d_in[7];
    const float* bk        = (const float*)d_in[8];
    const float* wv        = (const float*)d_in[9];
    const float* bv        = (const float*)d_in[10];
    const float* wo        = (const float*)d_in[11];
    const float* wgu       = (const float*)d_in[12];
    const float* wd        = (const float*)d_in[13];

    float* out_h   = (float*)d_out;
    float* out_res = out_h + (size_t)out_size / 2;

    float *res1, *qkv, *hattn;
    __half *xn, *at, *h2, *ac, *Qf, *Kf, *Vh;
    __half *qkvT, *woT, *guT, *wdT;
    cudaGetSymbolAddress((void**)&res1,  g_res1);
    cudaGetSymbolAddress((void**)&qkv,   g_qkv);
    cudaGetSymbolAddress((void**)&hattn, g_hattn);
    cudaGetSymbolAddress((void**)&xn,    g_xn);
    cudaGetSymbolAddress((void**)&at,    g_at);
    cudaGetSymbolAddress((void**)&h2,    g_h2);
    cudaGetSymbolAddress((void**)&ac,    g_ac);
    cudaGetSymbolAddress((void**)&Qf,    g_Qf);
    cudaGetSymbolAddress((void**)&Kf,    g_Kf);
    cudaGetSymbolAddress((void**)&Vh,    g_Vh);
    cudaGetSymbolAddress((void**)&qkvT,  g_qkvT);
    cudaGetSymbolAddress((void**)&woT,   g_woT);
    cudaGetSymbolAddress((void**)&guT,   g_guT);
    cudaGetSymbolAddress((void**)&wdT,   g_wdT);

    cudaFuncSetAttribute(gemm_mma<0>, cudaFuncAttributeMaxDynamicSharedMemorySize, GEMM_SMEM);
    cudaFuncSetAttribute(gemm_mma<1>, cudaFuncAttributeMaxDynamicSharedMemorySize, GEMM_SMEM);
    cudaFuncSetAttribute(gemm_mma<2>, cudaFuncAttributeMaxDynamicSharedMemorySize, GEMM_SMEM);
    cudaFuncSetAttribute(flash_mma, cudaFuncAttributeMaxDynamicSharedMemorySize, FLASH_SMEM);

    // 0. weight preprocessing (single fp16)
    wsplit_qkv_kernel<<<dim3(128, 64), dim3(32,8)>>>(wq, wk, wv, qkvT);
    wsplit_kernel<<<dim3(64, 64), dim3(32,8)>>>(wo, woT, NHQ*HD, HH);
    wsplit_gu_kernel<<<dim3(512, 64), dim3(32,8)>>>(wgu, guT);
    wsplit_kernel<<<dim3(64, 256), dim3(32,8)>>>(wd, wdT, INTER, HH);

    // 1. res1 + rmsnorm -> fp16
    add_rmsnorm_kernel<<<TT, 256>>>(hidden, residual, ln1, res1, xn);

    // 2. fused QKV projection (fp32 out, bias)
    gemm_mma<1><<<dim3(32, 32), 256, GEMM_SMEM>>>(xn, qkvT,
        bq, bk, bv, qkv, nullptr, TT, 4096, HH);

    // 3. RoPE -> single fp16 Q,K ; V transpose -> fp16
    qkconv_kernel<<<(TT * 24 * 64) / 256, 256>>>(qkv, positions, Qf, Kf);
    vconv_kernel<<<dim3(SS/32, HD/32, BB*NKV), dim3(32,8)>>>(qkv, Vh);

    // 4. flash attention -> fp16 at
    flash_mma<<<dim3(SS/128, NHQ, BB), 256, FLASH_SMEM>>>(Qf, Kf, Vh, at);

    // 5. output projection
    gemm_mma<0><<<dim3(16, 32), 256, GEMM_SMEM>>>(at, woT,
        nullptr, nullptr, nullptr, hattn, nullptr, TT, HH, NHQ*HD);

    // 6. res2 + rmsnorm -> fp16
    add_rmsnorm_kernel<<<TT, 256>>>(hattn, res1, ln2, out_res, h2);

    // 7. gate_up GEMM + fused SwiGLU -> fp16 act
    gemm_mma<2><<<dim3(128, 32), 256, GEMM_SMEM>>>(h2, guT,
        nullptr, nullptr, nullptr, nullptr, ac, TT, 16384, HH);

    // 8. down GEMM -> out first half
    gemm_mma<0><<<dim3(16, 32), 256, GEMM_SMEM>>>(ac, wdT,
        nullptr, nullptr, nullptr, out_h, nullptr, TT, HH, INTER);
}